// round 1
// baseline (speedup 1.0000x reference)
#include <cuda_runtime.h>
#include <math.h>
#include <math_constants.h>

#define Nn   50000
#define Ee   800000
#define DD   256      // DIN = DOUT = 256
#define EDD  128      // edge feature dim
#define Hh   4
#define Cc   64

// ---------------- scratch (device globals, no allocs) ----------------
__device__ float g_q[Nn * DD];
__device__ float g_k[Nn * DD];
__device__ float g_v[Nn * DD];
__device__ float g_s[Nn * DD];
__device__ float g_h[Nn * DD];        // layer-1 output / layer-2 input & accumulator
__device__ float g_e[(size_t)Ee * DD];        // edge projections (819 MB)
__device__ float g_alpha[(size_t)Ee * Hh];
__device__ float g_amax[Nn * Hh];
__device__ float g_denom[Nn * Hh];

// ---------------- SGEMM: C[M,N] = A[M,K] @ B[K,N] + bias[N] ----------------
// 128x128 block tile, BK=8, 8x8 per thread, 256 threads. Row-major everything.
__global__ __launch_bounds__(256) void sgemm_bias(
    int M, int N, int K,
    const float* __restrict__ A, const float* __restrict__ B,
    const float* __restrict__ bias, float* __restrict__ C)
{
    const int BM = 128, BN = 128, BK = 8, TM = 8, TN = 8;
    __shared__ float As[BK][BM];
    __shared__ float Bs[BK][BN];

    const int tid = threadIdx.x;
    const int tx = tid & 15;       // 16 thread cols
    const int ty = tid >> 4;       // 16 thread rows
    const int row0 = blockIdx.y * BM;
    const int col0 = blockIdx.x * BN;

    // A tile load: 128 rows x 8 k, one float4 per thread (2 threads/row)
    const int aRow = tid >> 1;
    const int aCol = (tid & 1) * 4;
    // B tile load: 8 k-rows x 128 cols, one float4 per thread
    const int bRow = tid >> 5;
    const int bCol = (tid & 31) * 4;

    float acc[TM][TN];
    #pragma unroll
    for (int i = 0; i < TM; i++)
        #pragma unroll
        for (int j = 0; j < TN; j++) acc[i][j] = 0.f;

    for (int k0 = 0; k0 < K; k0 += BK) {
        // load A (guard M), store transposed
        {
            const int gr = row0 + aRow;
            float4 av = make_float4(0.f, 0.f, 0.f, 0.f);
            if (gr < M) av = *(const float4*)(A + (size_t)gr * K + k0 + aCol);
            As[aCol + 0][aRow] = av.x;
            As[aCol + 1][aRow] = av.y;
            As[aCol + 2][aRow] = av.z;
            As[aCol + 3][aRow] = av.w;
        }
        // load B (always in-bounds: N and K are multiples of tile)
        {
            float4 bv = *(const float4*)(B + (size_t)(k0 + bRow) * N + col0 + bCol);
            *(float4*)&Bs[bRow][bCol] = bv;
        }
        __syncthreads();

        #pragma unroll
        for (int kk = 0; kk < BK; kk++) {
            float ar[TM], br[TN];
            #pragma unroll
            for (int i = 0; i < TM; i++) ar[i] = As[kk][ty * TM + i];
            #pragma unroll
            for (int j = 0; j < TN; j++) br[j] = Bs[kk][tx * TN + j];
            #pragma unroll
            for (int i = 0; i < TM; i++)
                #pragma unroll
                for (int j = 0; j < TN; j++)
                    acc[i][j] += ar[i] * br[j];
        }
        __syncthreads();
    }

    #pragma unroll
    for (int i = 0; i < TM; i++) {
        const int gr = row0 + ty * TM + i;
        if (gr >= M) continue;
        #pragma unroll
        for (int j = 0; j < TN; j += 4) {
            const int gc = col0 + tx * TN + j;
            float4 o;
            o.x = acc[i][j + 0] + bias[gc + 0];
            o.y = acc[i][j + 1] + bias[gc + 1];
            o.z = acc[i][j + 2] + bias[gc + 2];
            o.w = acc[i][j + 3] + bias[gc + 3];
            *(float4*)(C + (size_t)gr * N + gc) = o;
        }
    }
}

// ---------------- attention helper kernels ----------------
__device__ __forceinline__ void atomicMaxFloat(float* addr, float val)
{
    int old = __float_as_int(*addr);
    while (__int_as_float(old) < val) {
        int assumed = old;
        old = atomicCAS((int*)addr, assumed, __float_as_int(val));
        if (old == assumed) break;
    }
}

// acc <- skip(s); amax <- -inf; denom <- 0
__global__ void init_nodes(const float* __restrict__ s, float* __restrict__ acc)
{
    int i = blockIdx.x * blockDim.x + threadIdx.x;
    if (i < Nn * DD) acc[i] = s[i];
    if (i < Nn * Hh) { g_amax[i] = -CUDART_INF_F; g_denom[i] = 0.f; }
}

// one warp per edge: alpha[e,h] = dot(q[dst,h], k[src,h]+e[e,h]) / sqrt(C)
__global__ __launch_bounds__(256) void alpha_kernel(
    const int* __restrict__ ei,
    const float* __restrict__ q, const float* __restrict__ k,
    const float* __restrict__ e)
{
    const int warp = (blockIdx.x * blockDim.x + threadIdx.x) >> 5;
    const int lane = threadIdx.x & 31;
    if (warp >= Ee) return;
    const int src = ei[warp];
    const int dst = ei[Ee + warp];
    const float4* qp = (const float4*)(q + (size_t)dst * DD);
    const float4* kp = (const float4*)(k + (size_t)src * DD);
    const float4* ep = (const float4*)(e + (size_t)warp * DD);

    float sum = 0.f;
    #pragma unroll
    for (int u = 0; u < 2; u++) {
        const int idx = lane * 2 + u;
        float4 qv = qp[idx], kv = kp[idx], ev = ep[idx];
        sum += qv.x * (kv.x + ev.x) + qv.y * (kv.y + ev.y)
             + qv.z * (kv.z + ev.z) + qv.w * (kv.w + ev.w);
    }
    // reduce within 8-lane head groups
    sum += __shfl_xor_sync(0xffffffffu, sum, 1);
    sum += __shfl_xor_sync(0xffffffffu, sum, 2);
    sum += __shfl_xor_sync(0xffffffffu, sum, 4);
    if ((lane & 7) == 0) {
        const int h = lane >> 3;
        const float a = sum * 0.125f;   // 1/sqrt(64)
        g_alpha[(size_t)warp * Hh + h] = a;
        atomicMaxFloat(&g_amax[dst * Hh + h], a);
    }
}

// one thread per (edge, head): ex = exp(alpha - amax[dst]); denom += ex
__global__ void expsum_kernel(const int* __restrict__ ei)
{
    const int i = blockIdx.x * blockDim.x + threadIdx.x;
    if (i >= Ee * Hh) return;
    const int e = i >> 2, h = i & 3;
    const int dst = ei[Ee + e];
    const float ex = expf(g_alpha[i] - g_amax[dst * Hh + h]);
    g_alpha[i] = ex;
    atomicAdd(&g_denom[dst * Hh + h], ex);
}

// one warp per edge: out[dst] += (v[src]+e) * ex/(denom[dst]+eps)
__global__ __launch_bounds__(256) void scatter_kernel(
    const int* __restrict__ ei,
    const float* __restrict__ v, const float* __restrict__ e,
    float* __restrict__ out)
{
    const int warp = (blockIdx.x * blockDim.x + threadIdx.x) >> 5;
    const int lane = threadIdx.x & 31;
    if (warp >= Ee) return;
    const int src = ei[warp];
    const int dst = ei[Ee + warp];
    const int h = lane >> 3;
    const float w = g_alpha[(size_t)warp * Hh + h]
                  / (g_denom[dst * Hh + h] + 1e-16f);
    const float4* vp = (const float4*)(v + (size_t)src * DD);
    const float4* ep = (const float4*)(e + (size_t)warp * DD);
    float* op = out + (size_t)dst * DD;
    #pragma unroll
    for (int u = 0; u < 2; u++) {
        const int idx = lane * 2 + u;
        float4 vv = vp[idx], ev = ep[idx];
        const int c = idx * 4;
        atomicAdd(op + c + 0, (vv.x + ev.x) * w);
        atomicAdd(op + c + 1, (vv.y + ev.y) * w);
        atomicAdd(op + c + 2, (vv.z + ev.z) * w);
        atomicAdd(op + c + 3, (vv.w + ev.w) * w);
    }
}

__global__ void relu_kernel(float* __restrict__ x, int n)
{
    int i = blockIdx.x * blockDim.x + threadIdx.x;
    if (i < n) x[i] = fmaxf(x[i], 0.f);
}

// ---------------- host driver ----------------
static float* symaddr(const void* sym)
{
    void* p = nullptr;
    cudaGetSymbolAddress(&p, sym);
    return (float*)p;
}

extern "C" void kernel_launch(void* const* d_in, const int* in_sizes, int n_in,
                              void* d_out, int out_size)
{
    const float* x  = (const float*)d_in[0];
    const int*   ei = (const int*)d_in[1];
    const float* ea = (const float*)d_in[2];
    // layer 1: Wq1 bq1 Wk1 bk1 Wv1 bv1 We1 be1 Ws1 bs1 (indices 3..12)
    const float* Wq1 = (const float*)d_in[3];  const float* bq1 = (const float*)d_in[4];
    const float* Wk1 = (const float*)d_in[5];  const float* bk1 = (const float*)d_in[6];
    const float* Wv1 = (const float*)d_in[7];  const float* bv1 = (const float*)d_in[8];
    const float* We1 = (const float*)d_in[9];  const float* be1 = (const float*)d_in[10];
    const float* Ws1 = (const float*)d_in[11]; const float* bs1 = (const float*)d_in[12];
    // layer 2 (indices 13..22)
    const float* Wq2 = (const float*)d_in[13]; const float* bq2 = (const float*)d_in[14];
    const float* Wk2 = (const float*)d_in[15]; const float* bk2 = (const float*)d_in[16];
    const float* Wv2 = (const float*)d_in[17]; const float* bv2 = (const float*)d_in[18];
    const float* We2 = (const float*)d_in[19]; const float* be2 = (const float*)d_in[20];
    const float* Ws2 = (const float*)d_in[21]; const float* bs2 = (const float*)d_in[22];

    static float *q = nullptr, *k, *v, *s, *h, *e;
    if (!q) {
        q = symaddr(g_q); k = symaddr(g_k); v = symaddr(g_v);
        s = symaddr(g_s); h = symaddr(g_h); e = symaddr(g_e);
    }
    float* out = (float*)d_out;

    const dim3 gNode(DD / 128, (Nn + 127) / 128);   // 2 x 391
    const dim3 gEdge(DD / 128, Ee / 128);           // 2 x 6250
    const int  bInit = (Nn * DD + 255) / 256;
    const int  bWarpEdge = (Ee * 32 + 255) / 256;   // 1 warp / edge
    const int  bEH = (Ee * Hh + 255) / 256;

    // ---------- layer 1 (input x, K = 256) ----------
    sgemm_bias<<<gNode, 256>>>(Nn, DD, DD, x, Wq1, bq1, q);
    sgemm_bias<<<gNode, 256>>>(Nn, DD, DD, x, Wk1, bk1, k);
    sgemm_bias<<<gNode, 256>>>(Nn, DD, DD, x, Wv1, bv1, v);
    sgemm_bias<<<gNode, 256>>>(Nn, DD, DD, x, Ws1, bs1, s);
    sgemm_bias<<<gEdge, 256>>>(Ee, DD, EDD, ea, We1, be1, e);

    init_nodes<<<bInit, 256>>>(s, h);
    alpha_kernel<<<bWarpEdge, 256>>>(ei, q, k, e);
    expsum_kernel<<<bEH, 256>>>(ei);
    scatter_kernel<<<bWarpEdge, 256>>>(ei, v, e, h);
    relu_kernel<<<bInit, 256>>>(h, Nn * DD);

    // ---------- layer 2 (input h, K = 256) ----------
    sgemm_bias<<<gNode, 256>>>(Nn, DD, DD, h, Wq2, bq2, q);
    sgemm_bias<<<gNode, 256>>>(Nn, DD, DD, h, Wk2, bk2, k);
    sgemm_bias<<<gNode, 256>>>(Nn, DD, DD, h, Wv2, bv2, v);
    sgemm_bias<<<gNode, 256>>>(Nn, DD, DD, h, Ws2, bs2, s);
    sgemm_bias<<<gEdge, 256>>>(Ee, DD, EDD, ea, We2, be2, e);

    init_nodes<<<bInit, 256>>>(s, out);
    alpha_kernel<<<bWarpEdge, 256>>>(ei, q, k, e);
    expsum_kernel<<<bEH, 256>>>(ei);
    scatter_kernel<<<bWarpEdge, 256>>>(ei, v, e, out);
}

// round 3
// speedup vs baseline: 1.2930x; 1.2930x over previous
#include <cuda_runtime.h>
#include <cuda_bf16.h>
#include <math.h>
#include <math_constants.h>
#include <cstdint>

#define Nn   50000
#define Ee   800000
#define DD   256
#define EDD  128
#define Hh   4

// ================= scratch (device globals) =================
__device__ float g_q[Nn * DD];
__device__ float g_k[Nn * DD];
__device__ float g_v[Nn * DD];
__device__ float g_h[Nn * DD];
__device__ float g_e[(size_t)Ee * DD];
__device__ float g_alpha[(size_t)Ee * Hh];
__device__ float g_amax[Nn * Hh];
__device__ float g_denom[Nn * Hh];
__device__ float g_wt[10 * 256 * 256];   // K-major transposed weights

// ================= mma.sync helpers (baseline sm_80+ PTX) =================
__device__ __forceinline__ uint32_t smem_u32(const void* p) {
    uint32_t a;
    asm("{ .reg .u64 t; cvta.to.shared.u64 t, %1; cvt.u32.u64 %0, t; }"
        : "=r"(a) : "l"(p));
    return a;
}
__device__ __forceinline__ void ldsm_x4(uint32_t* r, uint32_t a) {
    asm volatile("ldmatrix.sync.aligned.m8n8.x4.shared.b16 {%0,%1,%2,%3}, [%4];"
        : "=r"(r[0]), "=r"(r[1]), "=r"(r[2]), "=r"(r[3]) : "r"(a));
}
__device__ __forceinline__ void ldsm_x2(uint32_t* r, uint32_t a) {
    asm volatile("ldmatrix.sync.aligned.m8n8.x2.shared.b16 {%0,%1}, [%2];"
        : "=r"(r[0]), "=r"(r[1]) : "r"(a));
}
__device__ __forceinline__ void mma_bf16(float* d, const uint32_t* a, const uint32_t* b) {
    asm volatile("mma.sync.aligned.m16n8k16.row.col.f32.bf16.bf16.f32 "
        "{%0,%1,%2,%3}, {%4,%5,%6,%7}, {%8,%9}, {%0,%1,%2,%3};"
        : "+f"(d[0]), "+f"(d[1]), "+f"(d[2]), "+f"(d[3])
        : "r"(a[0]), "r"(a[1]), "r"(a[2]), "r"(a[3]), "r"(b[0]), "r"(b[1]));
}

// ================= bf16x3 GEMM: C[M,256] = A[M,K] @ Bt[256,K]^T + bias =======
// Block 128x128, BK=32, 8 warps each computing 64x32 via m16n8k16 tiles.
#define BM 128
#define BN 128
#define BKc 32
#define PAD 40   // smem row pitch in bf16 elems (80B rows -> conflict-free ldmatrix)

__global__ __launch_bounds__(256, 1) void gemm_mma(
    int M, int K,
    const float* __restrict__ A, const float* __restrict__ Bt,
    const float* __restrict__ bias, float* __restrict__ C)
{
    __shared__ __nv_bfloat16 Ah[BM * PAD], Al[BM * PAD];
    __shared__ __nv_bfloat16 Bh[BN * PAD], Bl[BN * PAD];

    const int tid  = threadIdx.x;
    const int lane = tid & 31;
    const int wid  = tid >> 5;
    const int wm   = wid >> 2;          // 0..1 : 64-row slice
    const int wn   = wid & 3;           // 0..3 : 32-col slice
    const int row0 = blockIdx.y * BM;
    const int col0 = blockIdx.x * BN;

    const int lr = tid >> 1;            // loader row 0..127
    const int lc = (tid & 1) * 16;      // loader col base (16 floats each)

    const uint32_t sAh = smem_u32(Ah), sAl = smem_u32(Al);
    const uint32_t sBh = smem_u32(Bh), sBl = smem_u32(Bl);

    // ldmatrix per-lane address components
    const int aRow    = lane & 15;
    const int aColSel = (lane >> 4) * 8;
    const int bRow    = lane & 7;
    const int bColSel = ((lane >> 3) & 1) * 8;

    float acc[4][4][4];
    #pragma unroll
    for (int i = 0; i < 4; i++)
        #pragma unroll
        for (int j = 0; j < 4; j++)
            #pragma unroll
            for (int t = 0; t < 4; t++) acc[i][j][t] = 0.f;

    for (int k0 = 0; k0 < K; k0 += BKc) {
        // ---- load + split A chunk ----
        {
            const int gr = row0 + lr;
            const float* ap = A + (size_t)gr * K + k0 + lc;
            #pragma unroll
            for (int i = 0; i < 4; i++) {
                float4 v = (gr < M) ? *(const float4*)(ap + i * 4)
                                    : make_float4(0.f, 0.f, 0.f, 0.f);
                __nv_bfloat162 h0 = __floats2bfloat162_rn(v.x, v.y);
                __nv_bfloat162 h1 = __floats2bfloat162_rn(v.z, v.w);
                __nv_bfloat162 l0 = __floats2bfloat162_rn(v.x - __low2float(h0),
                                                          v.y - __high2float(h0));
                __nv_bfloat162 l1 = __floats2bfloat162_rn(v.z - __low2float(h1),
                                                          v.w - __high2float(h1));
                const int o = lr * PAD + lc + i * 4;
                *(__nv_bfloat162*)&Ah[o]     = h0;
                *(__nv_bfloat162*)&Ah[o + 2] = h1;
                *(__nv_bfloat162*)&Al[o]     = l0;
                *(__nv_bfloat162*)&Al[o + 2] = l1;
            }
        }
        // ---- load + split B chunk (Bt is [256][K] K-major) ----
        {
            const float* bp = Bt + (size_t)(col0 + lr) * K + k0 + lc;
            #pragma unroll
            for (int i = 0; i < 4; i++) {
                float4 v = *(const float4*)(bp + i * 4);
                __nv_bfloat162 h0 = __floats2bfloat162_rn(v.x, v.y);
                __nv_bfloat162 h1 = __floats2bfloat162_rn(v.z, v.w);
                __nv_bfloat162 l0 = __floats2bfloat162_rn(v.x - __low2float(h0),
                                                          v.y - __high2float(h0));
                __nv_bfloat162 l1 = __floats2bfloat162_rn(v.z - __low2float(h1),
                                                          v.w - __high2float(h1));
                const int o = lr * PAD + lc + i * 4;
                *(__nv_bfloat162*)&Bh[o]     = h0;
                *(__nv_bfloat162*)&Bh[o + 2] = h1;
                *(__nv_bfloat162*)&Bl[o]     = l0;
                *(__nv_bfloat162*)&Bl[o + 2] = l1;
            }
        }
        __syncthreads();

        #pragma unroll
        for (int ks = 0; ks < 2; ks++) {
            const int kb = ks * 16;
            uint32_t ah[4][4], al[4][4], bh[4][2], bl[4][2];
            #pragma unroll
            for (int mt = 0; mt < 4; mt++) {
                const uint32_t off =
                    (uint32_t)((wm * 64 + mt * 16 + aRow) * PAD + kb + aColSel) * 2;
                ldsm_x4(ah[mt], sAh + off);
                ldsm_x4(al[mt], sAl + off);
            }
            #pragma unroll
            for (int nt = 0; nt < 4; nt++) {
                const uint32_t off =
                    (uint32_t)((wn * 32 + nt * 8 + bRow) * PAD + kb + bColSel) * 2;
                ldsm_x2(bh[nt], sBh + off);
                ldsm_x2(bl[nt], sBl + off);
            }
            #pragma unroll
            for (int mt = 0; mt < 4; mt++)
                #pragma unroll
                for (int nt = 0; nt < 4; nt++) {
                    mma_bf16(acc[mt][nt], ah[mt], bh[nt]);
                    mma_bf16(acc[mt][nt], ah[mt], bl[nt]);
                    mma_bf16(acc[mt][nt], al[mt], bh[nt]);
                }
        }
        __syncthreads();
    }

    // ---- epilogue: c-frag (t/4, 2*(t%4)) rows +0/+8, fp32 bias ----
    #pragma unroll
    for (int mt = 0; mt < 4; mt++) {
        const int r = row0 + wm * 64 + mt * 16 + (lane >> 2);
        #pragma unroll
        for (int nt = 0; nt < 4; nt++) {
            const int c = col0 + wn * 32 + nt * 8 + (lane & 3) * 2;
            if (r < M) {
                float2 o = make_float2(acc[mt][nt][0] + bias[c],
                                       acc[mt][nt][1] + bias[c + 1]);
                *(float2*)(C + (size_t)r * 256 + c) = o;
            }
            if (r + 8 < M) {
                float2 o = make_float2(acc[mt][nt][2] + bias[c],
                                       acc[mt][nt][3] + bias[c + 1]);
                *(float2*)(C + (size_t)(r + 8) * 256 + c) = o;
            }
        }
    }
}

// ================= weight transpose: Wt[n][k] = W[k][n] =================
__global__ void transpose_w(const float* __restrict__ W, float* __restrict__ Wt, int K)
{
    const int i = blockIdx.x * blockDim.x + threadIdx.x;
    if (i < K * 256) {
        const int k = i >> 8, n = i & 255;
        Wt[n * K + k] = W[i];
    }
}

// ================= attention phase (unchanged from passing R1) ==========
__device__ __forceinline__ void atomicMaxFloat(float* addr, float val)
{
    int old = __float_as_int(*addr);
    while (__int_as_float(old) < val) {
        int assumed = old;
        old = atomicCAS((int*)addr, assumed, __float_as_int(val));
        if (old == assumed) break;
    }
}

__global__ void init_seg()
{
    const int i = blockIdx.x * blockDim.x + threadIdx.x;
    if (i < Nn * Hh) { g_amax[i] = -CUDART_INF_F; g_denom[i] = 0.f; }
}

__global__ __launch_bounds__(256) void alpha_kernel(
    const int* __restrict__ ei,
    const float* __restrict__ q, const float* __restrict__ k,
    const float* __restrict__ e)
{
    const int warp = (blockIdx.x * blockDim.x + threadIdx.x) >> 5;
    const int lane = threadIdx.x & 31;
    if (warp >= Ee) return;
    const int src = ei[warp];
    const int dst = ei[Ee + warp];
    const float4* qp = (const float4*)(q + (size_t)dst * DD);
    const float4* kp = (const float4*)(k + (size_t)src * DD);
    const float4* ep = (const float4*)(e + (size_t)warp * DD);

    float sum = 0.f;
    #pragma unroll
    for (int u = 0; u < 2; u++) {
        const int idx = lane * 2 + u;
        float4 qv = qp[idx], kv = kp[idx], ev = ep[idx];
        sum += qv.x * (kv.x + ev.x) + qv.y * (kv.y + ev.y)
             + qv.z * (kv.z + ev.z) + qv.w * (kv.w + ev.w);
    }
    sum += __shfl_xor_sync(0xffffffffu, sum, 1);
    sum += __shfl_xor_sync(0xffffffffu, sum, 2);
    sum += __shfl_xor_sync(0xffffffffu, sum, 4);
    if ((lane & 7) == 0) {
        const int h = lane >> 3;
        const float a = sum * 0.125f;
        g_alpha[(size_t)warp * Hh + h] = a;
        atomicMaxFloat(&g_amax[dst * Hh + h], a);
    }
}

__global__ void expsum_kernel(const int* __restrict__ ei)
{
    const int i = blockIdx.x * blockDim.x + threadIdx.x;
    if (i >= Ee * Hh) return;
    const int e = i >> 2, h = i & 3;
    const int dst = ei[Ee + e];
    const float ex = expf(g_alpha[i] - g_amax[dst * Hh + h]);
    g_alpha[i] = ex;
    atomicAdd(&g_denom[dst * Hh + h], ex);
}

__global__ __launch_bounds__(256) void scatter_kernel(
    const int* __restrict__ ei,
    const float* __restrict__ v, const float* __restrict__ e,
    float* __restrict__ out)
{
    const int warp = (blockIdx.x * blockDim.x + threadIdx.x) >> 5;
    const int lane = threadIdx.x & 31;
    if (warp >= Ee) return;
    const int src = ei[warp];
    const int dst = ei[Ee + warp];
    const int h = lane >> 3;
    const float w = g_alpha[(size_t)warp * Hh + h]
                  / (g_denom[dst * Hh + h] + 1e-16f);
    const float4* vp = (const float4*)(v + (size_t)src * DD);
    const float4* ep = (const float4*)(e + (size_t)warp * DD);
    float* op = out + (size_t)dst * DD;
    #pragma unroll
    for (int u = 0; u < 2; u++) {
        const int idx = lane * 2 + u;
        float4 vv = vp[idx], ev = ep[idx];
        const int c = idx * 4;
        atomicAdd(op + c + 0, (vv.x + ev.x) * w);
        atomicAdd(op + c + 1, (vv.y + ev.y) * w);
        atomicAdd(op + c + 2, (vv.z + ev.z) * w);
        atomicAdd(op + c + 3, (vv.w + ev.w) * w);
    }
}

__global__ void relu_kernel(float* __restrict__ x, int n)
{
    const int i = blockIdx.x * blockDim.x + threadIdx.x;
    if (i < n) x[i] = fmaxf(x[i], 0.f);
}

// ================= host driver =================
static float* symaddr(const void* sym)
{
    void* p = nullptr;
    cudaGetSymbolAddress(&p, sym);
    return (float*)p;
}

extern "C" void kernel_launch(void* const* d_in, const int* in_sizes, int n_in,
                              void* d_out, int out_size)
{
    const float* x  = (const float*)d_in[0];
    const int*   ei = (const int*)d_in[1];
    const float* ea = (const float*)d_in[2];
    const float* W1[5] = { (const float*)d_in[3],  (const float*)d_in[5],
                           (const float*)d_in[7],  (const float*)d_in[9],
                           (const float*)d_in[11] };               // Wq Wk Wv We Ws
    const float* b1[5] = { (const float*)d_in[4],  (const float*)d_in[6],
                           (const float*)d_in[8],  (const float*)d_in[10],
                           (const float*)d_in[12] };
    const float* W2[5] = { (const float*)d_in[13], (const float*)d_in[15],
                           (const float*)d_in[17], (const float*)d_in[19],
                           (const float*)d_in[21] };
    const float* b2[5] = { (const float*)d_in[14], (const float*)d_in[16],
                           (const float*)d_in[18], (const float*)d_in[20],
                           (const float*)d_in[22] };

    static float *q = nullptr, *k, *v, *h, *e, *wt;
    if (!q) {
        q = symaddr(g_q); k = symaddr(g_k); v = symaddr(g_v);
        h = symaddr(g_h); e = symaddr(g_e); wt = symaddr(g_wt);
    }
    float* out = (float*)d_out;

    // transpose all 10 weights to K-major
    const int Kdim[5] = { 256, 256, 256, 128, 256 };
    for (int i = 0; i < 5; i++) {
        transpose_w<<<(Kdim[i] * 256 + 255) / 256, 256>>>(W1[i], wt + i * 65536, Kdim[i]);
        transpose_w<<<(Kdim[i] * 256 + 255) / 256, 256>>>(W2[i], wt + (5 + i) * 65536, Kdim[i]);
    }

    const dim3 gNode(2, (Nn + 127) / 128);
    const dim3 gEdge(2, Ee / 128);
    const int  bWarpEdge = (Ee * 32 + 255) / 256;
    const int  bEH = (Ee * Hh + 255) / 256;
    const int  bInit = (Nn * Hh + 255) / 256;
    const int  bRelu = (Nn * DD + 255) / 256;

    // ---------- layer 1 ----------
    gemm_mma<<<gNode, 256>>>(Nn, 256, x, wt + 0 * 65536, b1[0], q);
    gemm_mma<<<gNode, 256>>>(Nn, 256, x, wt + 1 * 65536, b1[1], k);
    gemm_mma<<<gNode, 256>>>(Nn, 256, x, wt + 2 * 65536, b1[2], v);
    gemm_mma<<<gNode, 256>>>(Nn, 256, x, wt + 4 * 65536, b1[4], h);   // skip -> acc
    gemm_mma<<<gEdge, 256>>>(Ee, 128, ea, wt + 3 * 65536, b1[3], e);

    init_seg<<<bInit, 256>>>();
    alpha_kernel<<<bWarpEdge, 256>>>(ei, q, k, e);
    expsum_kernel<<<bEH, 256>>>(ei);
    scatter_kernel<<<bWarpEdge, 256>>>(ei, v, e, h);
    relu_kernel<<<bRelu, 256>>>(h, Nn * DD);

    // ---------- layer 2 ----------
    gemm_mma<<<gNode, 256>>>(Nn, 256, h, wt + 5 * 65536, b2[0], q);
    gemm_mma<<<gNode, 256>>>(Nn, 256, h, wt + 6 * 65536, b2[1], k);
    gemm_mma<<<gNode, 256>>>(Nn, 256, h, wt + 7 * 65536, b2[2], v);
    gemm_mma<<<gNode, 256>>>(Nn, 256, h, wt + 9 * 65536, b2[4], out); // skip -> acc
    gemm_mma<<<gEdge, 256>>>(Ee, 128, ea, wt + 8 * 65536, b2[3], e);

    init_seg<<<bInit, 256>>>();
    alpha_kernel<<<bWarpEdge, 256>>>(ei, q, k, e);
    expsum_kernel<<<bEH, 256>>>(ei);
    scatter_kernel<<<bWarpEdge, 256>>>(ei, v, e, out);
}

// round 4
// speedup vs baseline: 1.9660x; 1.5205x over previous
#include <cuda_runtime.h>
#include <cuda_bf16.h>
#include <math.h>
#include <math_constants.h>
#include <cstdint>

#define Nn   50000
#define Ee   800000
#define DD   256
#define EDD  128
#define Hh   4

typedef __nv_bfloat16 bf16;

// ================= scratch (device globals) =================
__device__ float g_q[Nn * DD];
__device__ float g_k[Nn * DD];
__device__ float g_v[Nn * DD];
__device__ float g_h[Nn * DD];
__device__ float g_e[(size_t)Ee * DD];
__device__ float g_alpha[(size_t)Ee * Hh];
__device__ float g_amax[Nn * Hh];
__device__ float g_denom[Nn * Hh];
// pre-split bf16 operands
__device__ bf16 g_xhi[Nn * DD], g_xlo[Nn * DD];
__device__ bf16 g_ehi[(size_t)Ee * EDD], g_elo[(size_t)Ee * EDD];
#define WOFF_QKVS1 0
#define WOFF_E1    262144
#define WOFF_QKVS2 294912
#define WOFF_E2    557056
__device__ bf16 g_whi[589824], g_wlo[589824];

// ================= PTX helpers =================
__device__ __forceinline__ uint32_t smem_u32(const void* p) {
    uint32_t a;
    asm("{ .reg .u64 t; cvta.to.shared.u64 t, %1; cvt.u32.u64 %0, t; }"
        : "=r"(a) : "l"(p));
    return a;
}
__device__ __forceinline__ void ldsm_x4(uint32_t* r, uint32_t a) {
    asm volatile("ldmatrix.sync.aligned.m8n8.x4.shared.b16 {%0,%1,%2,%3}, [%4];"
        : "=r"(r[0]), "=r"(r[1]), "=r"(r[2]), "=r"(r[3]) : "r"(a));
}
__device__ __forceinline__ void ldsm_x2(uint32_t* r, uint32_t a) {
    asm volatile("ldmatrix.sync.aligned.m8n8.x2.shared.b16 {%0,%1}, [%2];"
        : "=r"(r[0]), "=r"(r[1]) : "r"(a));
}
__device__ __forceinline__ void mma_bf16(float* d, const uint32_t* a, const uint32_t* b) {
    asm volatile("mma.sync.aligned.m16n8k16.row.col.f32.bf16.bf16.f32 "
        "{%0,%1,%2,%3}, {%4,%5,%6,%7}, {%8,%9}, {%0,%1,%2,%3};"
        : "+f"(d[0]), "+f"(d[1]), "+f"(d[2]), "+f"(d[3])
        : "r"(a[0]), "r"(a[1]), "r"(a[2]), "r"(a[3]), "r"(b[0]), "r"(b[1]));
}
__device__ __forceinline__ void cpa16(uint32_t dst, const void* src, int sz) {
    asm volatile("cp.async.cg.shared.global [%0], [%1], 16, %2;"
        :: "r"(dst), "l"(src), "r"(sz) : "memory");
}
#define CP_COMMIT() asm volatile("cp.async.commit_group;" ::: "memory")
#define CP_WAIT1()  asm volatile("cp.async.wait_group 1;" ::: "memory")
#define CP_WAIT0()  asm volatile("cp.async.wait_group 0;" ::: "memory")

// ================= bf16x3 pipelined GEMM ============================
// C[M, col] = A @ Wfused^T + bias.  Block 128 rows x 128 cols, BK=32 chunks.
// Fused W has (#outs * 256) K-major rows; colblock b -> output (b>>1),
// local cols (b&1)*128.  2-stage cp.async pipeline, pre-split bf16 inputs.
#define PAD 40   // bf16 elems per smem row (80B pitch -> conflict-free ldmatrix)
#define STG_B 40960            // bytes per stage (4 tiles * 128*40*2)
#define OFF_AL 10240
#define OFF_BH 20480
#define OFF_BL 30720
#define GEMM_SMEM (2 * STG_B)

__global__ __launch_bounds__(256) void gemm_bf3(
    int M, int K,
    const bf16* __restrict__ Ahi, const bf16* __restrict__ Alo,
    const bf16* __restrict__ Whi, const bf16* __restrict__ Wlo,
    float* c0, float* c1, float* c2, float* c3,
    const float* b0, const float* b1, const float* b2, const float* b3)
{
    extern __shared__ char sm[];
    const uint32_t sb = smem_u32(sm);

    const int tid  = threadIdx.x;
    const int lane = tid & 31;
    const int wid  = tid >> 5;
    const int wm   = wid >> 2;
    const int wn   = wid & 3;
    const int row0 = blockIdx.y * 128;
    const int nW0  = blockIdx.x * 128;          // row into fused W

    float* const outs[4]       = { c0, c1, c2, c3 };
    const float* const biases[4] = { b0, b1, b2, b3 };
    float*       Cout = outs[blockIdx.x >> 1];
    const float* bias = biases[blockIdx.x >> 1];
    const int    colb = (blockIdx.x & 1) * 128;

    // loader geometry: thread -> (row lr, 16-elem half lcb), 32B per matrix
    const int lr  = tid >> 1;
    const int lcb = (tid & 1) * 16;
    const int grA  = row0 + lr;
    const int okA  = (grA < M) ? 16 : 0;
    const size_t aoff = (size_t)(okA ? grA : 0) * K + lcb;
    const size_t boff = (size_t)(nW0 + lr) * K + lcb;
    const char* pAh = (const char*)(Ahi + aoff);
    const char* pAl = (const char*)(Alo + aoff);
    const char* pBh = (const char*)(Whi + boff);
    const char* pBl = (const char*)(Wlo + boff);
    const uint32_t dstA = sb + (uint32_t)(lr * 80 + (tid & 1) * 32);

    const int nchunk = K >> 5;

    // ldmatrix lane addressing
    const int aRow    = lane & 15;
    const int aColSel = (lane >> 4) * 8;
    const int bRow    = lane & 7;
    const int bColSel = ((lane >> 3) & 1) * 8;

    float acc[4][4][4];
    #pragma unroll
    for (int i = 0; i < 4; i++)
        #pragma unroll
        for (int j = 0; j < 4; j++)
            #pragma unroll
            for (int t = 0; t < 4; t++) acc[i][j][t] = 0.f;

    // ---- prefetch chunk 0 into stage 0 ----
    {
        cpa16(dstA,               pAh,      okA);
        cpa16(dstA + 16,          pAh + 16, okA);
        cpa16(dstA + OFF_AL,      pAl,      okA);
        cpa16(dstA + OFF_AL + 16, pAl + 16, okA);
        cpa16(dstA + OFF_BH,      pBh,      16);
        cpa16(dstA + OFF_BH + 16, pBh + 16, 16);
        cpa16(dstA + OFF_BL,      pBl,      16);
        cpa16(dstA + OFF_BL + 16, pBl + 16, 16);
        CP_COMMIT();
    }

    for (int c = 0; c < nchunk; c++) {
        if (c + 1 < nchunk) {
            const uint32_t d = dstA + ((c + 1) & 1) * STG_B;
            const int go = (c + 1) * 64;        // 32 elems * 2B
            cpa16(d,               pAh + go,      okA);
            cpa16(d + 16,          pAh + go + 16, okA);
            cpa16(d + OFF_AL,      pAl + go,      okA);
            cpa16(d + OFF_AL + 16, pAl + go + 16, okA);
            cpa16(d + OFF_BH,      pBh + go,      16);
            cpa16(d + OFF_BH + 16, pBh + go + 16, 16);
            cpa16(d + OFF_BL,      pBl + go,      16);
            cpa16(d + OFF_BL + 16, pBl + go + 16, 16);
            CP_COMMIT();
            CP_WAIT1();
        } else {
            CP_WAIT0();
        }
        __syncthreads();

        const uint32_t sbase = sb + (c & 1) * STG_B;
        #pragma unroll
        for (int ks = 0; ks < 2; ks++) {
            const int kb = ks * 16;
            uint32_t ah[4][4], al[4][4], bh[4][2], bl[4][2];
            #pragma unroll
            for (int mt = 0; mt < 4; mt++) {
                const uint32_t off = sbase +
                    (uint32_t)((wm * 64 + mt * 16 + aRow) * PAD + kb + aColSel) * 2;
                ldsm_x4(ah[mt], off);
                ldsm_x4(al[mt], off + OFF_AL);
            }
            #pragma unroll
            for (int nt = 0; nt < 4; nt++) {
                const uint32_t off = sbase + OFF_BH +
                    (uint32_t)((wn * 32 + nt * 8 + bRow) * PAD + kb + bColSel) * 2;
                ldsm_x2(bh[nt], off);
                ldsm_x2(bl[nt], off + (OFF_BL - OFF_BH));
            }
            #pragma unroll
            for (int mt = 0; mt < 4; mt++)
                #pragma unroll
                for (int nt = 0; nt < 4; nt++) {
                    mma_bf16(acc[mt][nt], ah[mt], bh[nt]);
                    mma_bf16(acc[mt][nt], ah[mt], bl[nt]);
                    mma_bf16(acc[mt][nt], al[mt], bh[nt]);
                }
        }
        __syncthreads();
    }

    // ---- epilogue ----
    #pragma unroll
    for (int mt = 0; mt < 4; mt++) {
        const int r = row0 + wm * 64 + mt * 16 + (lane >> 2);
        #pragma unroll
        for (int nt = 0; nt < 4; nt++) {
            const int c = colb + wn * 32 + nt * 8 + (lane & 3) * 2;
            if (r < M) {
                float2 o = make_float2(acc[mt][nt][0] + bias[c],
                                       acc[mt][nt][1] + bias[c + 1]);
                *(float2*)(Cout + (size_t)r * 256 + c) = o;
            }
            if (r + 8 < M) {
                float2 o = make_float2(acc[mt][nt][2] + bias[c],
                                       acc[mt][nt][3] + bias[c + 1]);
                *(float2*)(Cout + (size_t)(r + 8) * 256 + c) = o;
            }
        }
    }
}

// ======== weight transpose + split: hi/lo[n][k] = split(W[k][n]) ========
__global__ void tsplit_w(const float* __restrict__ W,
                         bf16* __restrict__ hi, bf16* __restrict__ lo, int K)
{
    const int i = blockIdx.x * blockDim.x + threadIdx.x;
    if (i < K * 256) {
        const int k = i >> 8, n = i & 255;
        const float v = W[i];
        const bf16 h = __float2bfloat16(v);
        hi[(size_t)n * K + k] = h;
        lo[(size_t)n * K + k] = __float2bfloat16(v - __bfloat162float(h));
    }
}

// ======== elementwise fp32 -> bf16 hi/lo split (n divisible by 4) ========
__global__ void split_bf(const float* __restrict__ in,
                         bf16* __restrict__ hi, bf16* __restrict__ lo, size_t n4)
{
    const size_t i = (size_t)blockIdx.x * blockDim.x + threadIdx.x;
    if (i >= n4) return;
    float4 v = ((const float4*)in)[i];
    __nv_bfloat162 h0 = __floats2bfloat162_rn(v.x, v.y);
    __nv_bfloat162 h1 = __floats2bfloat162_rn(v.z, v.w);
    __nv_bfloat162 l0 = __floats2bfloat162_rn(v.x - __low2float(h0), v.y - __high2float(h0));
    __nv_bfloat162 l1 = __floats2bfloat162_rn(v.z - __low2float(h1), v.w - __high2float(h1));
    ((__nv_bfloat162*)hi)[2 * i]     = h0;
    ((__nv_bfloat162*)hi)[2 * i + 1] = h1;
    ((__nv_bfloat162*)lo)[2 * i]     = l0;
    ((__nv_bfloat162*)lo)[2 * i + 1] = l1;
}

// relu then split (layer-1 output -> layer-2 input)
__global__ void relu_split(const float* __restrict__ in,
                           bf16* __restrict__ hi, bf16* __restrict__ lo, size_t n4)
{
    const size_t i = (size_t)blockIdx.x * blockDim.x + threadIdx.x;
    if (i >= n4) return;
    float4 v = ((const float4*)in)[i];
    v.x = fmaxf(v.x, 0.f); v.y = fmaxf(v.y, 0.f);
    v.z = fmaxf(v.z, 0.f); v.w = fmaxf(v.w, 0.f);
    __nv_bfloat162 h0 = __floats2bfloat162_rn(v.x, v.y);
    __nv_bfloat162 h1 = __floats2bfloat162_rn(v.z, v.w);
    __nv_bfloat162 l0 = __floats2bfloat162_rn(v.x - __low2float(h0), v.y - __high2float(h0));
    __nv_bfloat162 l1 = __floats2bfloat162_rn(v.z - __low2float(h1), v.w - __high2float(h1));
    ((__nv_bfloat162*)hi)[2 * i]     = h0;
    ((__nv_bfloat162*)hi)[2 * i + 1] = h1;
    ((__nv_bfloat162*)lo)[2 * i]     = l0;
    ((__nv_bfloat162*)lo)[2 * i + 1] = l1;
}

// ================= attention phase =================
__device__ __forceinline__ void atomicMaxFloat(float* addr, float val)
{
    int old = __float_as_int(*addr);
    while (__int_as_float(old) < val) {
        int assumed = old;
        old = atomicCAS((int*)addr, assumed, __float_as_int(val));
        if (old == assumed) break;
    }
}

__global__ void init_seg()
{
    const int i = blockIdx.x * blockDim.x + threadIdx.x;
    if (i < Nn * Hh) { g_amax[i] = -CUDART_INF_F; g_denom[i] = 0.f; }
}

__global__ __launch_bounds__(256) void alpha_kernel(
    const int* __restrict__ ei,
    const float* __restrict__ q, const float* __restrict__ k,
    const float* __restrict__ e)
{
    const int warp = (blockIdx.x * blockDim.x + threadIdx.x) >> 5;
    const int lane = threadIdx.x & 31;
    if (warp >= Ee) return;
    const int src = ei[warp];
    const int dst = ei[Ee + warp];
    const float4* qp = (const float4*)(q + (size_t)dst * DD);
    const float4* kp = (const float4*)(k + (size_t)src * DD);
    const float4* ep = (const float4*)(e + (size_t)warp * DD);

    float sum = 0.f;
    #pragma unroll
    for (int u = 0; u < 2; u++) {
        const int idx = lane * 2 + u;
        float4 qv = qp[idx], kv = kp[idx], ev = ep[idx];
        sum += qv.x * (kv.x + ev.x) + qv.y * (kv.y + ev.y)
             + qv.z * (kv.z + ev.z) + qv.w * (kv.w + ev.w);
    }
    sum += __shfl_xor_sync(0xffffffffu, sum, 1);
    sum += __shfl_xor_sync(0xffffffffu, sum, 2);
    sum += __shfl_xor_sync(0xffffffffu, sum, 4);
    if ((lane & 7) == 0) {
        const int h = lane >> 3;
        const float a = sum * 0.125f;
        g_alpha[(size_t)warp * Hh + h] = a;
        atomicMaxFloat(&g_amax[dst * Hh + h], a);
    }
}

__global__ void expsum_kernel(const int* __restrict__ ei)
{
    const int i = blockIdx.x * blockDim.x + threadIdx.x;
    if (i >= Ee * Hh) return;
    const int e = i >> 2, h = i & 3;
    const int dst = ei[Ee + e];
    const float ex = expf(g_alpha[i] - g_amax[dst * Hh + h]);
    g_alpha[i] = ex;
    atomicAdd(&g_denom[dst * Hh + h], ex);
}

__global__ __launch_bounds__(256) void scatter_kernel(
    const int* __restrict__ ei,
    const float* __restrict__ v, const float* __restrict__ e,
    float* __restrict__ out)
{
    const int warp = (blockIdx.x * blockDim.x + threadIdx.x) >> 5;
    const int lane = threadIdx.x & 31;
    if (warp >= Ee) return;
    const int src = ei[warp];
    const int dst = ei[Ee + warp];
    const int h = lane >> 3;
    const float w = g_alpha[(size_t)warp * Hh + h]
                  / (g_denom[dst * Hh + h] + 1e-16f);
    const float4* vp = (const float4*)(v + (size_t)src * DD);
    const float4* ep = (const float4*)(e + (size_t)warp * DD);
    float* op = out + (size_t)dst * DD;
    #pragma unroll
    for (int u = 0; u < 2; u++) {
        const int idx = lane * 2 + u;
        float4 vv = vp[idx], ev = ep[idx];
        asm volatile("red.global.add.v4.f32 [%0], {%1, %2, %3, %4};"
            :: "l"(op + idx * 4),
               "f"((vv.x + ev.x) * w), "f"((vv.y + ev.y) * w),
               "f"((vv.z + ev.z) * w), "f"((vv.w + ev.w) * w)
            : "memory");
    }
}

// ================= host driver =================
static void* symaddr(const void* sym)
{
    void* p = nullptr;
    cudaGetSymbolAddress(&p, sym);
    return p;
}

extern "C" void kernel_launch(void* const* d_in, const int* in_sizes, int n_in,
                              void* d_out, int out_size)
{
    const float* x  = (const float*)d_in[0];
    const int*   ei = (const int*)d_in[1];
    const float* ea = (const float*)d_in[2];
    const float* W1[5] = { (const float*)d_in[3],  (const float*)d_in[5],
                           (const float*)d_in[7],  (const float*)d_in[9],
                           (const float*)d_in[11] };               // Wq Wk Wv We Ws
    const float* b1[5] = { (const float*)d_in[4],  (const float*)d_in[6],
                           (const float*)d_in[8],  (const float*)d_in[10],
                           (const float*)d_in[12] };
    const float* W2[5] = { (const float*)d_in[13], (const float*)d_in[15],
                           (const float*)d_in[17], (const float*)d_in[19],
                           (const float*)d_in[21] };
    const float* b2[5] = { (const float*)d_in[14], (const float*)d_in[16],
                           (const float*)d_in[18], (const float*)d_in[20],
                           (const float*)d_in[22] };

    static float *q = nullptr, *k, *v, *h, *e;
    static bf16 *xhi, *xlo, *ehi, *elo, *whi, *wlo;
    if (!q) {
        q = (float*)symaddr(g_q); k = (float*)symaddr(g_k);
        v = (float*)symaddr(g_v); h = (float*)symaddr(g_h);
        e = (float*)symaddr(g_e);
        xhi = (bf16*)symaddr(g_xhi); xlo = (bf16*)symaddr(g_xlo);
        ehi = (bf16*)symaddr(g_ehi); elo = (bf16*)symaddr(g_elo);
        whi = (bf16*)symaddr(g_whi); wlo = (bf16*)symaddr(g_wlo);
        cudaFuncSetAttribute(gemm_bf3,
            cudaFuncAttributeMaxDynamicSharedMemorySize, GEMM_SMEM);
    }
    float* out = (float*)d_out;

    // ---- weight transpose + split (fused QKVS layout: q,k,v,s at 256-row steps)
    for (int s = 0; s < 4; s++) {
        tsplit_w<<<256, 256>>>(W1[s], whi + WOFF_QKVS1 + (size_t)s * 65536,
                                      wlo + WOFF_QKVS1 + (size_t)s * 65536, 256);
        tsplit_w<<<256, 256>>>(W2[s == 3 ? 4 : s], // placeholder, fixed below
                                      whi + WOFF_QKVS2 + (size_t)s * 65536,
                                      wlo + WOFF_QKVS2 + (size_t)s * 65536, 256);
    }
    // fix: order for QKVS is Wq,Wk,Wv,Ws = indices 0,1,2,4 of W arrays
    tsplit_w<<<256, 256>>>(W1[4], whi + WOFF_QKVS1 + 3u * 65536,
                                  wlo + WOFF_QKVS1 + 3u * 65536, 256);
    tsplit_w<<<256, 256>>>(W2[4], whi + WOFF_QKVS2 + 3u * 65536,
                                  wlo + WOFF_QKVS2 + 3u * 65536, 256);
    tsplit_w<<<128, 256>>>(W1[3], whi + WOFF_E1, wlo + WOFF_E1, 128);
    tsplit_w<<<128, 256>>>(W2[3], whi + WOFF_E2, wlo + WOFF_E2, 128);

    // ---- activation splits
    split_bf<<<(Nn * DD / 4 + 255) / 256, 256>>>(x, xhi, xlo, (size_t)Nn * DD / 4);
    split_bf<<<((size_t)Ee * EDD / 4 + 255) / 256, 256>>>(ea, ehi, elo, (size_t)Ee * EDD / 4);

    const dim3 gQKVS(8, (Nn + 127) / 128);
    const dim3 gEdge(2, Ee / 128);
    const int  bWarpEdge = (Ee * 32 + 255) / 256;
    const int  bEH = (Ee * Hh + 255) / 256;
    const int  bInit = (Nn * Hh + 255) / 256;
    const int  bSplit = (Nn * DD / 4 + 255) / 256;

    // ---------- layer 1 ----------
    gemm_bf3<<<gQKVS, 256, GEMM_SMEM>>>(Nn, 256, xhi, xlo,
        whi + WOFF_QKVS1, wlo + WOFF_QKVS1,
        q, k, v, h, b1[0], b1[1], b1[2], b1[4]);
    gemm_bf3<<<gEdge, 256, GEMM_SMEM>>>(Ee, 128, ehi, elo,
        whi + WOFF_E1, wlo + WOFF_E1,
        e, e, e, e, b1[3], b1[3], b1[3], b1[3]);

    init_seg<<<bInit, 256>>>();
    alpha_kernel<<<bWarpEdge, 256>>>(ei, q, k, e);
    expsum_kernel<<<bEH, 256>>>(ei);
    scatter_kernel<<<bWarpEdge, 256>>>(ei, v, e, h);
    relu_split<<<bSplit, 256>>>(h, xhi, xlo, (size_t)Nn * DD / 4);

    // ---------- layer 2 ----------
    gemm_bf3<<<gQKVS, 256, GEMM_SMEM>>>(Nn, 256, xhi, xlo,
        whi + WOFF_QKVS2, wlo + WOFF_QKVS2,
        q, k, v, out, b2[0], b2[1], b2[2], b2[4]);
    gemm_bf3<<<gEdge, 256, GEMM_SMEM>>>(Ee, 128, ehi, elo,
        whi + WOFF_E2, wlo + WOFF_E2,
        e, e, e, e, b2[3], b2[3], b2[3], b2[3]);

    init_seg<<<bInit, 256>>>();
    alpha_kernel<<<bWarpEdge, 256>>>(ei, q, k, e);
    expsum_kernel<<<bEH, 256>>>(ei);
    scatter_kernel<<<bWarpEdge, 256>>>(ei, v, e, out);
}

// round 5
// speedup vs baseline: 2.3643x; 1.2026x over previous
#include <cuda_runtime.h>
#include <cuda_bf16.h>
#include <math.h>
#include <math_constants.h>
#include <cstdint>

#define Nn   50000
#define Ee   800000
#define DD   256
#define EDD  128
#define Hh   4

typedef __nv_bfloat16 bf16;

// ================= scratch (device globals) =================
__device__ float g_q[Nn * DD];
__device__ float g_k[Nn * DD];
__device__ float g_v[Nn * DD];
__device__ float g_h[Nn * DD];
__device__ float g_e[(size_t)Ee * DD];
// CSR for dst-grouped edges
__device__ int g_deg[Nn];
__device__ int g_cursor[Nn];
__device__ int g_loc[Nn];
__device__ int g_bsum[256];
__device__ int g_rowptr[Nn + 1];
__device__ int g_adj[Ee];
// pre-split bf16 operands
__device__ bf16 g_xhi[Nn * DD], g_xlo[Nn * DD];
__device__ bf16 g_ehi[(size_t)Ee * EDD], g_elo[(size_t)Ee * EDD];
#define WOFF_QKVS1 0
#define WOFF_E1    262144
#define WOFF_QKVS2 294912
#define WOFF_E2    557056
__device__ bf16 g_whi[589824], g_wlo[589824];

// ================= PTX helpers =================
__device__ __forceinline__ uint32_t smem_u32(const void* p) {
    uint32_t a;
    asm("{ .reg .u64 t; cvta.to.shared.u64 t, %1; cvt.u32.u64 %0, t; }"
        : "=r"(a) : "l"(p));
    return a;
}
__device__ __forceinline__ void ldsm_x4(uint32_t* r, uint32_t a) {
    asm volatile("ldmatrix.sync.aligned.m8n8.x4.shared.b16 {%0,%1,%2,%3}, [%4];"
        : "=r"(r[0]), "=r"(r[1]), "=r"(r[2]), "=r"(r[3]) : "r"(a));
}
__device__ __forceinline__ void ldsm_x2(uint32_t* r, uint32_t a) {
    asm volatile("ldmatrix.sync.aligned.m8n8.x2.shared.b16 {%0,%1}, [%2];"
        : "=r"(r[0]), "=r"(r[1]) : "r"(a));
}
__device__ __forceinline__ void mma_bf16(float* d, const uint32_t* a, const uint32_t* b) {
    asm volatile("mma.sync.aligned.m16n8k16.row.col.f32.bf16.bf16.f32 "
        "{%0,%1,%2,%3}, {%4,%5,%6,%7}, {%8,%9}, {%0,%1,%2,%3};"
        : "+f"(d[0]), "+f"(d[1]), "+f"(d[2]), "+f"(d[3])
        : "r"(a[0]), "r"(a[1]), "r"(a[2]), "r"(a[3]), "r"(b[0]), "r"(b[1]));
}
__device__ __forceinline__ void cpa16(uint32_t dst, const void* src, int sz) {
    asm volatile("cp.async.cg.shared.global [%0], [%1], 16, %2;"
        :: "r"(dst), "l"(src), "r"(sz) : "memory");
}
#define CP_COMMIT() asm volatile("cp.async.commit_group;" ::: "memory")
#define CP_WAIT1()  asm volatile("cp.async.wait_group 1;" ::: "memory")
#define CP_WAIT0()  asm volatile("cp.async.wait_group 0;" ::: "memory")

// ================= bf16x3 pipelined GEMM (unchanged from R4) =============
#define PAD 40
#define STG_B 40960
#define OFF_AL 10240
#define OFF_BH 20480
#define OFF_BL 30720
#define GEMM_SMEM (2 * STG_B)

__global__ __launch_bounds__(256) void gemm_bf3(
    int M, int K,
    const bf16* __restrict__ Ahi, const bf16* __restrict__ Alo,
    const bf16* __restrict__ Whi, const bf16* __restrict__ Wlo,
    float* c0, float* c1, float* c2, float* c3,
    const float* b0, const float* b1, const float* b2, const float* b3)
{
    extern __shared__ char sm[];
    const uint32_t sb = smem_u32(sm);

    const int tid  = threadIdx.x;
    const int lane = tid & 31;
    const int wid  = tid >> 5;
    const int wm   = wid >> 2;
    const int wn   = wid & 3;
    const int row0 = blockIdx.y * 128;
    const int nW0  = blockIdx.x * 128;

    float* const outs[4]         = { c0, c1, c2, c3 };
    const float* const biases[4] = { b0, b1, b2, b3 };
    float*       Cout = outs[blockIdx.x >> 1];
    const float* bias = biases[blockIdx.x >> 1];
    const int    colb = (blockIdx.x & 1) * 128;

    const int lr  = tid >> 1;
    const int lcb = (tid & 1) * 16;
    const int grA  = row0 + lr;
    const int okA  = (grA < M) ? 16 : 0;
    const size_t aoff = (size_t)(okA ? grA : 0) * K + lcb;
    const size_t boff = (size_t)(nW0 + lr) * K + lcb;
    const char* pAh = (const char*)(Ahi + aoff);
    const char* pAl = (const char*)(Alo + aoff);
    const char* pBh = (const char*)(Whi + boff);
    const char* pBl = (const char*)(Wlo + boff);
    const uint32_t dstA = sb + (uint32_t)(lr * 80 + (tid & 1) * 32);

    const int nchunk = K >> 5;

    const int aRow    = lane & 15;
    const int aColSel = (lane >> 4) * 8;
    const int bRow    = lane & 7;
    const int bColSel = ((lane >> 3) & 1) * 8;

    float acc[4][4][4];
    #pragma unroll
    for (int i = 0; i < 4; i++)
        #pragma unroll
        for (int j = 0; j < 4; j++)
            #pragma unroll
            for (int t = 0; t < 4; t++) acc[i][j][t] = 0.f;

    {
        cpa16(dstA,               pAh,      okA);
        cpa16(dstA + 16,          pAh + 16, okA);
        cpa16(dstA + OFF_AL,      pAl,      okA);
        cpa16(dstA + OFF_AL + 16, pAl + 16, okA);
        cpa16(dstA + OFF_BH,      pBh,      16);
        cpa16(dstA + OFF_BH + 16, pBh + 16, 16);
        cpa16(dstA + OFF_BL,      pBl,      16);
        cpa16(dstA + OFF_BL + 16, pBl + 16, 16);
        CP_COMMIT();
    }

    for (int c = 0; c < nchunk; c++) {
        if (c + 1 < nchunk) {
            const uint32_t d = dstA + ((c + 1) & 1) * STG_B;
            const int go = (c + 1) * 64;
            cpa16(d,               pAh + go,      okA);
            cpa16(d + 16,          pAh + go + 16, okA);
            cpa16(d + OFF_AL,      pAl + go,      okA);
            cpa16(d + OFF_AL + 16, pAl + go + 16, okA);
            cpa16(d + OFF_BH,      pBh + go,      16);
            cpa16(d + OFF_BH + 16, pBh + go + 16, 16);
            cpa16(d + OFF_BL,      pBl + go,      16);
            cpa16(d + OFF_BL + 16, pBl + go + 16, 16);
            CP_COMMIT();
            CP_WAIT1();
        } else {
            CP_WAIT0();
        }
        __syncthreads();

        const uint32_t sbase = sb + (c & 1) * STG_B;
        #pragma unroll
        for (int ks = 0; ks < 2; ks++) {
            const int kb = ks * 16;
            uint32_t ah[4][4], al[4][4], bh[4][2], bl[4][2];
            #pragma unroll
            for (int mt = 0; mt < 4; mt++) {
                const uint32_t off = sbase +
                    (uint32_t)((wm * 64 + mt * 16 + aRow) * PAD + kb + aColSel) * 2;
                ldsm_x4(ah[mt], off);
                ldsm_x4(al[mt], off + OFF_AL);
            }
            #pragma unroll
            for (int nt = 0; nt < 4; nt++) {
                const uint32_t off = sbase + OFF_BH +
                    (uint32_t)((wn * 32 + nt * 8 + bRow) * PAD + kb + bColSel) * 2;
                ldsm_x2(bh[nt], off);
                ldsm_x2(bl[nt], off + (OFF_BL - OFF_BH));
            }
            #pragma unroll
            for (int mt = 0; mt < 4; mt++)
                #pragma unroll
                for (int nt = 0; nt < 4; nt++) {
                    mma_bf16(acc[mt][nt], ah[mt], bh[nt]);
                    mma_bf16(acc[mt][nt], ah[mt], bl[nt]);
                    mma_bf16(acc[mt][nt], al[mt], bh[nt]);
                }
        }
        __syncthreads();
    }

    #pragma unroll
    for (int mt = 0; mt < 4; mt++) {
        const int r = row0 + wm * 64 + mt * 16 + (lane >> 2);
        #pragma unroll
        for (int nt = 0; nt < 4; nt++) {
            const int c = colb + wn * 32 + nt * 8 + (lane & 3) * 2;
            if (r < M) {
                float2 o = make_float2(acc[mt][nt][0] + bias[c],
                                       acc[mt][nt][1] + bias[c + 1]);
                *(float2*)(Cout + (size_t)r * 256 + c) = o;
            }
            if (r + 8 < M) {
                float2 o = make_float2(acc[mt][nt][2] + bias[c],
                                       acc[mt][nt][3] + bias[c + 1]);
                *(float2*)(Cout + (size_t)(r + 8) * 256 + c) = o;
            }
        }
    }
}

// ======== weight transpose + split ========
__global__ void tsplit_w(const float* __restrict__ W,
                         bf16* __restrict__ hi, bf16* __restrict__ lo, int K)
{
    const int i = blockIdx.x * blockDim.x + threadIdx.x;
    if (i < K * 256) {
        const int k = i >> 8, n = i & 255;
        const float v = W[i];
        const bf16 h = __float2bfloat16(v);
        hi[(size_t)n * K + k] = h;
        lo[(size_t)n * K + k] = __float2bfloat16(v - __bfloat162float(h));
    }
}

__global__ void split_bf(const float* __restrict__ in,
                         bf16* __restrict__ hi, bf16* __restrict__ lo, size_t n4)
{
    const size_t i = (size_t)blockIdx.x * blockDim.x + threadIdx.x;
    if (i >= n4) return;
    float4 v = ((const float4*)in)[i];
    __nv_bfloat162 h0 = __floats2bfloat162_rn(v.x, v.y);
    __nv_bfloat162 h1 = __floats2bfloat162_rn(v.z, v.w);
    __nv_bfloat162 l0 = __floats2bfloat162_rn(v.x - __low2float(h0), v.y - __high2float(h0));
    __nv_bfloat162 l1 = __floats2bfloat162_rn(v.z - __low2float(h1), v.w - __high2float(h1));
    ((__nv_bfloat162*)hi)[2 * i]     = h0;
    ((__nv_bfloat162*)hi)[2 * i + 1] = h1;
    ((__nv_bfloat162*)lo)[2 * i]     = l0;
    ((__nv_bfloat162*)lo)[2 * i + 1] = l1;
}

__global__ void relu_split(const float* __restrict__ in,
                           bf16* __restrict__ hi, bf16* __restrict__ lo, size_t n4)
{
    const size_t i = (size_t)blockIdx.x * blockDim.x + threadIdx.x;
    if (i >= n4) return;
    float4 v = ((const float4*)in)[i];
    v.x = fmaxf(v.x, 0.f); v.y = fmaxf(v.y, 0.f);
    v.z = fmaxf(v.z, 0.f); v.w = fmaxf(v.w, 0.f);
    __nv_bfloat162 h0 = __floats2bfloat162_rn(v.x, v.y);
    __nv_bfloat162 h1 = __floats2bfloat162_rn(v.z, v.w);
    __nv_bfloat162 l0 = __floats2bfloat162_rn(v.x - __low2float(h0), v.y - __high2float(h0));
    __nv_bfloat162 l1 = __floats2bfloat162_rn(v.z - __low2float(h1), v.w - __high2float(h1));
    ((__nv_bfloat162*)hi)[2 * i]     = h0;
    ((__nv_bfloat162*)hi)[2 * i + 1] = h1;
    ((__nv_bfloat162*)lo)[2 * i]     = l0;
    ((__nv_bfloat162*)lo)[2 * i + 1] = l1;
}

// ================= CSR build =================
__global__ void csr_zero()
{
    const int i = blockIdx.x * blockDim.x + threadIdx.x;
    if (i < Nn) { g_deg[i] = 0; g_cursor[i] = 0; }
}
__global__ void csr_count(const int* __restrict__ ei)
{
    const int i = blockIdx.x * blockDim.x + threadIdx.x;
    if (i < Ee) atomicAdd(&g_deg[ei[Ee + i]], 1);
}
__global__ void csr_scan_local()
{
    __shared__ int s[256];
    const int tid = threadIdx.x;
    const int i = blockIdx.x * 256 + tid;
    const int v = (i < Nn) ? g_deg[i] : 0;
    s[tid] = v; __syncthreads();
    for (int off = 1; off < 256; off <<= 1) {
        const int t = (tid >= off) ? s[tid - off] : 0;
        __syncthreads();
        s[tid] += t;
        __syncthreads();
    }
    if (i < Nn) g_loc[i] = s[tid] - v;       // exclusive within block
    if (tid == 255) g_bsum[blockIdx.x] = s[255];
}
__global__ void csr_scan_bsum(int nb)
{
    __shared__ int s[256];
    const int t = threadIdx.x;
    const int v = (t < nb) ? g_bsum[t] : 0;
    s[t] = v; __syncthreads();
    for (int off = 1; off < 256; off <<= 1) {
        const int u = (t >= off) ? s[t - off] : 0;
        __syncthreads();
        s[t] += u;
        __syncthreads();
    }
    if (t < nb) g_bsum[t] = s[t] - v;        // exclusive
}
__global__ void csr_finalize()
{
    const int i = blockIdx.x * blockDim.x + threadIdx.x;
    if (i < Nn) g_rowptr[i] = g_loc[i] + g_bsum[i >> 8];
    if (i == 0) g_rowptr[Nn] = Ee;
}
__global__ void csr_fill(const int* __restrict__ ei)
{
    const int eid = blockIdx.x * blockDim.x + threadIdx.x;
    if (eid < Ee) {
        const int dst = ei[Ee + eid];
        const int p = atomicAdd(&g_cursor[dst], 1);
        g_adj[g_rowptr[dst] + p] = eid;
    }
}

// ================= flash-style segment softmax + aggregate =================
// One warp per dst node. 4 heads x 8 lanes; each lane owns 8 channels.
// out[dst] += sum_e softmax(dot(q, k[src]+e)/8) * (v[src]+e)
__global__ __launch_bounds__(256) void flash_agg(
    const int* __restrict__ ei,
    const float* __restrict__ q, const float* __restrict__ k,
    const float* __restrict__ v, const float* __restrict__ e,
    float* __restrict__ out)
{
    const int warp = (blockIdx.x * blockDim.x + threadIdx.x) >> 5;
    const int lane = threadIdx.x & 31;
    if (warp >= Nn) return;
    const int beg = g_rowptr[warp];
    const int end = g_rowptr[warp + 1];
    if (beg == end) return;

    const int li = lane * 2;                 // float4 index of this lane's 8 chans
    const float4* qp = (const float4*)(q + (size_t)warp * DD);
    const float4 q0 = qp[li], q1 = qp[li + 1];

    float m = -CUDART_INF_F, d = 0.f;
    float4 a0 = make_float4(0.f, 0.f, 0.f, 0.f);
    float4 a1 = make_float4(0.f, 0.f, 0.f, 0.f);

    for (int idx = beg; idx < end; idx++) {
        const int eid = g_adj[idx];
        const int src = ei[eid];
        const float4* ep = (const float4*)(e + (size_t)eid * DD);
        const float4* kp = (const float4*)(k + (size_t)src * DD);
        const float4* vp = (const float4*)(v + (size_t)src * DD);
        const float4 e0 = ep[li], e1 = ep[li + 1];
        const float4 k0 = kp[li], k1 = kp[li + 1];
        const float4 v0 = vp[li], v1 = vp[li + 1];

        float dot = q0.x * (k0.x + e0.x) + q0.y * (k0.y + e0.y)
                  + q0.z * (k0.z + e0.z) + q0.w * (k0.w + e0.w)
                  + q1.x * (k1.x + e1.x) + q1.y * (k1.y + e1.y)
                  + q1.z * (k1.z + e1.z) + q1.w * (k1.w + e1.w);
        dot += __shfl_xor_sync(0xffffffffu, dot, 1);
        dot += __shfl_xor_sync(0xffffffffu, dot, 2);
        dot += __shfl_xor_sync(0xffffffffu, dot, 4);
        const float a = dot * 0.125f;        // 1/sqrt(64)

        const float mn = fmaxf(m, a);
        const float sc = __expf(m - mn);
        const float w  = __expf(a - mn);
        d = d * sc + w;
        a0.x = a0.x * sc + (v0.x + e0.x) * w;
        a0.y = a0.y * sc + (v0.y + e0.y) * w;
        a0.z = a0.z * sc + (v0.z + e0.z) * w;
        a0.w = a0.w * sc + (v0.w + e0.w) * w;
        a1.x = a1.x * sc + (v1.x + e1.x) * w;
        a1.y = a1.y * sc + (v1.y + e1.y) * w;
        a1.z = a1.z * sc + (v1.z + e1.z) * w;
        a1.w = a1.w * sc + (v1.w + e1.w) * w;
        m = mn;
    }

    const float inv = 1.f / (d + 1e-16f);
    float* op = out + (size_t)warp * DD + lane * 8;
    float4 o0 = *(float4*)op, o1 = *(float4*)(op + 4);
    o0.x += a0.x * inv; o0.y += a0.y * inv;
    o0.z += a0.z * inv; o0.w += a0.w * inv;
    o1.x += a1.x * inv; o1.y += a1.y * inv;
    o1.z += a1.z * inv; o1.w += a1.w * inv;
    *(float4*)op       = o0;
    *(float4*)(op + 4) = o1;
}

// ================= host driver =================
static void* symaddr(const void* sym)
{
    void* p = nullptr;
    cudaGetSymbolAddress(&p, sym);
    return p;
}

extern "C" void kernel_launch(void* const* d_in, const int* in_sizes, int n_in,
                              void* d_out, int out_size)
{
    const float* x  = (const float*)d_in[0];
    const int*   ei = (const int*)d_in[1];
    const float* ea = (const float*)d_in[2];
    const float* W1[5] = { (const float*)d_in[3],  (const float*)d_in[5],
                           (const float*)d_in[7],  (const float*)d_in[9],
                           (const float*)d_in[11] };               // Wq Wk Wv We Ws
    const float* b1[5] = { (const float*)d_in[4],  (const float*)d_in[6],
                           (const float*)d_in[8],  (const float*)d_in[10],
                           (const float*)d_in[12] };
    const float* W2[5] = { (const float*)d_in[13], (const float*)d_in[15],
                           (const float*)d_in[17], (const float*)d_in[19],
                           (const float*)d_in[21] };
    const float* b2[5] = { (const float*)d_in[14], (const float*)d_in[16],
                           (const float*)d_in[18], (const float*)d_in[20],
                           (const float*)d_in[22] };

    static float *q = nullptr, *k, *v, *h, *e;
    static bf16 *xhi, *xlo, *ehi, *elo, *whi, *wlo;
    if (!q) {
        q = (float*)symaddr(g_q); k = (float*)symaddr(g_k);
        v = (float*)symaddr(g_v); h = (float*)symaddr(g_h);
        e = (float*)symaddr(g_e);
        xhi = (bf16*)symaddr(g_xhi); xlo = (bf16*)symaddr(g_xlo);
        ehi = (bf16*)symaddr(g_ehi); elo = (bf16*)symaddr(g_elo);
        whi = (bf16*)symaddr(g_whi); wlo = (bf16*)symaddr(g_wlo);
        cudaFuncSetAttribute(gemm_bf3,
            cudaFuncAttributeMaxDynamicSharedMemorySize, GEMM_SMEM);
    }
    float* out = (float*)d_out;

    // ---- weight transpose + split: QKVS fused rows = Wq,Wk,Wv,Ws ----
    const float* qkvs1[4] = { W1[0], W1[1], W1[2], W1[4] };
    const float* qkvs2[4] = { W2[0], W2[1], W2[2], W2[4] };
    for (int s = 0; s < 4; s++) {
        tsplit_w<<<256, 256>>>(qkvs1[s], whi + WOFF_QKVS1 + (size_t)s * 65536,
                                         wlo + WOFF_QKVS1 + (size_t)s * 65536, 256);
        tsplit_w<<<256, 256>>>(qkvs2[s], whi + WOFF_QKVS2 + (size_t)s * 65536,
                                         wlo + WOFF_QKVS2 + (size_t)s * 65536, 256);
    }
    tsplit_w<<<128, 256>>>(W1[3], whi + WOFF_E1, wlo + WOFF_E1, 128);
    tsplit_w<<<128, 256>>>(W2[3], whi + WOFF_E2, wlo + WOFF_E2, 128);

    // ---- activation splits + CSR build ----
    split_bf<<<(Nn * DD / 4 + 255) / 256, 256>>>(x, xhi, xlo, (size_t)Nn * DD / 4);
    split_bf<<<((size_t)Ee * EDD / 4 + 255) / 256, 256>>>(ea, ehi, elo,
                                                          (size_t)Ee * EDD / 4);
    const int NB = (Nn + 255) / 256;       // 196 scan blocks
    csr_zero<<<NB, 256>>>();
    csr_count<<<(Ee + 255) / 256, 256>>>(ei);
    csr_scan_local<<<NB, 256>>>();
    csr_scan_bsum<<<1, 256>>>(NB);
    csr_finalize<<<NB, 256>>>();
    csr_fill<<<(Ee + 255) / 256, 256>>>(ei);

    const dim3 gQKVS(8, (Nn + 127) / 128);
    const dim3 gEdge(2, Ee / 128);
    const int  bFlash = (Nn * 32 + 255) / 256;
    const int  bSplit = (Nn * DD / 4 + 255) / 256;

    // ---------- layer 1 ----------
    gemm_bf3<<<gQKVS, 256, GEMM_SMEM>>>(Nn, 256, xhi, xlo,
        whi + WOFF_QKVS1, wlo + WOFF_QKVS1,
        q, k, v, h, b1[0], b1[1], b1[2], b1[4]);        // skip -> h
    gemm_bf3<<<gEdge, 256, GEMM_SMEM>>>(Ee, 128, ehi, elo,
        whi + WOFF_E1, wlo + WOFF_E1,
        e, e, e, e, b1[3], b1[3], b1[3], b1[3]);

    flash_agg<<<bFlash, 256>>>(ei, q, k, v, e, h);
    relu_split<<<bSplit, 256>>>(h, xhi, xlo, (size_t)Nn * DD / 4);

    // ---------- layer 2 ----------
    gemm_bf3<<<gQKVS, 256, GEMM_SMEM>>>(Nn, 256, xhi, xlo,
        whi + WOFF_QKVS2, wlo + WOFF_QKVS2,
        q, k, v, out, b2[0], b2[1], b2[2], b2[4]);      // skip -> out
    gemm_bf3<<<gEdge, 256, GEMM_SMEM>>>(Ee, 128, ehi, elo,
        whi + WOFF_E2, wlo + WOFF_E2,
        e, e, e, e, b2[3], b2[3], b2[3], b2[3]);

    flash_agg<<<bFlash, 256>>>(ei, q, k, v, e, out);
}

// round 6
// speedup vs baseline: 2.3793x; 1.0064x over previous
#include <cuda_runtime.h>
#include <cuda_bf16.h>
#include <math.h>
#include <math_constants.h>
#include <cstdint>

#define Nn   50000
#define Ee   800000
#define DD   256
#define EDD  128
#define Hh   4

typedef __nv_bfloat16 bf16;

// ================= scratch (device globals) =================
__device__ float g_q[Nn * DD];
__device__ float g_k[Nn * DD];
__device__ float g_v[Nn * DD];
__device__ float g_h[Nn * DD];
__device__ float g_e1[(size_t)Ee * DD];   // layer-1 edge projections
__device__ float g_e2[(size_t)Ee * DD];   // layer-2 edge projections
// CSR for dst-grouped edges
__device__ int g_deg[Nn];
__device__ int g_cursor[Nn];
__device__ int g_loc[Nn];
__device__ int g_bsum[256];
__device__ int g_rowptr[Nn + 1];
__device__ int g_adj[Ee];
// pre-split bf16 operands
__device__ bf16 g_xhi[Nn * DD], g_xlo[Nn * DD];
__device__ bf16 g_ehi[(size_t)Ee * EDD], g_elo[(size_t)Ee * EDD];
#define WOFF_QKVS1 0
#define WOFF_E1    262144
#define WOFF_QKVS2 294912
#define WOFF_E2    557056
__device__ bf16 g_whi[589824], g_wlo[589824];

// ================= PTX helpers =================
__device__ __forceinline__ uint32_t smem_u32(const void* p) {
    uint32_t a;
    asm("{ .reg .u64 t; cvta.to.shared.u64 t, %1; cvt.u32.u64 %0, t; }"
        : "=r"(a) : "l"(p));
    return a;
}
__device__ __forceinline__ void ldsm_x4(uint32_t* r, uint32_t a) {
    asm volatile("ldmatrix.sync.aligned.m8n8.x4.shared.b16 {%0,%1,%2,%3}, [%4];"
        : "=r"(r[0]), "=r"(r[1]), "=r"(r[2]), "=r"(r[3]) : "r"(a));
}
__device__ __forceinline__ void ldsm_x2(uint32_t* r, uint32_t a) {
    asm volatile("ldmatrix.sync.aligned.m8n8.x2.shared.b16 {%0,%1}, [%2];"
        : "=r"(r[0]), "=r"(r[1]) : "r"(a));
}
__device__ __forceinline__ void mma_bf16(float* d, const uint32_t* a, const uint32_t* b) {
    asm volatile("mma.sync.aligned.m16n8k16.row.col.f32.bf16.bf16.f32 "
        "{%0,%1,%2,%3}, {%4,%5,%6,%7}, {%8,%9}, {%0,%1,%2,%3};"
        : "+f"(d[0]), "+f"(d[1]), "+f"(d[2]), "+f"(d[3])
        : "r"(a[0]), "r"(a[1]), "r"(a[2]), "r"(a[3]), "r"(b[0]), "r"(b[1]));
}
__device__ __forceinline__ void cpa16(uint32_t dst, const void* src, int sz) {
    asm volatile("cp.async.cg.shared.global [%0], [%1], 16, %2;"
        :: "r"(dst), "l"(src), "r"(sz) : "memory");
}
#define CP_COMMIT() asm volatile("cp.async.commit_group;" ::: "memory")
#define CP_WAIT1()  asm volatile("cp.async.wait_group 1;" ::: "memory")
#define CP_WAIT0()  asm volatile("cp.async.wait_group 0;" ::: "memory")

// ================= bf16x3 pipelined GEMM =============
#define PAD 40
#define STG_B 40960
#define OFF_AL 10240
#define OFF_BH 20480
#define OFF_BL 30720
#define GEMM_SMEM (2 * STG_B)

__global__ __launch_bounds__(256) void gemm_bf3(
    int M, int K,
    const bf16* __restrict__ Ahi, const bf16* __restrict__ Alo,
    const bf16* __restrict__ Whi, const bf16* __restrict__ Wlo,
    float* c0, float* c1, float* c2, float* c3,
    const float* b0, const float* b1, const float* b2, const float* b3)
{
    extern __shared__ char sm[];
    const uint32_t sb = smem_u32(sm);

    const int tid  = threadIdx.x;
    const int lane = tid & 31;
    const int wid  = tid >> 5;
    const int wm   = wid >> 2;
    const int wn   = wid & 3;
    const int row0 = blockIdx.y * 128;
    const int nW0  = blockIdx.x * 128;

    float* const outs[4]         = { c0, c1, c2, c3 };
    const float* const biases[4] = { b0, b1, b2, b3 };
    float*       Cout = outs[blockIdx.x >> 1];
    const float* bias = biases[blockIdx.x >> 1];
    const int    colb = (blockIdx.x & 1) * 128;

    const int lr  = tid >> 1;
    const int lcb = (tid & 1) * 16;
    const int grA  = row0 + lr;
    const int okA  = (grA < M) ? 16 : 0;
    const size_t aoff = (size_t)(okA ? grA : 0) * K + lcb;
    const size_t boff = (size_t)(nW0 + lr) * K + lcb;
    const char* pAh = (const char*)(Ahi + aoff);
    const char* pAl = (const char*)(Alo + aoff);
    const char* pBh = (const char*)(Whi + boff);
    const char* pBl = (const char*)(Wlo + boff);
    const uint32_t dstA = sb + (uint32_t)(lr * 80 + (tid & 1) * 32);

    const int nchunk = K >> 5;

    const int aRow    = lane & 15;
    const int aColSel = (lane >> 4) * 8;
    const int bRow    = lane & 7;
    const int bColSel = ((lane >> 3) & 1) * 8;

    float acc[4][4][4];
    #pragma unroll
    for (int i = 0; i < 4; i++)
        #pragma unroll
        for (int j = 0; j < 4; j++)
            #pragma unroll
            for (int t = 0; t < 4; t++) acc[i][j][t] = 0.f;

    {
        cpa16(dstA,               pAh,      okA);
        cpa16(dstA + 16,          pAh + 16, okA);
        cpa16(dstA + OFF_AL,      pAl,      okA);
        cpa16(dstA + OFF_AL + 16, pAl + 16, okA);
        cpa16(dstA + OFF_BH,      pBh,      16);
        cpa16(dstA + OFF_BH + 16, pBh + 16, 16);
        cpa16(dstA + OFF_BL,      pBl,      16);
        cpa16(dstA + OFF_BL + 16, pBl + 16, 16);
        CP_COMMIT();
    }

    for (int c = 0; c < nchunk; c++) {
        if (c + 1 < nchunk) {
            const uint32_t d = dstA + ((c + 1) & 1) * STG_B;
            const int go = (c + 1) * 64;
            cpa16(d,               pAh + go,      okA);
            cpa16(d + 16,          pAh + go + 16, okA);
            cpa16(d + OFF_AL,      pAl + go,      okA);
            cpa16(d + OFF_AL + 16, pAl + go + 16, okA);
            cpa16(d + OFF_BH,      pBh + go,      16);
            cpa16(d + OFF_BH + 16, pBh + go + 16, 16);
            cpa16(d + OFF_BL,      pBl + go,      16);
            cpa16(d + OFF_BL + 16, pBl + go + 16, 16);
            CP_COMMIT();
            CP_WAIT1();
        } else {
            CP_WAIT0();
        }
        __syncthreads();

        const uint32_t sbase = sb + (c & 1) * STG_B;
        #pragma unroll
        for (int ks = 0; ks < 2; ks++) {
            const int kb = ks * 16;
            uint32_t ah[4][4], al[4][4], bh[4][2], bl[4][2];
            #pragma unroll
            for (int mt = 0; mt < 4; mt++) {
                const uint32_t off = sbase +
                    (uint32_t)((wm * 64 + mt * 16 + aRow) * PAD + kb + aColSel) * 2;
                ldsm_x4(ah[mt], off);
                ldsm_x4(al[mt], off + OFF_AL);
            }
            #pragma unroll
            for (int nt = 0; nt < 4; nt++) {
                const uint32_t off = sbase + OFF_BH +
                    (uint32_t)((wn * 32 + nt * 8 + bRow) * PAD + kb + bColSel) * 2;
                ldsm_x2(bh[nt], off);
                ldsm_x2(bl[nt], off + (OFF_BL - OFF_BH));
            }
            #pragma unroll
            for (int mt = 0; mt < 4; mt++)
                #pragma unroll
                for (int nt = 0; nt < 4; nt++) {
                    mma_bf16(acc[mt][nt], ah[mt], bh[nt]);
                    mma_bf16(acc[mt][nt], ah[mt], bl[nt]);
                    mma_bf16(acc[mt][nt], al[mt], bh[nt]);
                }
        }
        __syncthreads();
    }

    #pragma unroll
    for (int mt = 0; mt < 4; mt++) {
        const int r = row0 + wm * 64 + mt * 16 + (lane >> 2);
        #pragma unroll
        for (int nt = 0; nt < 4; nt++) {
            const int c = colb + wn * 32 + nt * 8 + (lane & 3) * 2;
            if (r < M) {
                float2 o = make_float2(acc[mt][nt][0] + bias[c],
                                       acc[mt][nt][1] + bias[c + 1]);
                *(float2*)(Cout + (size_t)r * 256 + c) = o;
            }
            if (r + 8 < M) {
                float2 o = make_float2(acc[mt][nt][2] + bias[c],
                                       acc[mt][nt][3] + bias[c + 1]);
                *(float2*)(Cout + (size_t)(r + 8) * 256 + c) = o;
            }
        }
    }
}

// ======== weight transpose + split ========
__global__ void tsplit_w(const float* __restrict__ W,
                         bf16* __restrict__ hi, bf16* __restrict__ lo, int K)
{
    const int i = blockIdx.x * blockDim.x + threadIdx.x;
    if (i < K * 256) {
        const int k = i >> 8, n = i & 255;
        const float v = W[i];
        const bf16 h = __float2bfloat16(v);
        hi[(size_t)n * K + k] = h;
        lo[(size_t)n * K + k] = __float2bfloat16(v - __bfloat162float(h));
    }
}

__global__ void split_bf(const float* __restrict__ in,
                         bf16* __restrict__ hi, bf16* __restrict__ lo, size_t n4)
{
    const size_t i = (size_t)blockIdx.x * blockDim.x + threadIdx.x;
    if (i >= n4) return;
    float4 v = ((const float4*)in)[i];
    __nv_bfloat162 h0 = __floats2bfloat162_rn(v.x, v.y);
    __nv_bfloat162 h1 = __floats2bfloat162_rn(v.z, v.w);
    __nv_bfloat162 l0 = __floats2bfloat162_rn(v.x - __low2float(h0), v.y - __high2float(h0));
    __nv_bfloat162 l1 = __floats2bfloat162_rn(v.z - __low2float(h1), v.w - __high2float(h1));
    ((__nv_bfloat162*)hi)[2 * i]     = h0;
    ((__nv_bfloat162*)hi)[2 * i + 1] = h1;
    ((__nv_bfloat162*)lo)[2 * i]     = l0;
    ((__nv_bfloat162*)lo)[2 * i + 1] = l1;
}

__global__ void relu_split(const float* __restrict__ in,
                           bf16* __restrict__ hi, bf16* __restrict__ lo, size_t n4)
{
    const size_t i = (size_t)blockIdx.x * blockDim.x + threadIdx.x;
    if (i >= n4) return;
    float4 v = ((const float4*)in)[i];
    v.x = fmaxf(v.x, 0.f); v.y = fmaxf(v.y, 0.f);
    v.z = fmaxf(v.z, 0.f); v.w = fmaxf(v.w, 0.f);
    __nv_bfloat162 h0 = __floats2bfloat162_rn(v.x, v.y);
    __nv_bfloat162 h1 = __floats2bfloat162_rn(v.z, v.w);
    __nv_bfloat162 l0 = __floats2bfloat162_rn(v.x - __low2float(h0), v.y - __high2float(h0));
    __nv_bfloat162 l1 = __floats2bfloat162_rn(v.z - __low2float(h1), v.w - __high2float(h1));
    ((__nv_bfloat162*)hi)[2 * i]     = h0;
    ((__nv_bfloat162*)hi)[2 * i + 1] = h1;
    ((__nv_bfloat162*)lo)[2 * i]     = l0;
    ((__nv_bfloat162*)lo)[2 * i + 1] = l1;
}

// ================= CSR build =================
__global__ void csr_zero()
{
    const int i = blockIdx.x * blockDim.x + threadIdx.x;
    if (i < Nn) { g_deg[i] = 0; g_cursor[i] = 0; }
}
__global__ void csr_count(const int* __restrict__ ei)
{
    const int i = blockIdx.x * blockDim.x + threadIdx.x;
    if (i < Ee) atomicAdd(&g_deg[ei[Ee + i]], 1);
}
__global__ void csr_scan_local()
{
    __shared__ int s[256];
    const int tid = threadIdx.x;
    const int i = blockIdx.x * 256 + tid;
    const int v = (i < Nn) ? g_deg[i] : 0;
    s[tid] = v; __syncthreads();
    for (int off = 1; off < 256; off <<= 1) {
        const int t = (tid >= off) ? s[tid - off] : 0;
        __syncthreads();
        s[tid] += t;
        __syncthreads();
    }
    if (i < Nn) g_loc[i] = s[tid] - v;
    if (tid == 255) g_bsum[blockIdx.x] = s[255];
}
__global__ void csr_scan_bsum(int nb)
{
    __shared__ int s[256];
    const int t = threadIdx.x;
    const int v = (t < nb) ? g_bsum[t] : 0;
    s[t] = v; __syncthreads();
    for (int off = 1; off < 256; off <<= 1) {
        const int u = (t >= off) ? s[t - off] : 0;
        __syncthreads();
        s[t] += u;
        __syncthreads();
    }
    if (t < nb) g_bsum[t] = s[t] - v;
}
__global__ void csr_finalize()
{
    const int i = blockIdx.x * blockDim.x + threadIdx.x;
    if (i < Nn) g_rowptr[i] = g_loc[i] + g_bsum[i >> 8];
    if (i == 0) g_rowptr[Nn] = Ee;
}
__global__ void csr_fill(const int* __restrict__ ei)
{
    const int eid = blockIdx.x * blockDim.x + threadIdx.x;
    if (eid < Ee) {
        const int dst = ei[Ee + eid];
        const int p = atomicAdd(&g_cursor[dst], 1);
        g_adj[g_rowptr[dst] + p] = eid;
    }
}

// ================= flash-style segment softmax + aggregate =================
__global__ __launch_bounds__(256) void flash_agg(
    const int* __restrict__ ei,
    const float* __restrict__ q, const float* __restrict__ k,
    const float* __restrict__ v, const float* __restrict__ e,
    float* __restrict__ out)
{
    const int warp = (blockIdx.x * blockDim.x + threadIdx.x) >> 5;
    const int lane = threadIdx.x & 31;
    if (warp >= Nn) return;
    const int beg = g_rowptr[warp];
    const int end = g_rowptr[warp + 1];
    if (beg == end) return;

    const int li = lane * 2;
    const float4* qp = (const float4*)(q + (size_t)warp * DD);
    const float4 q0 = qp[li], q1 = qp[li + 1];

    float m = -CUDART_INF_F, d = 0.f;
    float4 a0 = make_float4(0.f, 0.f, 0.f, 0.f);
    float4 a1 = make_float4(0.f, 0.f, 0.f, 0.f);

    for (int idx = beg; idx < end; idx++) {
        const int eid = g_adj[idx];
        const int src = ei[eid];
        const float4* ep = (const float4*)(e + (size_t)eid * DD);
        const float4* kp = (const float4*)(k + (size_t)src * DD);
        const float4* vp = (const float4*)(v + (size_t)src * DD);
        const float4 e0 = ep[li], e1 = ep[li + 1];
        const float4 k0 = kp[li], k1 = kp[li + 1];
        const float4 v0 = vp[li], v1 = vp[li + 1];

        float dot = q0.x * (k0.x + e0.x) + q0.y * (k0.y + e0.y)
                  + q0.z * (k0.z + e0.z) + q0.w * (k0.w + e0.w)
                  + q1.x * (k1.x + e1.x) + q1.y * (k1.y + e1.y)
                  + q1.z * (k1.z + e1.z) + q1.w * (k1.w + e1.w);
        dot += __shfl_xor_sync(0xffffffffu, dot, 1);
        dot += __shfl_xor_sync(0xffffffffu, dot, 2);
        dot += __shfl_xor_sync(0xffffffffu, dot, 4);
        const float a = dot * 0.125f;

        const float mn = fmaxf(m, a);
        const float sc = __expf(m - mn);
        const float w  = __expf(a - mn);
        d = d * sc + w;
        a0.x = a0.x * sc + (v0.x + e0.x) * w;
        a0.y = a0.y * sc + (v0.y + e0.y) * w;
        a0.z = a0.z * sc + (v0.z + e0.z) * w;
        a0.w = a0.w * sc + (v0.w + e0.w) * w;
        a1.x = a1.x * sc + (v1.x + e1.x) * w;
        a1.y = a1.y * sc + (v1.y + e1.y) * w;
        a1.z = a1.z * sc + (v1.z + e1.z) * w;
        a1.w = a1.w * sc + (v1.w + e1.w) * w;
        m = mn;
    }

    const float inv = 1.f / (d + 1e-16f);
    float* op = out + (size_t)warp * DD + lane * 8;
    float4 o0 = *(float4*)op, o1 = *(float4*)(op + 4);
    o0.x += a0.x * inv; o0.y += a0.y * inv;
    o0.z += a0.z * inv; o0.w += a0.w * inv;
    o1.x += a1.x * inv; o1.y += a1.y * inv;
    o1.z += a1.z * inv; o1.w += a1.w * inv;
    *(float4*)op       = o0;
    *(float4*)(op + 4) = o1;
}

// ================= host driver =================
static void* symaddr(const void* sym)
{
    void* p = nullptr;
    cudaGetSymbolAddress(&p, sym);
    return p;
}

extern "C" void kernel_launch(void* const* d_in, const int* in_sizes, int n_in,
                              void* d_out, int out_size)
{
    const float* x  = (const float*)d_in[0];
    const int*   ei = (const int*)d_in[1];
    const float* ea = (const float*)d_in[2];
    const float* W1[5] = { (const float*)d_in[3],  (const float*)d_in[5],
                           (const float*)d_in[7],  (const float*)d_in[9],
                           (const float*)d_in[11] };               // Wq Wk Wv We Ws
    const float* b1[5] = { (const float*)d_in[4],  (const float*)d_in[6],
                           (const float*)d_in[8],  (const float*)d_in[10],
                           (const float*)d_in[12] };
    const float* W2[5] = { (const float*)d_in[13], (const float*)d_in[15],
                           (const float*)d_in[17], (const float*)d_in[19],
                           (const float*)d_in[21] };
    const float* b2[5] = { (const float*)d_in[14], (const float*)d_in[16],
                           (const float*)d_in[18], (const float*)d_in[20],
                           (const float*)d_in[22] };

    static float *q = nullptr, *k, *v, *h, *e1, *e2;
    static bf16 *xhi, *xlo, *ehi, *elo, *whi, *wlo;
    static cudaStream_t sB;
    static cudaEvent_t evRoot, evE1, evE2;
    if (!q) {
        q  = (float*)symaddr(g_q);  k  = (float*)symaddr(g_k);
        v  = (float*)symaddr(g_v);  h  = (float*)symaddr(g_h);
        e1 = (float*)symaddr(g_e1); e2 = (float*)symaddr(g_e2);
        xhi = (bf16*)symaddr(g_xhi); xlo = (bf16*)symaddr(g_xlo);
        ehi = (bf16*)symaddr(g_ehi); elo = (bf16*)symaddr(g_elo);
        whi = (bf16*)symaddr(g_whi); wlo = (bf16*)symaddr(g_wlo);
        cudaFuncSetAttribute(gemm_bf3,
            cudaFuncAttributeMaxDynamicSharedMemorySize, GEMM_SMEM);
        cudaStreamCreateWithFlags(&sB, cudaStreamNonBlocking);
        cudaEventCreateWithFlags(&evRoot, cudaEventDisableTiming);
        cudaEventCreateWithFlags(&evE1,  cudaEventDisableTiming);
        cudaEventCreateWithFlags(&evE2,  cudaEventDisableTiming);
    }
    float* out = (float*)d_out;

    const dim3 gQKVS(8, (Nn + 127) / 128);
    const dim3 gEdge(2, Ee / 128);
    const int  bFlash = (Nn * 32 + 255) / 256;
    const int  bSplit = (Nn * DD / 4 + 255) / 256;
    const int  NB = (Nn + 255) / 256;

    // ================= fork: edge pipeline on sB =================
    cudaEventRecord(evRoot, 0);
    cudaStreamWaitEvent(sB, evRoot, 0);

    tsplit_w<<<128, 256, 0, sB>>>(W1[3], whi + WOFF_E1, wlo + WOFF_E1, 128);
    tsplit_w<<<128, 256, 0, sB>>>(W2[3], whi + WOFF_E2, wlo + WOFF_E2, 128);
    split_bf<<<(int)(((size_t)Ee * EDD / 4 + 255) / 256), 256, 0, sB>>>(
        ea, ehi, elo, (size_t)Ee * EDD / 4);
    gemm_bf3<<<gEdge, 256, GEMM_SMEM, sB>>>(Ee, 128, ehi, elo,
        whi + WOFF_E1, wlo + WOFF_E1,
        e1, e1, e1, e1, b1[3], b1[3], b1[3], b1[3]);
    cudaEventRecord(evE1, sB);
    gemm_bf3<<<gEdge, 256, GEMM_SMEM, sB>>>(Ee, 128, ehi, elo,
        whi + WOFF_E2, wlo + WOFF_E2,
        e2, e2, e2, e2, b2[3], b2[3], b2[3], b2[3]);
    cudaEventRecord(evE2, sB);

    // ================= main stream: node pipeline =================
    const float* qkvs1[4] = { W1[0], W1[1], W1[2], W1[4] };
    const float* qkvs2[4] = { W2[0], W2[1], W2[2], W2[4] };
    for (int s = 0; s < 4; s++) {
        tsplit_w<<<256, 256>>>(qkvs1[s], whi + WOFF_QKVS1 + (size_t)s * 65536,
                                         wlo + WOFF_QKVS1 + (size_t)s * 65536, 256);
        tsplit_w<<<256, 256>>>(qkvs2[s], whi + WOFF_QKVS2 + (size_t)s * 65536,
                                         wlo + WOFF_QKVS2 + (size_t)s * 65536, 256);
    }
    split_bf<<<bSplit, 256>>>(x, xhi, xlo, (size_t)Nn * DD / 4);

    csr_zero<<<NB, 256>>>();
    csr_count<<<(Ee + 255) / 256, 256>>>(ei);
    csr_scan_local<<<NB, 256>>>();
    csr_scan_bsum<<<1, 256>>>(NB);
    csr_finalize<<<NB, 256>>>();
    csr_fill<<<(Ee + 255) / 256, 256>>>(ei);

    // layer 1 node QKVS (skip -> h)
    gemm_bf3<<<gQKVS, 256, GEMM_SMEM>>>(Nn, 256, xhi, xlo,
        whi + WOFF_QKVS1, wlo + WOFF_QKVS1,
        q, k, v, h, b1[0], b1[1], b1[2], b1[4]);

    cudaStreamWaitEvent(0, evE1, 0);
    flash_agg<<<bFlash, 256>>>(ei, q, k, v, e1, h);
    relu_split<<<bSplit, 256>>>(h, xhi, xlo, (size_t)Nn * DD / 4);

    // layer 2 node QKVS (skip -> out)
    gemm_bf3<<<gQKVS, 256, GEMM_SMEM>>>(Nn, 256, xhi, xlo,
        whi + WOFF_QKVS2, wlo + WOFF_QKVS2,
        q, k, v, out, b2[0], b2[1], b2[2], b2[4]);

    cudaStreamWaitEvent(0, evE2, 0);
    flash_agg<<<bFlash, 256>>>(ei, q, k, v, e2, out);
}

// round 7
// speedup vs baseline: 2.8564x; 1.2005x over previous
#include <cuda_runtime.h>
#include <cuda_bf16.h>
#include <math.h>
#include <math_constants.h>
#include <cstdint>

#define Nn   50000
#define Ee   800000
#define DD   256
#define EDD  128
#define Hh   4

typedef __nv_bfloat16 bf16;

// ================= scratch (device globals) =================
__device__ float g_q[Nn * DD];
__device__ float g_k[Nn * DD];
__device__ float g_v[Nn * DD];
__device__ float g_h[Nn * DD];
__device__ float g_e1[(size_t)Ee * DD];   // layer-1 edge projections (dst-sorted)
__device__ float g_e2[(size_t)Ee * DD];   // layer-2 edge projections (dst-sorted)
// CSR for dst-grouped edges
__device__ int g_deg[Nn];
__device__ int g_cursor[Nn];
__device__ int g_loc[Nn];
__device__ int g_bsum[256];
__device__ int g_rowptr[Nn + 1];
__device__ int g_adj[Ee];                 // sorted pos -> original edge id
__device__ int g_srcp[Ee];                // sorted pos -> src node
// pre-split bf16 operands
__device__ bf16 g_xhi[Nn * DD], g_xlo[Nn * DD];
__device__ bf16 g_ehi[(size_t)Ee * EDD], g_elo[(size_t)Ee * EDD];
#define WOFF_QKVS1 0
#define WOFF_E1    262144
#define WOFF_QKVS2 294912
#define WOFF_E2    557056
__device__ bf16 g_whi[589824], g_wlo[589824];

// ================= PTX helpers =================
__device__ __forceinline__ uint32_t smem_u32(const void* p) {
    uint32_t a;
    asm("{ .reg .u64 t; cvta.to.shared.u64 t, %1; cvt.u32.u64 %0, t; }"
        : "=r"(a) : "l"(p));
    return a;
}
__device__ __forceinline__ void ldsm_x4(uint32_t* r, uint32_t a) {
    asm volatile("ldmatrix.sync.aligned.m8n8.x4.shared.b16 {%0,%1,%2,%3}, [%4];"
        : "=r"(r[0]), "=r"(r[1]), "=r"(r[2]), "=r"(r[3]) : "r"(a));
}
__device__ __forceinline__ void ldsm_x2(uint32_t* r, uint32_t a) {
    asm volatile("ldmatrix.sync.aligned.m8n8.x2.shared.b16 {%0,%1}, [%2];"
        : "=r"(r[0]), "=r"(r[1]) : "r"(a));
}
__device__ __forceinline__ void mma_bf16(float* d, const uint32_t* a, const uint32_t* b) {
    asm volatile("mma.sync.aligned.m16n8k16.row.col.f32.bf16.bf16.f32 "
        "{%0,%1,%2,%3}, {%4,%5,%6,%7}, {%8,%9}, {%0,%1,%2,%3};"
        : "+f"(d[0]), "+f"(d[1]), "+f"(d[2]), "+f"(d[3])
        : "r"(a[0]), "r"(a[1]), "r"(a[2]), "r"(a[3]), "r"(b[0]), "r"(b[1]));
}
__device__ __forceinline__ void cpa16(uint32_t dst, const void* src, int sz) {
    asm volatile("cp.async.cg.shared.global [%0], [%1], 16, %2;"
        :: "r"(dst), "l"(src), "r"(sz) : "memory");
}
#define CP_COMMIT() asm volatile("cp.async.commit_group;" ::: "memory")
#define CP_WAIT1()  asm volatile("cp.async.wait_group 1;" ::: "memory")
#define CP_WAIT0()  asm volatile("cp.async.wait_group 0;" ::: "memory")

// ================= bf16x3 pipelined GEMM =============
// rowmap != nullptr -> A rows gathered through rowmap (edge permutation)
#define PAD 40
#define STG_B 40960
#define OFF_AL 10240
#define OFF_BH 20480
#define OFF_BL 30720
#define GEMM_SMEM (2 * STG_B)

__global__ __launch_bounds__(256, 2) void gemm_bf3(
    int M, int K,
    const bf16* __restrict__ Ahi, const bf16* __restrict__ Alo,
    const bf16* __restrict__ Whi, const bf16* __restrict__ Wlo,
    const int* __restrict__ rowmap,
    float* c0, float* c1, float* c2, float* c3,
    const float* b0, const float* b1, const float* b2, const float* b3)
{
    extern __shared__ char sm[];
    const uint32_t sb = smem_u32(sm);

    const int tid  = threadIdx.x;
    const int lane = tid & 31;
    const int wid  = tid >> 5;
    const int wm   = wid >> 2;
    const int wn   = wid & 3;
    const int row0 = blockIdx.y * 128;
    const int nW0  = blockIdx.x * 128;

    float* const outs[4]         = { c0, c1, c2, c3 };
    const float* const biases[4] = { b0, b1, b2, b3 };
    float*       Cout = outs[blockIdx.x >> 1];
    const float* bias = biases[blockIdx.x >> 1];
    const int    colb = (blockIdx.x & 1) * 128;

    const int lr  = tid >> 1;
    const int lcb = (tid & 1) * 16;
    const int grA  = row0 + lr;
    const int okA  = (grA < M) ? 16 : 0;
    int arow = okA ? grA : 0;
    if (rowmap) arow = rowmap[arow];
    const size_t aoff = (size_t)arow * K + lcb;
    const size_t boff = (size_t)(nW0 + lr) * K + lcb;
    const char* pAh = (const char*)(Ahi + aoff);
    const char* pAl = (const char*)(Alo + aoff);
    const char* pBh = (const char*)(Whi + boff);
    const char* pBl = (const char*)(Wlo + boff);
    const uint32_t dstA = sb + (uint32_t)(lr * 80 + (tid & 1) * 32);

    const int nchunk = K >> 5;

    const int aRow    = lane & 15;
    const int aColSel = (lane >> 4) * 8;
    const int bRow    = lane & 7;
    const int bColSel = ((lane >> 3) & 1) * 8;

    float acc[4][4][4];
    #pragma unroll
    for (int i = 0; i < 4; i++)
        #pragma unroll
        for (int j = 0; j < 4; j++)
            #pragma unroll
            for (int t = 0; t < 4; t++) acc[i][j][t] = 0.f;

    {
        cpa16(dstA,               pAh,      okA);
        cpa16(dstA + 16,          pAh + 16, okA);
        cpa16(dstA + OFF_AL,      pAl,      okA);
        cpa16(dstA + OFF_AL + 16, pAl + 16, okA);
        cpa16(dstA + OFF_BH,      pBh,      16);
        cpa16(dstA + OFF_BH + 16, pBh + 16, 16);
        cpa16(dstA + OFF_BL,      pBl,      16);
        cpa16(dstA + OFF_BL + 16, pBl + 16, 16);
        CP_COMMIT();
    }

    for (int c = 0; c < nchunk; c++) {
        if (c + 1 < nchunk) {
            const uint32_t d = dstA + ((c + 1) & 1) * STG_B;
            const int go = (c + 1) * 64;
            cpa16(d,               pAh + go,      okA);
            cpa16(d + 16,          pAh + go + 16, okA);
            cpa16(d + OFF_AL,      pAl + go,      okA);
            cpa16(d + OFF_AL + 16, pAl + go + 16, okA);
            cpa16(d + OFF_BH,      pBh + go,      16);
            cpa16(d + OFF_BH + 16, pBh + go + 16, 16);
            cpa16(d + OFF_BL,      pBl + go,      16);
            cpa16(d + OFF_BL + 16, pBl + go + 16, 16);
            CP_COMMIT();
            CP_WAIT1();
        } else {
            CP_WAIT0();
        }
        __syncthreads();

        const uint32_t sbase = sb + (c & 1) * STG_B;
        #pragma unroll
        for (int ks = 0; ks < 2; ks++) {
            const int kb = ks * 16;
            uint32_t ah[4][4], al[4][4], bh[4][2], bl[4][2];
            #pragma unroll
            for (int mt = 0; mt < 4; mt++) {
                const uint32_t off = sbase +
                    (uint32_t)((wm * 64 + mt * 16 + aRow) * PAD + kb + aColSel) * 2;
                ldsm_x4(ah[mt], off);
                ldsm_x4(al[mt], off + OFF_AL);
            }
            #pragma unroll
            for (int nt = 0; nt < 4; nt++) {
                const uint32_t off = sbase + OFF_BH +
                    (uint32_t)((wn * 32 + nt * 8 + bRow) * PAD + kb + bColSel) * 2;
                ldsm_x2(bh[nt], off);
                ldsm_x2(bl[nt], off + (OFF_BL - OFF_BH));
            }
            #pragma unroll
            for (int mt = 0; mt < 4; mt++)
                #pragma unroll
                for (int nt = 0; nt < 4; nt++) {
                    mma_bf16(acc[mt][nt], ah[mt], bh[nt]);
                    mma_bf16(acc[mt][nt], ah[mt], bl[nt]);
                    mma_bf16(acc[mt][nt], al[mt], bh[nt]);
                }
        }
        __syncthreads();
    }

    #pragma unroll
    for (int mt = 0; mt < 4; mt++) {
        const int r = row0 + wm * 64 + mt * 16 + (lane >> 2);
        #pragma unroll
        for (int nt = 0; nt < 4; nt++) {
            const int c = colb + wn * 32 + nt * 8 + (lane & 3) * 2;
            if (r < M) {
                float2 o = make_float2(acc[mt][nt][0] + bias[c],
                                       acc[mt][nt][1] + bias[c + 1]);
                *(float2*)(Cout + (size_t)r * 256 + c) = o;
            }
            if (r + 8 < M) {
                float2 o = make_float2(acc[mt][nt][2] + bias[c],
                                       acc[mt][nt][3] + bias[c + 1]);
                *(float2*)(Cout + (size_t)(r + 8) * 256 + c) = o;
            }
        }
    }
}

// ======== weight transpose + split ========
__global__ void tsplit_w(const float* __restrict__ W,
                         bf16* __restrict__ hi, bf16* __restrict__ lo, int K)
{
    const int i = blockIdx.x * blockDim.x + threadIdx.x;
    if (i < K * 256) {
        const int k = i >> 8, n = i & 255;
        const float v = W[i];
        const bf16 h = __float2bfloat16(v);
        hi[(size_t)n * K + k] = h;
        lo[(size_t)n * K + k] = __float2bfloat16(v - __bfloat162float(h));
    }
}

__global__ void split_bf(const float* __restrict__ in,
                         bf16* __restrict__ hi, bf16* __restrict__ lo, size_t n4)
{
    const size_t i = (size_t)blockIdx.x * blockDim.x + threadIdx.x;
    if (i >= n4) return;
    float4 v = ((const float4*)in)[i];
    __nv_bfloat162 h0 = __floats2bfloat162_rn(v.x, v.y);
    __nv_bfloat162 h1 = __floats2bfloat162_rn(v.z, v.w);
    __nv_bfloat162 l0 = __floats2bfloat162_rn(v.x - __low2float(h0), v.y - __high2float(h0));
    __nv_bfloat162 l1 = __floats2bfloat162_rn(v.z - __low2float(h1), v.w - __high2float(h1));
    ((__nv_bfloat162*)hi)[2 * i]     = h0;
    ((__nv_bfloat162*)hi)[2 * i + 1] = h1;
    ((__nv_bfloat162*)lo)[2 * i]     = l0;
    ((__nv_bfloat162*)lo)[2 * i + 1] = l1;
}

__global__ void relu_split(const float* __restrict__ in,
                           bf16* __restrict__ hi, bf16* __restrict__ lo, size_t n4)
{
    const size_t i = (size_t)blockIdx.x * blockDim.x + threadIdx.x;
    if (i >= n4) return;
    float4 v = ((const float4*)in)[i];
    v.x = fmaxf(v.x, 0.f); v.y = fmaxf(v.y, 0.f);
    v.z = fmaxf(v.z, 0.f); v.w = fmaxf(v.w, 0.f);
    __nv_bfloat162 h0 = __floats2bfloat162_rn(v.x, v.y);
    __nv_bfloat162 h1 = __floats2bfloat162_rn(v.z, v.w);
    __nv_bfloat162 l0 = __floats2bfloat162_rn(v.x - __low2float(h0), v.y - __high2float(h0));
    __nv_bfloat162 l1 = __floats2bfloat162_rn(v.z - __low2float(h1), v.w - __high2float(h1));
    ((__nv_bfloat162*)hi)[2 * i]     = h0;
    ((__nv_bfloat162*)hi)[2 * i + 1] = h1;
    ((__nv_bfloat162*)lo)[2 * i]     = l0;
    ((__nv_bfloat162*)lo)[2 * i + 1] = l1;
}

// ================= CSR build =================
__global__ void csr_zero()
{
    const int i = blockIdx.x * blockDim.x + threadIdx.x;
    if (i < Nn) { g_deg[i] = 0; g_cursor[i] = 0; }
}
__global__ void csr_count(const int* __restrict__ ei)
{
    const int i = blockIdx.x * blockDim.x + threadIdx.x;
    if (i < Ee) atomicAdd(&g_deg[ei[Ee + i]], 1);
}
__global__ void csr_scan_local()
{
    __shared__ int s[256];
    const int tid = threadIdx.x;
    const int i = blockIdx.x * 256 + tid;
    const int v = (i < Nn) ? g_deg[i] : 0;
    s[tid] = v; __syncthreads();
    for (int off = 1; off < 256; off <<= 1) {
        const int t = (tid >= off) ? s[tid - off] : 0;
        __syncthreads();
        s[tid] += t;
        __syncthreads();
    }
    if (i < Nn) g_loc[i] = s[tid] - v;
    if (tid == 255) g_bsum[blockIdx.x] = s[255];
}
__global__ void csr_scan_bsum(int nb)
{
    __shared__ int s[256];
    const int t = threadIdx.x;
    const int v = (t < nb) ? g_bsum[t] : 0;
    s[t] = v; __syncthreads();
    for (int off = 1; off < 256; off <<= 1) {
        const int u = (t >= off) ? s[t - off] : 0;
        __syncthreads();
        s[t] += u;
        __syncthreads();
    }
    if (t < nb) g_bsum[t] = s[t] - v;
}
__global__ void csr_finalize()
{
    const int i = blockIdx.x * blockDim.x + threadIdx.x;
    if (i < Nn) g_rowptr[i] = g_loc[i] + g_bsum[i >> 8];
    if (i == 0) g_rowptr[Nn] = Ee;
}
__global__ void csr_fill(const int* __restrict__ ei)
{
    const int eid = blockIdx.x * blockDim.x + threadIdx.x;
    if (eid < Ee) {
        const int src = ei[eid];
        const int dst = ei[Ee + eid];
        const int p = atomicAdd(&g_cursor[dst], 1);
        const int pos = g_rowptr[dst] + p;
        g_adj[pos]  = eid;
        g_srcp[pos] = src;
    }
}

// ================= flash-style segment softmax + aggregate =================
// e is dst-sorted: row idx of e corresponds to sorted position idx.
__global__ __launch_bounds__(256) void flash_agg(
    const float* __restrict__ q, const float* __restrict__ k,
    const float* __restrict__ v, const float* __restrict__ e,
    float* __restrict__ out)
{
    const int warp = (blockIdx.x * blockDim.x + threadIdx.x) >> 5;
    const int lane = threadIdx.x & 31;
    if (warp >= Nn) return;
    const int beg = g_rowptr[warp];
    const int end = g_rowptr[warp + 1];
    if (beg == end) return;

    const int li = lane * 2;
    const float4* qp = (const float4*)(q + (size_t)warp * DD);
    const float4 q0 = qp[li], q1 = qp[li + 1];

    float m = -CUDART_INF_F, d = 0.f;
    float4 a0 = make_float4(0.f, 0.f, 0.f, 0.f);
    float4 a1 = make_float4(0.f, 0.f, 0.f, 0.f);

    for (int idx = beg; idx < end; idx++) {
        const int src = g_srcp[idx];
        const float4* ep = (const float4*)(e + (size_t)idx * DD);
        const float4* kp = (const float4*)(k + (size_t)src * DD);
        const float4* vp = (const float4*)(v + (size_t)src * DD);
        const float4 e0 = ep[li], e1 = ep[li + 1];
        const float4 k0 = kp[li], k1 = kp[li + 1];
        const float4 v0 = vp[li], v1 = vp[li + 1];

        float dot = q0.x * (k0.x + e0.x) + q0.y * (k0.y + e0.y)
                  + q0.z * (k0.z + e0.z) + q0.w * (k0.w + e0.w)
                  + q1.x * (k1.x + e1.x) + q1.y * (k1.y + e1.y)
                  + q1.z * (k1.z + e1.z) + q1.w * (k1.w + e1.w);
        dot += __shfl_xor_sync(0xffffffffu, dot, 1);
        dot += __shfl_xor_sync(0xffffffffu, dot, 2);
        dot += __shfl_xor_sync(0xffffffffu, dot, 4);
        const float a = dot * 0.125f;

        const float mn = fmaxf(m, a);
        const float sc = __expf(m - mn);
        const float w  = __expf(a - mn);
        d = d * sc + w;
        a0.x = a0.x * sc + (v0.x + e0.x) * w;
        a0.y = a0.y * sc + (v0.y + e0.y) * w;
        a0.z = a0.z * sc + (v0.z + e0.z) * w;
        a0.w = a0.w * sc + (v0.w + e0.w) * w;
        a1.x = a1.x * sc + (v1.x + e1.x) * w;
        a1.y = a1.y * sc + (v1.y + e1.y) * w;
        a1.z = a1.z * sc + (v1.z + e1.z) * w;
        a1.w = a1.w * sc + (v1.w + e1.w) * w;
        m = mn;
    }

    const float inv = 1.f / (d + 1e-16f);
    float* op = out + (size_t)warp * DD + lane * 8;
    float4 o0 = *(float4*)op, o1 = *(float4*)(op + 4);
    o0.x += a0.x * inv; o0.y += a0.y * inv;
    o0.z += a0.z * inv; o0.w += a0.w * inv;
    o1.x += a1.x * inv; o1.y += a1.y * inv;
    o1.z += a1.z * inv; o1.w += a1.w * inv;
    *(float4*)op       = o0;
    *(float4*)(op + 4) = o1;
}

// ================= host driver =================
static void* symaddr(const void* sym)
{
    void* p = nullptr;
    cudaGetSymbolAddress(&p, sym);
    return p;
}

extern "C" void kernel_launch(void* const* d_in, const int* in_sizes, int n_in,
                              void* d_out, int out_size)
{
    const float* x  = (const float*)d_in[0];
    const int*   ei = (const int*)d_in[1];
    const float* ea = (const float*)d_in[2];
    const float* W1[5] = { (const float*)d_in[3],  (const float*)d_in[5],
                           (const float*)d_in[7],  (const float*)d_in[9],
                           (const float*)d_in[11] };
    const float* b1[5] = { (const float*)d_in[4],  (const float*)d_in[6],
                           (const float*)d_in[8],  (const float*)d_in[10],
                           (const float*)d_in[12] };
    const float* W2[5] = { (const float*)d_in[13], (const float*)d_in[15],
                           (const float*)d_in[17], (const float*)d_in[19],
                           (const float*)d_in[21] };
    const float* b2[5] = { (const float*)d_in[14], (const float*)d_in[16],
                           (const float*)d_in[18], (const float*)d_in[20],
                           (const float*)d_in[22] };

    static float *q = nullptr, *k, *v, *h, *e1, *e2;
    static bf16 *xhi, *xlo, *ehi, *elo, *whi, *wlo;
    static int *adj;
    static cudaStream_t sB;
    static cudaEvent_t evRoot, evCSR, evE1, evE2;
    if (!q) {
        q  = (float*)symaddr(g_q);  k  = (float*)symaddr(g_k);
        v  = (float*)symaddr(g_v);  h  = (float*)symaddr(g_h);
        e1 = (float*)symaddr(g_e1); e2 = (float*)symaddr(g_e2);
        xhi = (bf16*)symaddr(g_xhi); xlo = (bf16*)symaddr(g_xlo);
        ehi = (bf16*)symaddr(g_ehi); elo = (bf16*)symaddr(g_elo);
        whi = (bf16*)symaddr(g_whi); wlo = (bf16*)symaddr(g_wlo);
        adj = (int*)symaddr(g_adj);
        cudaFuncSetAttribute(gemm_bf3,
            cudaFuncAttributeMaxDynamicSharedMemorySize, GEMM_SMEM);
        cudaStreamCreateWithFlags(&sB, cudaStreamNonBlocking);
        cudaEventCreateWithFlags(&evRoot, cudaEventDisableTiming);
        cudaEventCreateWithFlags(&evCSR,  cudaEventDisableTiming);
        cudaEventCreateWithFlags(&evE1,   cudaEventDisableTiming);
        cudaEventCreateWithFlags(&evE2,   cudaEventDisableTiming);
    }
    float* out = (float*)d_out;

    const dim3 gQKVS(8, (Nn + 127) / 128);
    const dim3 gEdge(2, Ee / 128);
    const int  bFlash = (Nn * 32 + 255) / 256;
    const int  bSplit = (Nn * DD / 4 + 255) / 256;
    const int  NB = (Nn + 255) / 256;

    // ================= fork =================
    cudaEventRecord(evRoot, 0);
    cudaStreamWaitEvent(sB, evRoot, 0);

    // sB: edge-side prep (independent of CSR until the GEMMs)
    tsplit_w<<<128, 256, 0, sB>>>(W1[3], whi + WOFF_E1, wlo + WOFF_E1, 128);
    tsplit_w<<<128, 256, 0, sB>>>(W2[3], whi + WOFF_E2, wlo + WOFF_E2, 128);
    split_bf<<<(int)(((size_t)Ee * EDD / 4 + 255) / 256), 256, 0, sB>>>(
        ea, ehi, elo, (size_t)Ee * EDD / 4);

    // main: node-side prep + CSR
    const float* qkvs1[4] = { W1[0], W1[1], W1[2], W1[4] };
    const float* qkvs2[4] = { W2[0], W2[1], W2[2], W2[4] };
    for (int s = 0; s < 4; s++) {
        tsplit_w<<<256, 256>>>(qkvs1[s], whi + WOFF_QKVS1 + (size_t)s * 65536,
                                         wlo + WOFF_QKVS1 + (size_t)s * 65536, 256);
        tsplit_w<<<256, 256>>>(qkvs2[s], whi + WOFF_QKVS2 + (size_t)s * 65536,
                                         wlo + WOFF_QKVS2 + (size_t)s * 65536, 256);
    }
    split_bf<<<bSplit, 256>>>(x, xhi, xlo, (size_t)Nn * DD / 4);

    csr_zero<<<NB, 256>>>();
    csr_count<<<(Ee + 255) / 256, 256>>>(ei);
    csr_scan_local<<<NB, 256>>>();
    csr_scan_bsum<<<1, 256>>>(NB);
    csr_finalize<<<NB, 256>>>();
    csr_fill<<<(Ee + 255) / 256, 256>>>(ei);
    cudaEventRecord(evCSR, 0);

    // sB: dst-sorted edge GEMMs (A rows gathered via g_adj)
    cudaStreamWaitEvent(sB, evCSR, 0);
    gemm_bf3<<<gEdge, 256, GEMM_SMEM, sB>>>(Ee, 128, ehi, elo,
        whi + WOFF_E1, wlo + WOFF_E1, adj,
        e1, e1, e1, e1, b1[3], b1[3], b1[3], b1[3]);
    cudaEventRecord(evE1, sB);
    gemm_bf3<<<gEdge, 256, GEMM_SMEM, sB>>>(Ee, 128, ehi, elo,
        whi + WOFF_E2, wlo + WOFF_E2, adj,
        e2, e2, e2, e2, b2[3], b2[3], b2[3], b2[3]);
    cudaEventRecord(evE2, sB);

    // main: layer 1 node QKVS (skip -> h)
    gemm_bf3<<<gQKVS, 256, GEMM_SMEM>>>(Nn, 256, xhi, xlo,
        whi + WOFF_QKVS1, wlo + WOFF_QKVS1, nullptr,
        q, k, v, h, b1[0], b1[1], b1[2], b1[4]);

    cudaStreamWaitEvent(0, evE1, 0);
    flash_agg<<<bFlash, 256>>>(q, k, v, e1, h);
    relu_split<<<bSplit, 256>>>(h, xhi, xlo, (size_t)Nn * DD / 4);

    // main: layer 2 node QKVS (skip -> out)
    gemm_bf3<<<gQKVS, 256, GEMM_SMEM>>>(Nn, 256, xhi, xlo,
        whi + WOFF_QKVS2, wlo + WOFF_QKVS2, nullptr,
        q, k, v, out, b2[0], b2[1], b2[2], b2[4]);

    cudaStreamWaitEvent(0, evE2, 0);
    flash_agg<<<bFlash, 256>>>(q, k, v, e2, out);
}

// round 8
// speedup vs baseline: 3.1737x; 1.1111x over previous
#include <cuda_runtime.h>
#include <cuda_bf16.h>
#include <cuda_fp16.h>
#include <math.h>
#include <math_constants.h>
#include <cstdint>

#define Nn   50000
#define Ee   800000
#define DD   256
#define EDD  128
#define Hh   4

typedef __nv_bfloat16 bf16;

// ================= scratch (device globals) =================
__device__ __half g_q[Nn * DD];
__device__ __half g_k[Nn * DD];
__device__ __half g_v[Nn * DD];
__device__ float  g_h[Nn * DD];
__device__ __half g_e1[(size_t)Ee * DD];   // layer-1 edge projections (dst-sorted, fp16)
__device__ __half g_e2[(size_t)Ee * DD];   // layer-2 edge projections (dst-sorted, fp16)
// CSR for dst-grouped edges
__device__ int g_deg[Nn];
__device__ int g_cursor[Nn];
__device__ int g_loc[Nn];
__device__ int g_bsum[256];
__device__ int g_rowptr[Nn + 1];
__device__ int g_adj[Ee];                 // sorted pos -> original edge id
__device__ int g_srcp[Ee];                // sorted pos -> src node
// pre-split bf16 operands
__device__ bf16 g_xhi[Nn * DD], g_xlo[Nn * DD];
__device__ bf16 g_ehi[(size_t)Ee * EDD], g_elo[(size_t)Ee * EDD];
#define WOFF_QKVS1 0
#define WOFF_E1    262144
#define WOFF_QKVS2 294912
#define WOFF_E2    557056
__device__ bf16 g_whi[589824], g_wlo[589824];

// ================= PTX helpers =================
__device__ __forceinline__ uint32_t smem_u32(const void* p) {
    uint32_t a;
    asm("{ .reg .u64 t; cvta.to.shared.u64 t, %1; cvt.u32.u64 %0, t; }"
        : "=r"(a) : "l"(p));
    return a;
}
__device__ __forceinline__ void ldsm_x4(uint32_t* r, uint32_t a) {
    asm volatile("ldmatrix.sync.aligned.m8n8.x4.shared.b16 {%0,%1,%2,%3}, [%4];"
        : "=r"(r[0]), "=r"(r[1]), "=r"(r[2]), "=r"(r[3]) : "r"(a));
}
__device__ __forceinline__ void ldsm_x2(uint32_t* r, uint32_t a) {
    asm volatile("ldmatrix.sync.aligned.m8n8.x2.shared.b16 {%0,%1}, [%2];"
        : "=r"(r[0]), "=r"(r[1]) : "r"(a));
}
__device__ __forceinline__ void mma_bf16(float* d, const uint32_t* a, const uint32_t* b) {
    asm volatile("mma.sync.aligned.m16n8k16.row.col.f32.bf16.bf16.f32 "
        "{%0,%1,%2,%3}, {%4,%5,%6,%7}, {%8,%9}, {%0,%1,%2,%3};"
        : "+f"(d[0]), "+f"(d[1]), "+f"(d[2]), "+f"(d[3])
        : "r"(a[0]), "r"(a[1]), "r"(a[2]), "r"(a[3]), "r"(b[0]), "r"(b[1]));
}
__device__ __forceinline__ void cpa16(uint32_t dst, const void* src, int sz) {
    asm volatile("cp.async.cg.shared.global [%0], [%1], 16, %2;"
        :: "r"(dst), "l"(src), "r"(sz) : "memory");
}
#define CP_COMMIT() asm volatile("cp.async.commit_group;" ::: "memory")
#define CP_WAIT1()  asm volatile("cp.async.wait_group 1;" ::: "memory")
#define CP_WAIT0()  asm volatile("cp.async.wait_group 0;" ::: "memory")

__device__ __forceinline__ void cvt8(float* f, uint4 u) {
    const __half2* h = (const __half2*)&u;
    float2 t;
    t = __half22float2(h[0]); f[0] = t.x; f[1] = t.y;
    t = __half22float2(h[1]); f[2] = t.x; f[3] = t.y;
    t = __half22float2(h[2]); f[4] = t.x; f[5] = t.y;
    t = __half22float2(h[3]); f[6] = t.x; f[7] = t.y;
}

// ================= bf16x3 pipelined GEMM =============
// Outputs 0..2 are fp16 (q/k/v or e); output 3 is fp32 (skip accumulator).
#define PAD 40
#define STG_B 40960
#define OFF_AL 10240
#define OFF_BH 20480
#define OFF_BL 30720
#define GEMM_SMEM (2 * STG_B)

__global__ __launch_bounds__(256, 2) void gemm_bf3(
    int M, int K,
    const bf16* __restrict__ Ahi, const bf16* __restrict__ Alo,
    const bf16* __restrict__ Whi, const bf16* __restrict__ Wlo,
    const int* __restrict__ rowmap,
    __half* c0h, __half* c1h, __half* c2h, float* c3f,
    const float* b0, const float* b1, const float* b2, const float* b3)
{
    extern __shared__ char sm[];
    const uint32_t sb = smem_u32(sm);

    const int tid  = threadIdx.x;
    const int lane = tid & 31;
    const int wid  = tid >> 5;
    const int wm   = wid >> 2;
    const int wn   = wid & 3;
    const int row0 = blockIdx.y * 128;
    const int nW0  = blockIdx.x * 128;

    __half* const houts[3]       = { c0h, c1h, c2h };
    const float* const biases[4] = { b0, b1, b2, b3 };
    const int    outIdx = blockIdx.x >> 1;
    const float* bias   = biases[outIdx];
    const int    colb   = (blockIdx.x & 1) * 128;

    const int lr  = tid >> 1;
    const int lcb = (tid & 1) * 16;
    const int grA  = row0 + lr;
    const int okA  = (grA < M) ? 16 : 0;
    int arow = okA ? grA : 0;
    if (rowmap) arow = rowmap[arow];
    const size_t aoff = (size_t)arow * K + lcb;
    const size_t boff = (size_t)(nW0 + lr) * K + lcb;
    const char* pAh = (const char*)(Ahi + aoff);
    const char* pAl = (const char*)(Alo + aoff);
    const char* pBh = (const char*)(Whi + boff);
    const char* pBl = (const char*)(Wlo + boff);
    const uint32_t dstA = sb + (uint32_t)(lr * 80 + (tid & 1) * 32);

    const int nchunk = K >> 5;

    const int aRow    = lane & 15;
    const int aColSel = (lane >> 4) * 8;
    const int bRow    = lane & 7;
    const int bColSel = ((lane >> 3) & 1) * 8;

    float acc[4][4][4];
    #pragma unroll
    for (int i = 0; i < 4; i++)
        #pragma unroll
        for (int j = 0; j < 4; j++)
            #pragma unroll
            for (int t = 0; t < 4; t++) acc[i][j][t] = 0.f;

    {
        cpa16(dstA,               pAh,      okA);
        cpa16(dstA + 16,          pAh + 16, okA);
        cpa16(dstA + OFF_AL,      pAl,      okA);
        cpa16(dstA + OFF_AL + 16, pAl + 16, okA);
        cpa16(dstA + OFF_BH,      pBh,      16);
        cpa16(dstA + OFF_BH + 16, pBh + 16, 16);
        cpa16(dstA + OFF_BL,      pBl,      16);
        cpa16(dstA + OFF_BL + 16, pBl + 16, 16);
        CP_COMMIT();
    }

    for (int c = 0; c < nchunk; c++) {
        if (c + 1 < nchunk) {
            const uint32_t d = dstA + ((c + 1) & 1) * STG_B;
            const int go = (c + 1) * 64;
            cpa16(d,               pAh + go,      okA);
            cpa16(d + 16,          pAh + go + 16, okA);
            cpa16(d + OFF_AL,      pAl + go,      okA);
            cpa16(d + OFF_AL + 16, pAl + go + 16, okA);
            cpa16(d + OFF_BH,      pBh + go,      16);
            cpa16(d + OFF_BH + 16, pBh + go + 16, 16);
            cpa16(d + OFF_BL,      pBl + go,      16);
            cpa16(d + OFF_BL + 16, pBl + go + 16, 16);
            CP_COMMIT();
            CP_WAIT1();
        } else {
            CP_WAIT0();
        }
        __syncthreads();

        const uint32_t sbase = sb + (c & 1) * STG_B;
        #pragma unroll
        for (int ks = 0; ks < 2; ks++) {
            const int kb = ks * 16;
            uint32_t ah[4][4], al[4][4], bh[4][2], bl[4][2];
            #pragma unroll
            for (int mt = 0; mt < 4; mt++) {
                const uint32_t off = sbase +
                    (uint32_t)((wm * 64 + mt * 16 + aRow) * PAD + kb + aColSel) * 2;
                ldsm_x4(ah[mt], off);
                ldsm_x4(al[mt], off + OFF_AL);
            }
            #pragma unroll
            for (int nt = 0; nt < 4; nt++) {
                const uint32_t off = sbase + OFF_BH +
                    (uint32_t)((wn * 32 + nt * 8 + bRow) * PAD + kb + bColSel) * 2;
                ldsm_x2(bh[nt], off);
                ldsm_x2(bl[nt], off + (OFF_BL - OFF_BH));
            }
            #pragma unroll
            for (int mt = 0; mt < 4; mt++)
                #pragma unroll
                for (int nt = 0; nt < 4; nt++) {
                    mma_bf16(acc[mt][nt], ah[mt], bh[nt]);
                    mma_bf16(acc[mt][nt], ah[mt], bl[nt]);
                    mma_bf16(acc[mt][nt], al[mt], bh[nt]);
                }
        }
        __syncthreads();
    }

    // ---- epilogue: fp16 for outputs 0-2, fp32 for output 3 ----
    if (outIdx < 3) {
        __half* Ch = houts[outIdx];
        #pragma unroll
        for (int mt = 0; mt < 4; mt++) {
            const int r = row0 + wm * 64 + mt * 16 + (lane >> 2);
            #pragma unroll
            for (int nt = 0; nt < 4; nt++) {
                const int c = colb + wn * 32 + nt * 8 + (lane & 3) * 2;
                if (r < M)
                    *(__half2*)(Ch + (size_t)r * 256 + c) =
                        __floats2half2_rn(acc[mt][nt][0] + bias[c],
                                          acc[mt][nt][1] + bias[c + 1]);
                if (r + 8 < M)
                    *(__half2*)(Ch + (size_t)(r + 8) * 256 + c) =
                        __floats2half2_rn(acc[mt][nt][2] + bias[c],
                                          acc[mt][nt][3] + bias[c + 1]);
            }
        }
    } else {
        #pragma unroll
        for (int mt = 0; mt < 4; mt++) {
            const int r = row0 + wm * 64 + mt * 16 + (lane >> 2);
            #pragma unroll
            for (int nt = 0; nt < 4; nt++) {
                const int c = colb + wn * 32 + nt * 8 + (lane & 3) * 2;
                if (r < M) {
                    float2 o = make_float2(acc[mt][nt][0] + bias[c],
                                           acc[mt][nt][1] + bias[c + 1]);
                    *(float2*)(c3f + (size_t)r * 256 + c) = o;
                }
                if (r + 8 < M) {
                    float2 o = make_float2(acc[mt][nt][2] + bias[c],
                                           acc[mt][nt][3] + bias[c + 1]);
                    *(float2*)(c3f + (size_t)(r + 8) * 256 + c) = o;
                }
            }
        }
    }
}

// ======== weight transpose + split ========
__global__ void tsplit_w(const float* __restrict__ W,
                         bf16* __restrict__ hi, bf16* __restrict__ lo, int K)
{
    const int i = blockIdx.x * blockDim.x + threadIdx.x;
    if (i < K * 256) {
        const int k = i >> 8, n = i & 255;
        const float v = W[i];
        const bf16 h = __float2bfloat16(v);
        hi[(size_t)n * K + k] = h;
        lo[(size_t)n * K + k] = __float2bfloat16(v - __bfloat162float(h));
    }
}

__global__ void split_bf(const float* __restrict__ in,
                         bf16* __restrict__ hi, bf16* __restrict__ lo, size_t n4)
{
    const size_t i = (size_t)blockIdx.x * blockDim.x + threadIdx.x;
    if (i >= n4) return;
    float4 v = ((const float4*)in)[i];
    __nv_bfloat162 h0 = __floats2bfloat162_rn(v.x, v.y);
    __nv_bfloat162 h1 = __floats2bfloat162_rn(v.z, v.w);
    __nv_bfloat162 l0 = __floats2bfloat162_rn(v.x - __low2float(h0), v.y - __high2float(h0));
    __nv_bfloat162 l1 = __floats2bfloat162_rn(v.z - __low2float(h1), v.w - __high2float(h1));
    ((__nv_bfloat162*)hi)[2 * i]     = h0;
    ((__nv_bfloat162*)hi)[2 * i + 1] = h1;
    ((__nv_bfloat162*)lo)[2 * i]     = l0;
    ((__nv_bfloat162*)lo)[2 * i + 1] = l1;
}

__global__ void relu_split(const float* __restrict__ in,
                           bf16* __restrict__ hi, bf16* __restrict__ lo, size_t n4)
{
    const size_t i = (size_t)blockIdx.x * blockDim.x + threadIdx.x;
    if (i >= n4) return;
    float4 v = ((const float4*)in)[i];
    v.x = fmaxf(v.x, 0.f); v.y = fmaxf(v.y, 0.f);
    v.z = fmaxf(v.z, 0.f); v.w = fmaxf(v.w, 0.f);
    __nv_bfloat162 h0 = __floats2bfloat162_rn(v.x, v.y);
    __nv_bfloat162 h1 = __floats2bfloat162_rn(v.z, v.w);
    __nv_bfloat162 l0 = __floats2bfloat162_rn(v.x - __low2float(h0), v.y - __high2float(h0));
    __nv_bfloat162 l1 = __floats2bfloat162_rn(v.z - __low2float(h1), v.w - __high2float(h1));
    ((__nv_bfloat162*)hi)[2 * i]     = h0;
    ((__nv_bfloat162*)hi)[2 * i + 1] = h1;
    ((__nv_bfloat162*)lo)[2 * i]     = l0;
    ((__nv_bfloat162*)lo)[2 * i + 1] = l1;
}

// ================= CSR build =================
__global__ void csr_zero()
{
    const int i = blockIdx.x * blockDim.x + threadIdx.x;
    if (i < Nn) { g_deg[i] = 0; g_cursor[i] = 0; }
}
__global__ void csr_count(const int* __restrict__ ei)
{
    const int i = blockIdx.x * blockDim.x + threadIdx.x;
    if (i < Ee) atomicAdd(&g_deg[ei[Ee + i]], 1);
}
__global__ void csr_scan_local()
{
    __shared__ int s[256];
    const int tid = threadIdx.x;
    const int i = blockIdx.x * 256 + tid;
    const int v = (i < Nn) ? g_deg[i] : 0;
    s[tid] = v; __syncthreads();
    for (int off = 1; off < 256; off <<= 1) {
        const int t = (tid >= off) ? s[tid - off] : 0;
        __syncthreads();
        s[tid] += t;
        __syncthreads();
    }
    if (i < Nn) g_loc[i] = s[tid] - v;
    if (tid == 255) g_bsum[blockIdx.x] = s[255];
}
__global__ void csr_scan_bsum(int nb)
{
    __shared__ int s[256];
    const int t = threadIdx.x;
    const int v = (t < nb) ? g_bsum[t] : 0;
    s[t] = v; __syncthreads();
    for (int off = 1; off < 256; off <<= 1) {
        const int u = (t >= off) ? s[t - off] : 0;
        __syncthreads();
        s[t] += u;
        __syncthreads();
    }
    if (t < nb) g_bsum[t] = s[t] - v;
}
__global__ void csr_finalize()
{
    const int i = blockIdx.x * blockDim.x + threadIdx.x;
    if (i < Nn) g_rowptr[i] = g_loc[i] + g_bsum[i >> 8];
    if (i == 0) g_rowptr[Nn] = Ee;
}
__global__ void csr_fill(const int* __restrict__ ei)
{
    const int eid = blockIdx.x * blockDim.x + threadIdx.x;
    if (eid < Ee) {
        const int src = ei[eid];
        const int dst = ei[Ee + eid];
        const int p = atomicAdd(&g_cursor[dst], 1);
        const int pos = g_rowptr[dst] + p;
        g_adj[pos]  = eid;
        g_srcp[pos] = src;
    }
}

// ================= flash-style segment softmax + aggregate (fp16 in) ======
__global__ __launch_bounds__(256) void flash_agg(
    const __half* __restrict__ q, const __half* __restrict__ k,
    const __half* __restrict__ v, const __half* __restrict__ e,
    float* __restrict__ out)
{
    const int warp = (blockIdx.x * blockDim.x + threadIdx.x) >> 5;
    const int lane = threadIdx.x & 31;
    if (warp >= Nn) return;
    const int beg = g_rowptr[warp];
    const int end = g_rowptr[warp + 1];
    if (beg == end) return;

    const int co = lane * 8;
    float qf[8];
    { uint4 u = *(const uint4*)(q + (size_t)warp * DD + co); cvt8(qf, u); }

    float m = -CUDART_INF_F, d = 0.f;
    float a[8];
    #pragma unroll
    for (int i = 0; i < 8; i++) a[i] = 0.f;

    for (int idx = beg; idx < end; idx++) {
        const int src = g_srcp[idx];
        float ef[8], kf[8], vf[8];
        { uint4 u = *(const uint4*)(e + (size_t)idx * DD + co); cvt8(ef, u); }
        { uint4 u = *(const uint4*)(k + (size_t)src * DD + co); cvt8(kf, u); }
        { uint4 u = *(const uint4*)(v + (size_t)src * DD + co); cvt8(vf, u); }

        float dot = 0.f;
        #pragma unroll
        for (int i = 0; i < 8; i++) dot += qf[i] * (kf[i] + ef[i]);
        dot += __shfl_xor_sync(0xffffffffu, dot, 1);
        dot += __shfl_xor_sync(0xffffffffu, dot, 2);
        dot += __shfl_xor_sync(0xffffffffu, dot, 4);
        const float al = dot * 0.125f;

        const float mn = fmaxf(m, al);
        const float sc = __expf(m - mn);
        const float w  = __expf(al - mn);
        d = d * sc + w;
        #pragma unroll
        for (int i = 0; i < 8; i++) a[i] = a[i] * sc + (vf[i] + ef[i]) * w;
        m = mn;
    }

    const float inv = 1.f / (d + 1e-16f);
    float* op = out + (size_t)warp * DD + co;
    float4 o0 = *(float4*)op, o1 = *(float4*)(op + 4);
    o0.x += a[0] * inv; o0.y += a[1] * inv;
    o0.z += a[2] * inv; o0.w += a[3] * inv;
    o1.x += a[4] * inv; o1.y += a[5] * inv;
    o1.z += a[6] * inv; o1.w += a[7] * inv;
    *(float4*)op       = o0;
    *(float4*)(op + 4) = o1;
}

// ================= host driver =================
static void* symaddr(const void* sym)
{
    void* p = nullptr;
    cudaGetSymbolAddress(&p, sym);
    return p;
}

extern "C" void kernel_launch(void* const* d_in, const int* in_sizes, int n_in,
                              void* d_out, int out_size)
{
    const float* x  = (const float*)d_in[0];
    const int*   ei = (const int*)d_in[1];
    const float* ea = (const float*)d_in[2];
    const float* W1[5] = { (const float*)d_in[3],  (const float*)d_in[5],
                           (const float*)d_in[7],  (const float*)d_in[9],
                           (const float*)d_in[11] };
    const float* b1[5] = { (const float*)d_in[4],  (const float*)d_in[6],
                           (const float*)d_in[8],  (const float*)d_in[10],
                           (const float*)d_in[12] };
    const float* W2[5] = { (const float*)d_in[13], (const float*)d_in[15],
                           (const float*)d_in[17], (const float*)d_in[19],
                           (const float*)d_in[21] };
    const float* b2[5] = { (const float*)d_in[14], (const float*)d_in[16],
                           (const float*)d_in[18], (const float*)d_in[20],
                           (const float*)d_in[22] };

    static __half *q = nullptr, *k, *v, *e1, *e2;
    static float *h;
    static bf16 *xhi, *xlo, *ehi, *elo, *whi, *wlo;
    static int *adj;
    static cudaStream_t sB;
    static cudaEvent_t evRoot, evCSR, evE1, evE2;
    if (!q) {
        q  = (__half*)symaddr(g_q);  k  = (__half*)symaddr(g_k);
        v  = (__half*)symaddr(g_v);  h  = (float*)symaddr(g_h);
        e1 = (__half*)symaddr(g_e1); e2 = (__half*)symaddr(g_e2);
        xhi = (bf16*)symaddr(g_xhi); xlo = (bf16*)symaddr(g_xlo);
        ehi = (bf16*)symaddr(g_ehi); elo = (bf16*)symaddr(g_elo);
        whi = (bf16*)symaddr(g_whi); wlo = (bf16*)symaddr(g_wlo);
        adj = (int*)symaddr(g_adj);
        cudaFuncSetAttribute(gemm_bf3,
            cudaFuncAttributeMaxDynamicSharedMemorySize, GEMM_SMEM);
        cudaStreamCreateWithFlags(&sB, cudaStreamNonBlocking);
        cudaEventCreateWithFlags(&evRoot, cudaEventDisableTiming);
        cudaEventCreateWithFlags(&evCSR,  cudaEventDisableTiming);
        cudaEventCreateWithFlags(&evE1,   cudaEventDisableTiming);
        cudaEventCreateWithFlags(&evE2,   cudaEventDisableTiming);
    }
    float* out = (float*)d_out;

    const dim3 gQKVS(8, (Nn + 127) / 128);
    const dim3 gEdge(2, Ee / 128);
    const int  bFlash = (Nn * 32 + 255) / 256;
    const int  bSplit = (Nn * DD / 4 + 255) / 256;
    const int  NB = (Nn + 255) / 256;

    // ================= fork =================
    cudaEventRecord(evRoot, 0);
    cudaStreamWaitEvent(sB, evRoot, 0);

    // sB: edge-side prep
    tsplit_w<<<128, 256, 0, sB>>>(W1[3], whi + WOFF_E1, wlo + WOFF_E1, 128);
    tsplit_w<<<128, 256, 0, sB>>>(W2[3], whi + WOFF_E2, wlo + WOFF_E2, 128);
    split_bf<<<(int)(((size_t)Ee * EDD / 4 + 255) / 256), 256, 0, sB>>>(
        ea, ehi, elo, (size_t)Ee * EDD / 4);

    // main: node-side prep + CSR
    const float* qkvs1[4] = { W1[0], W1[1], W1[2], W1[4] };
    const float* qkvs2[4] = { W2[0], W2[1], W2[2], W2[4] };
    for (int s = 0; s < 4; s++) {
        tsplit_w<<<256, 256>>>(qkvs1[s], whi + WOFF_QKVS1 + (size_t)s * 65536,
                                         wlo + WOFF_QKVS1 + (size_t)s * 65536, 256);
        tsplit_w<<<256, 256>>>(qkvs2[s], whi + WOFF_QKVS2 + (size_t)s * 65536,
                                         wlo + WOFF_QKVS2 + (size_t)s * 65536, 256);
    }
    split_bf<<<bSplit, 256>>>(x, xhi, xlo, (size_t)Nn * DD / 4);

    csr_zero<<<NB, 256>>>();
    csr_count<<<(Ee + 255) / 256, 256>>>(ei);
    csr_scan_local<<<NB, 256>>>();
    csr_scan_bsum<<<1, 256>>>(NB);
    csr_finalize<<<NB, 256>>>();
    csr_fill<<<(Ee + 255) / 256, 256>>>(ei);
    cudaEventRecord(evCSR, 0);

    // sB: dst-sorted edge GEMMs -> fp16 e buffers
    cudaStreamWaitEvent(sB, evCSR, 0);
    gemm_bf3<<<gEdge, 256, GEMM_SMEM, sB>>>(Ee, 128, ehi, elo,
        whi + WOFF_E1, wlo + WOFF_E1, adj,
        e1, e1, e1, nullptr, b1[3], b1[3], b1[3], b1[3]);
    cudaEventRecord(evE1, sB);
    gemm_bf3<<<gEdge, 256, GEMM_SMEM, sB>>>(Ee, 128, ehi, elo,
        whi + WOFF_E2, wlo + WOFF_E2, adj,
        e2, e2, e2, nullptr, b2[3], b2[3], b2[3], b2[3]);
    cudaEventRecord(evE2, sB);

    // main: layer 1 node QKVS (q/k/v fp16, skip fp32 -> h)
    gemm_bf3<<<gQKVS, 256, GEMM_SMEM>>>(Nn, 256, xhi, xlo,
        whi + WOFF_QKVS1, wlo + WOFF_QKVS1, nullptr,
        q, k, v, h, b1[0], b1[1], b1[2], b1[4]);

    cudaStreamWaitEvent(0, evE1, 0);
    flash_agg<<<bFlash, 256>>>(q, k, v, e1, h);
    relu_split<<<bSplit, 256>>>(h, xhi, xlo, (size_t)Nn * DD / 4);

    // main: layer 2 node QKVS (skip -> out)
    gemm_bf3<<<gQKVS, 256, GEMM_SMEM>>>(Nn, 256, xhi, xlo,
        whi + WOFF_QKVS2, wlo + WOFF_QKVS2, nullptr,
        q, k, v, out, b2[0], b2[1], b2[2], b2[4]);

    cudaStreamWaitEvent(0, evE2, 0);
    flash_agg<<<bFlash, 256>>>(q, k, v, e2, out);
}

// round 9
// speedup vs baseline: 3.9739x; 1.2521x over previous
#include <cuda_runtime.h>
#include <cuda_bf16.h>
#include <cuda_fp16.h>
#include <math.h>
#include <math_constants.h>
#include <cstdint>

#define Nn   50000
#define Ee   800000
#define DD   256
#define EDD  128
#define Hh   4

typedef __nv_bfloat16 bf16;

// ================= scratch (device globals) =================
__device__ __half g_q[Nn * DD];
__device__ __half g_k[Nn * DD];
__device__ __half g_v[Nn * DD];
__device__ float  g_h[Nn * DD];
__device__ __half g_e1[(size_t)Ee * DD];   // layer-1 edge projections (dst-sorted, fp16)
__device__ __half g_e2[(size_t)Ee * DD];   // layer-2 edge projections (dst-sorted, fp16)
// CSR for dst-grouped edges
__device__ int g_deg[Nn];
__device__ int g_cursor[Nn];
__device__ int g_loc[Nn];
__device__ int g_bsum[256];
__device__ int g_rowptr[Nn + 1];
__device__ int g_adj[Ee];                 // sorted pos -> original edge id
__device__ int g_srcp[Ee];                // sorted pos -> src node
// bf16 split operands (node side), fp16 edge operands
__device__ bf16 g_xhi[Nn * DD], g_xlo[Nn * DD];
__device__ __half g_eaf16[(size_t)Ee * EDD];
#define WOFF_QKVS1 0
#define WOFF_QKVS2 262144
__device__ bf16 g_whi[524288], g_wlo[524288];
__device__ __half g_wef16[2 * 256 * 128];   // fp16 K-major edge weights

// ================= PTX helpers =================
__device__ __forceinline__ uint32_t smem_u32(const void* p) {
    uint32_t a;
    asm("{ .reg .u64 t; cvta.to.shared.u64 t, %1; cvt.u32.u64 %0, t; }"
        : "=r"(a) : "l"(p));
    return a;
}
__device__ __forceinline__ void ldsm_x4(uint32_t* r, uint32_t a) {
    asm volatile("ldmatrix.sync.aligned.m8n8.x4.shared.b16 {%0,%1,%2,%3}, [%4];"
        : "=r"(r[0]), "=r"(r[1]), "=r"(r[2]), "=r"(r[3]) : "r"(a));
}
__device__ __forceinline__ void ldsm_x2(uint32_t* r, uint32_t a) {
    asm volatile("ldmatrix.sync.aligned.m8n8.x2.shared.b16 {%0,%1}, [%2];"
        : "=r"(r[0]), "=r"(r[1]) : "r"(a));
}
__device__ __forceinline__ void mma_bf16(float* d, const uint32_t* a, const uint32_t* b) {
    asm volatile("mma.sync.aligned.m16n8k16.row.col.f32.bf16.bf16.f32 "
        "{%0,%1,%2,%3}, {%4,%5,%6,%7}, {%8,%9}, {%0,%1,%2,%3};"
        : "+f"(d[0]), "+f"(d[1]), "+f"(d[2]), "+f"(d[3])
        : "r"(a[0]), "r"(a[1]), "r"(a[2]), "r"(a[3]), "r"(b[0]), "r"(b[1]));
}
__device__ __forceinline__ void mma_f16(float* d, const uint32_t* a, const uint32_t* b) {
    asm volatile("mma.sync.aligned.m16n8k16.row.col.f32.f16.f16.f32 "
        "{%0,%1,%2,%3}, {%4,%5,%6,%7}, {%8,%9}, {%0,%1,%2,%3};"
        : "+f"(d[0]), "+f"(d[1]), "+f"(d[2]), "+f"(d[3])
        : "r"(a[0]), "r"(a[1]), "r"(a[2]), "r"(a[3]), "r"(b[0]), "r"(b[1]));
}
__device__ __forceinline__ void cpa16(uint32_t dst, const void* src, int sz) {
    asm volatile("cp.async.cg.shared.global [%0], [%1], 16, %2;"
        :: "r"(dst), "l"(src), "r"(sz) : "memory");
}
#define CP_COMMIT() asm volatile("cp.async.commit_group;" ::: "memory")
#define CP_WAIT1()  asm volatile("cp.async.wait_group 1;" ::: "memory")
#define CP_WAIT0()  asm volatile("cp.async.wait_group 0;" ::: "memory")

__device__ __forceinline__ void cvt8(float* f, uint4 u) {
    const __half2* h = (const __half2*)&u;
    float2 t;
    t = __half22float2(h[0]); f[0] = t.x; f[1] = t.y;
    t = __half22float2(h[1]); f[2] = t.x; f[3] = t.y;
    t = __half22float2(h[2]); f[4] = t.x; f[5] = t.y;
    t = __half22float2(h[3]); f[6] = t.x; f[7] = t.y;
}

// ================= bf16x3 pipelined GEMM (node QKVS) =============
#define PAD 40
#define STG_B 40960
#define OFF_AL 10240
#define OFF_BH 20480
#define OFF_BL 30720
#define GEMM_SMEM (2 * STG_B)

__global__ __launch_bounds__(256, 2) void gemm_bf3(
    int M, int K,
    const bf16* __restrict__ Ahi, const bf16* __restrict__ Alo,
    const bf16* __restrict__ Whi, const bf16* __restrict__ Wlo,
    __half* c0h, __half* c1h, __half* c2h, float* c3f,
    const float* b0, const float* b1, const float* b2, const float* b3)
{
    extern __shared__ char sm[];
    const uint32_t sb = smem_u32(sm);

    const int tid  = threadIdx.x;
    const int lane = tid & 31;
    const int wid  = tid >> 5;
    const int wm   = wid >> 2;
    const int wn   = wid & 3;
    const int row0 = blockIdx.y * 128;
    const int nW0  = blockIdx.x * 128;

    __half* const houts[3]       = { c0h, c1h, c2h };
    const float* const biases[4] = { b0, b1, b2, b3 };
    const int    outIdx = blockIdx.x >> 1;
    const float* bias   = biases[outIdx];
    const int    colb   = (blockIdx.x & 1) * 128;

    const int lr  = tid >> 1;
    const int lcb = (tid & 1) * 16;
    const int grA  = row0 + lr;
    const int okA  = (grA < M) ? 16 : 0;
    const int arow = okA ? grA : 0;
    const size_t aoff = (size_t)arow * K + lcb;
    const size_t boff = (size_t)(nW0 + lr) * K + lcb;
    const char* pAh = (const char*)(Ahi + aoff);
    const char* pAl = (const char*)(Alo + aoff);
    const char* pBh = (const char*)(Whi + boff);
    const char* pBl = (const char*)(Wlo + boff);
    const uint32_t dstA = sb + (uint32_t)(lr * 80 + (tid & 1) * 32);

    const int nchunk = K >> 5;

    const int aRow    = lane & 15;
    const int aColSel = (lane >> 4) * 8;
    const int bRow    = lane & 7;
    const int bColSel = ((lane >> 3) & 1) * 8;

    float acc[4][4][4];
    #pragma unroll
    for (int i = 0; i < 4; i++)
        #pragma unroll
        for (int j = 0; j < 4; j++)
            #pragma unroll
            for (int t = 0; t < 4; t++) acc[i][j][t] = 0.f;

    {
        cpa16(dstA,               pAh,      okA);
        cpa16(dstA + 16,          pAh + 16, okA);
        cpa16(dstA + OFF_AL,      pAl,      okA);
        cpa16(dstA + OFF_AL + 16, pAl + 16, okA);
        cpa16(dstA + OFF_BH,      pBh,      16);
        cpa16(dstA + OFF_BH + 16, pBh + 16, 16);
        cpa16(dstA + OFF_BL,      pBl,      16);
        cpa16(dstA + OFF_BL + 16, pBl + 16, 16);
        CP_COMMIT();
    }

    for (int c = 0; c < nchunk; c++) {
        if (c + 1 < nchunk) {
            const uint32_t d = dstA + ((c + 1) & 1) * STG_B;
            const int go = (c + 1) * 64;
            cpa16(d,               pAh + go,      okA);
            cpa16(d + 16,          pAh + go + 16, okA);
            cpa16(d + OFF_AL,      pAl + go,      okA);
            cpa16(d + OFF_AL + 16, pAl + go + 16, okA);
            cpa16(d + OFF_BH,      pBh + go,      16);
            cpa16(d + OFF_BH + 16, pBh + go + 16, 16);
            cpa16(d + OFF_BL,      pBl + go,      16);
            cpa16(d + OFF_BL + 16, pBl + go + 16, 16);
            CP_COMMIT();
            CP_WAIT1();
        } else {
            CP_WAIT0();
        }
        __syncthreads();

        const uint32_t sbase = sb + (c & 1) * STG_B;
        #pragma unroll
        for (int ks = 0; ks < 2; ks++) {
            const int kb = ks * 16;
            uint32_t ah[4][4], al[4][4], bh[4][2], bl[4][2];
            #pragma unroll
            for (int mt = 0; mt < 4; mt++) {
                const uint32_t off = sbase +
                    (uint32_t)((wm * 64 + mt * 16 + aRow) * PAD + kb + aColSel) * 2;
                ldsm_x4(ah[mt], off);
                ldsm_x4(al[mt], off + OFF_AL);
            }
            #pragma unroll
            for (int nt = 0; nt < 4; nt++) {
                const uint32_t off = sbase + OFF_BH +
                    (uint32_t)((wn * 32 + nt * 8 + bRow) * PAD + kb + bColSel) * 2;
                ldsm_x2(bh[nt], off);
                ldsm_x2(bl[nt], off + (OFF_BL - OFF_BH));
            }
            #pragma unroll
            for (int mt = 0; mt < 4; mt++)
                #pragma unroll
                for (int nt = 0; nt < 4; nt++) {
                    mma_bf16(acc[mt][nt], ah[mt], bh[nt]);
                    mma_bf16(acc[mt][nt], ah[mt], bl[nt]);
                    mma_bf16(acc[mt][nt], al[mt], bh[nt]);
                }
        }
        __syncthreads();
    }

    if (outIdx < 3) {
        __half* Ch = houts[outIdx];
        #pragma unroll
        for (int mt = 0; mt < 4; mt++) {
            const int r = row0 + wm * 64 + mt * 16 + (lane >> 2);
            #pragma unroll
            for (int nt = 0; nt < 4; nt++) {
                const int c = colb + wn * 32 + nt * 8 + (lane & 3) * 2;
                if (r < M)
                    *(__half2*)(Ch + (size_t)r * 256 + c) =
                        __floats2half2_rn(acc[mt][nt][0] + bias[c],
                                          acc[mt][nt][1] + bias[c + 1]);
                if (r + 8 < M)
                    *(__half2*)(Ch + (size_t)(r + 8) * 256 + c) =
                        __floats2half2_rn(acc[mt][nt][2] + bias[c],
                                          acc[mt][nt][3] + bias[c + 1]);
            }
        }
    } else {
        #pragma unroll
        for (int mt = 0; mt < 4; mt++) {
            const int r = row0 + wm * 64 + mt * 16 + (lane >> 2);
            #pragma unroll
            for (int nt = 0; nt < 4; nt++) {
                const int c = colb + wn * 32 + nt * 8 + (lane & 3) * 2;
                if (r < M) {
                    float2 o = make_float2(acc[mt][nt][0] + bias[c],
                                           acc[mt][nt][1] + bias[c + 1]);
                    *(float2*)(c3f + (size_t)r * 256 + c) = o;
                }
                if (r + 8 < M) {
                    float2 o = make_float2(acc[mt][nt][2] + bias[c],
                                           acc[mt][nt][3] + bias[c + 1]);
                    *(float2*)(c3f + (size_t)(r + 8) * 256 + c) = o;
                }
            }
        }
    }
}

// ============ single-pass fp16 GEMM (edge projection) ============
// C[M,256] (fp16) = gather(A, rowmap)[M,K] @ W[256,K]^T + bias
#define STG_F 20480
#define OFF_FB 10240
#define GEMMF_SMEM (2 * STG_F)

__global__ __launch_bounds__(256, 2) void gemm_f16(
    int M, int K,
    const __half* __restrict__ A, const __half* __restrict__ W,
    const int* __restrict__ rowmap,
    __half* __restrict__ C, const float* __restrict__ bias)
{
    extern __shared__ char sm[];
    const uint32_t sb = smem_u32(sm);

    const int tid  = threadIdx.x;
    const int lane = tid & 31;
    const int wid  = tid >> 5;
    const int wm   = wid >> 2;
    const int wn   = wid & 3;
    const int row0 = blockIdx.y * 128;
    const int colb = blockIdx.x * 128;

    const int lr  = tid >> 1;
    const int lcb = (tid & 1) * 16;
    const int grA = row0 + lr;
    const int okA = (grA < M) ? 16 : 0;
    int arow = okA ? grA : 0;
    if (rowmap) arow = rowmap[arow];
    const char* pA = (const char*)(A + (size_t)arow * K + lcb);
    const char* pB = (const char*)(W + (size_t)(colb + lr) * K + lcb);
    const uint32_t dstA = sb + (uint32_t)(lr * 80 + (tid & 1) * 32);

    const int nchunk = K >> 5;

    const int aRow    = lane & 15;
    const int aColSel = (lane >> 4) * 8;
    const int bRow    = lane & 7;
    const int bColSel = ((lane >> 3) & 1) * 8;

    float acc[4][4][4];
    #pragma unroll
    for (int i = 0; i < 4; i++)
        #pragma unroll
        for (int j = 0; j < 4; j++)
            #pragma unroll
            for (int t = 0; t < 4; t++) acc[i][j][t] = 0.f;

    {
        cpa16(dstA,                pA,      okA);
        cpa16(dstA + 16,           pA + 16, okA);
        cpa16(dstA + OFF_FB,       pB,      16);
        cpa16(dstA + OFF_FB + 16,  pB + 16, 16);
        CP_COMMIT();
    }

    for (int c = 0; c < nchunk; c++) {
        if (c + 1 < nchunk) {
            const uint32_t d = dstA + ((c + 1) & 1) * STG_F;
            const int go = (c + 1) * 64;
            cpa16(d,               pA + go,      okA);
            cpa16(d + 16,          pA + go + 16, okA);
            cpa16(d + OFF_FB,      pB + go,      16);
            cpa16(d + OFF_FB + 16, pB + go + 16, 16);
            CP_COMMIT();
            CP_WAIT1();
        } else {
            CP_WAIT0();
        }
        __syncthreads();

        const uint32_t sbase = sb + (c & 1) * STG_F;
        #pragma unroll
        for (int ks = 0; ks < 2; ks++) {
            const int kb = ks * 16;
            uint32_t ah[4][4], bh[4][2];
            #pragma unroll
            for (int mt = 0; mt < 4; mt++) {
                const uint32_t off = sbase +
                    (uint32_t)((wm * 64 + mt * 16 + aRow) * PAD + kb + aColSel) * 2;
                ldsm_x4(ah[mt], off);
            }
            #pragma unroll
            for (int nt = 0; nt < 4; nt++) {
                const uint32_t off = sbase + OFF_FB +
                    (uint32_t)((wn * 32 + nt * 8 + bRow) * PAD + kb + bColSel) * 2;
                ldsm_x2(bh[nt], off);
            }
            #pragma unroll
            for (int mt = 0; mt < 4; mt++)
                #pragma unroll
                for (int nt = 0; nt < 4; nt++)
                    mma_f16(acc[mt][nt], ah[mt], bh[nt]);
        }
        __syncthreads();
    }

    #pragma unroll
    for (int mt = 0; mt < 4; mt++) {
        const int r = row0 + wm * 64 + mt * 16 + (lane >> 2);
        #pragma unroll
        for (int nt = 0; nt < 4; nt++) {
            const int c = colb + wn * 32 + nt * 8 + (lane & 3) * 2;
            if (r < M)
                *(__half2*)(C + (size_t)r * 256 + c) =
                    __floats2half2_rn(acc[mt][nt][0] + bias[c],
                                      acc[mt][nt][1] + bias[c + 1]);
            if (r + 8 < M)
                *(__half2*)(C + (size_t)(r + 8) * 256 + c) =
                    __floats2half2_rn(acc[mt][nt][2] + bias[c],
                                      acc[mt][nt][3] + bias[c + 1]);
        }
    }
}

// ======== weight prep ========
__global__ void tsplit_w(const float* __restrict__ W,
                         bf16* __restrict__ hi, bf16* __restrict__ lo, int K)
{
    const int i = blockIdx.x * blockDim.x + threadIdx.x;
    if (i < K * 256) {
        const int k = i >> 8, n = i & 255;
        const float v = W[i];
        const bf16 h = __float2bfloat16(v);
        hi[(size_t)n * K + k] = h;
        lo[(size_t)n * K + k] = __float2bfloat16(v - __bfloat162float(h));
    }
}
__global__ void tsplit_w16(const float* __restrict__ W, __half* __restrict__ wt, int K)
{
    const int i = blockIdx.x * blockDim.x + threadIdx.x;
    if (i < K * 256) {
        const int k = i >> 8, n = i & 255;
        wt[(size_t)n * K + k] = __float2half(W[i]);
    }
}

__global__ void split_bf(const float* __restrict__ in,
                         bf16* __restrict__ hi, bf16* __restrict__ lo, size_t n4)
{
    const size_t i = (size_t)blockIdx.x * blockDim.x + threadIdx.x;
    if (i >= n4) return;
    float4 v = ((const float4*)in)[i];
    __nv_bfloat162 h0 = __floats2bfloat162_rn(v.x, v.y);
    __nv_bfloat162 h1 = __floats2bfloat162_rn(v.z, v.w);
    __nv_bfloat162 l0 = __floats2bfloat162_rn(v.x - __low2float(h0), v.y - __high2float(h0));
    __nv_bfloat162 l1 = __floats2bfloat162_rn(v.z - __low2float(h1), v.w - __high2float(h1));
    ((__nv_bfloat162*)hi)[2 * i]     = h0;
    ((__nv_bfloat162*)hi)[2 * i + 1] = h1;
    ((__nv_bfloat162*)lo)[2 * i]     = l0;
    ((__nv_bfloat162*)lo)[2 * i + 1] = l1;
}

__global__ void cvt_f16(const float* __restrict__ in, __half* __restrict__ o, size_t n4)
{
    const size_t i = (size_t)blockIdx.x * blockDim.x + threadIdx.x;
    if (i >= n4) return;
    float4 v = ((const float4*)in)[i];
    ((__half2*)o)[2 * i]     = __floats2half2_rn(v.x, v.y);
    ((__half2*)o)[2 * i + 1] = __floats2half2_rn(v.z, v.w);
}

__global__ void relu_split(const float* __restrict__ in,
                           bf16* __restrict__ hi, bf16* __restrict__ lo, size_t n4)
{
    const size_t i = (size_t)blockIdx.x * blockDim.x + threadIdx.x;
    if (i >= n4) return;
    float4 v = ((const float4*)in)[i];
    v.x = fmaxf(v.x, 0.f); v.y = fmaxf(v.y, 0.f);
    v.z = fmaxf(v.z, 0.f); v.w = fmaxf(v.w, 0.f);
    __nv_bfloat162 h0 = __floats2bfloat162_rn(v.x, v.y);
    __nv_bfloat162 h1 = __floats2bfloat162_rn(v.z, v.w);
    __nv_bfloat162 l0 = __floats2bfloat162_rn(v.x - __low2float(h0), v.y - __high2float(h0));
    __nv_bfloat162 l1 = __floats2bfloat162_rn(v.z - __low2float(h1), v.w - __high2float(h1));
    ((__nv_bfloat162*)hi)[2 * i]     = h0;
    ((__nv_bfloat162*)hi)[2 * i + 1] = h1;
    ((__nv_bfloat162*)lo)[2 * i]     = l0;
    ((__nv_bfloat162*)lo)[2 * i + 1] = l1;
}

// ================= CSR build =================
__global__ void csr_zero()
{
    const int i = blockIdx.x * blockDim.x + threadIdx.x;
    if (i < Nn) { g_deg[i] = 0; g_cursor[i] = 0; }
}
__global__ void csr_count(const int* __restrict__ ei)
{
    const int i = blockIdx.x * blockDim.x + threadIdx.x;
    if (i < Ee) atomicAdd(&g_deg[ei[Ee + i]], 1);
}
__global__ void csr_scan_local()
{
    __shared__ int s[256];
    const int tid = threadIdx.x;
    const int i = blockIdx.x * 256 + tid;
    const int v = (i < Nn) ? g_deg[i] : 0;
    s[tid] = v; __syncthreads();
    for (int off = 1; off < 256; off <<= 1) {
        const int t = (tid >= off) ? s[tid - off] : 0;
        __syncthreads();
        s[tid] += t;
        __syncthreads();
    }
    if (i < Nn) g_loc[i] = s[tid] - v;
    if (tid == 255) g_bsum[blockIdx.x] = s[255];
}
__global__ void csr_scan_bsum(int nb)
{
    __shared__ int s[256];
    const int t = threadIdx.x;
    const int v = (t < nb) ? g_bsum[t] : 0;
    s[t] = v; __syncthreads();
    for (int off = 1; off < 256; off <<= 1) {
        const int u = (t >= off) ? s[t - off] : 0;
        __syncthreads();
        s[t] += u;
        __syncthreads();
    }
    if (t < nb) g_bsum[t] = s[t] - v;
}
__global__ void csr_finalize()
{
    const int i = blockIdx.x * blockDim.x + threadIdx.x;
    if (i < Nn) g_rowptr[i] = g_loc[i] + g_bsum[i >> 8];
    if (i == 0) g_rowptr[Nn] = Ee;
}
__global__ void csr_fill(const int* __restrict__ ei)
{
    const int eid = blockIdx.x * blockDim.x + threadIdx.x;
    if (eid < Ee) {
        const int src = ei[eid];
        const int dst = ei[Ee + eid];
        const int p = atomicAdd(&g_cursor[dst], 1);
        const int pos = g_rowptr[dst] + p;
        g_adj[pos]  = eid;
        g_srcp[pos] = src;
    }
}

// ================= flash-style segment softmax + aggregate (fp16 in) ======
__global__ __launch_bounds__(256) void flash_agg(
    const __half* __restrict__ q, const __half* __restrict__ k,
    const __half* __restrict__ v, const __half* __restrict__ e,
    float* __restrict__ out)
{
    const int warp = (blockIdx.x * blockDim.x + threadIdx.x) >> 5;
    const int lane = threadIdx.x & 31;
    if (warp >= Nn) return;
    const int beg = g_rowptr[warp];
    const int end = g_rowptr[warp + 1];
    if (beg == end) return;

    const int co = lane * 8;
    float qf[8];
    { uint4 u = *(const uint4*)(q + (size_t)warp * DD + co); cvt8(qf, u); }

    float m = -CUDART_INF_F, d = 0.f;
    float a[8];
    #pragma unroll
    for (int i = 0; i < 8; i++) a[i] = 0.f;

    for (int idx = beg; idx < end; idx++) {
        const int src = g_srcp[idx];
        float ef[8], kf[8], vf[8];
        { uint4 u = *(const uint4*)(e + (size_t)idx * DD + co); cvt8(ef, u); }
        { uint4 u = *(const uint4*)(k + (size_t)src * DD + co); cvt8(kf, u); }
        { uint4 u = *(const uint4*)(v + (size_t)src * DD + co); cvt8(vf, u); }

        float dot = 0.f;
        #pragma unroll
        for (int i = 0; i < 8; i++) dot += qf[i] * (kf[i] + ef[i]);
        dot += __shfl_xor_sync(0xffffffffu, dot, 1);
        dot += __shfl_xor_sync(0xffffffffu, dot, 2);
        dot += __shfl_xor_sync(0xffffffffu, dot, 4);
        const float al = dot * 0.125f;

        const float mn = fmaxf(m, al);
        const float sc = __expf(m - mn);
        const float w  = __expf(al - mn);
        d = d * sc + w;
        #pragma unroll
        for (int i = 0; i < 8; i++) a[i] = a[i] * sc + (vf[i] + ef[i]) * w;
        m = mn;
    }

    const float inv = 1.f / (d + 1e-16f);
    float* op = out + (size_t)warp * DD + co;
    float4 o0 = *(float4*)op, o1 = *(float4*)(op + 4);
    o0.x += a[0] * inv; o0.y += a[1] * inv;
    o0.z += a[2] * inv; o0.w += a[3] * inv;
    o1.x += a[4] * inv; o1.y += a[5] * inv;
    o1.z += a[6] * inv; o1.w += a[7] * inv;
    *(float4*)op       = o0;
    *(float4*)(op + 4) = o1;
}

// ================= host driver =================
static void* symaddr(const void* sym)
{
    void* p = nullptr;
    cudaGetSymbolAddress(&p, sym);
    return p;
}

extern "C" void kernel_launch(void* const* d_in, const int* in_sizes, int n_in,
                              void* d_out, int out_size)
{
    const float* x  = (const float*)d_in[0];
    const int*   ei = (const int*)d_in[1];
    const float* ea = (const float*)d_in[2];
    const float* W1[5] = { (const float*)d_in[3],  (const float*)d_in[5],
                           (const float*)d_in[7],  (const float*)d_in[9],
                           (const float*)d_in[11] };
    const float* b1[5] = { (const float*)d_in[4],  (const float*)d_in[6],
                           (const float*)d_in[8],  (const float*)d_in[10],
                           (const float*)d_in[12] };
    const float* W2[5] = { (const float*)d_in[13], (const float*)d_in[15],
                           (const float*)d_in[17], (const float*)d_in[19],
                           (const float*)d_in[21] };
    const float* b2[5] = { (const float*)d_in[14], (const float*)d_in[16],
                           (const float*)d_in[18], (const float*)d_in[20],
                           (const float*)d_in[22] };

    static __half *q = nullptr, *k, *v, *e1, *e2, *eaf, *wef;
    static float *h;
    static bf16 *xhi, *xlo, *whi, *wlo;
    static int *adj;
    static cudaStream_t sB;
    static cudaEvent_t evRoot, evCSR, evE1, evE2;
    if (!q) {
        q  = (__half*)symaddr(g_q);  k  = (__half*)symaddr(g_k);
        v  = (__half*)symaddr(g_v);  h  = (float*)symaddr(g_h);
        e1 = (__half*)symaddr(g_e1); e2 = (__half*)symaddr(g_e2);
        eaf = (__half*)symaddr(g_eaf16); wef = (__half*)symaddr(g_wef16);
        xhi = (bf16*)symaddr(g_xhi); xlo = (bf16*)symaddr(g_xlo);
        whi = (bf16*)symaddr(g_whi); wlo = (bf16*)symaddr(g_wlo);
        adj = (int*)symaddr(g_adj);
        cudaFuncSetAttribute(gemm_bf3,
            cudaFuncAttributeMaxDynamicSharedMemorySize, GEMM_SMEM);
        cudaFuncSetAttribute(gemm_f16,
            cudaFuncAttributeMaxDynamicSharedMemorySize, GEMMF_SMEM);
        cudaStreamCreateWithFlags(&sB, cudaStreamNonBlocking);
        cudaEventCreateWithFlags(&evRoot, cudaEventDisableTiming);
        cudaEventCreateWithFlags(&evCSR,  cudaEventDisableTiming);
        cudaEventCreateWithFlags(&evE1,   cudaEventDisableTiming);
        cudaEventCreateWithFlags(&evE2,   cudaEventDisableTiming);
    }
    float* out = (float*)d_out;

    const dim3 gQKVS(8, (Nn + 127) / 128);
    const dim3 gEdge(2, Ee / 128);
    const int  bFlash = (Nn * 32 + 255) / 256;
    const int  bSplit = (Nn * DD / 4 + 255) / 256;
    const int  NB = (Nn + 255) / 256;

    // ================= fork =================
    cudaEventRecord(evRoot, 0);
    cudaStreamWaitEvent(sB, evRoot, 0);

    // sB: edge-side prep (fp16)
    tsplit_w16<<<128, 256, 0, sB>>>(W1[3], wef, 128);
    tsplit_w16<<<128, 256, 0, sB>>>(W2[3], wef + 32768, 128);
    cvt_f16<<<(int)(((size_t)Ee * EDD / 4 + 255) / 256), 256, 0, sB>>>(
        ea, eaf, (size_t)Ee * EDD / 4);

    // main: node-side prep + CSR
    const float* qkvs1[4] = { W1[0], W1[1], W1[2], W1[4] };
    const float* qkvs2[4] = { W2[0], W2[1], W2[2], W2[4] };
    for (int s = 0; s < 4; s++) {
        tsplit_w<<<256, 256>>>(qkvs1[s], whi + WOFF_QKVS1 + (size_t)s * 65536,
                                         wlo + WOFF_QKVS1 + (size_t)s * 65536, 256);
        tsplit_w<<<256, 256>>>(qkvs2[s], whi + WOFF_QKVS2 + (size_t)s * 65536,
                                         wlo + WOFF_QKVS2 + (size_t)s * 65536, 256);
    }
    split_bf<<<bSplit, 256>>>(x, xhi, xlo, (size_t)Nn * DD / 4);

    csr_zero<<<NB, 256>>>();
    csr_count<<<(Ee + 255) / 256, 256>>>(ei);
    csr_scan_local<<<NB, 256>>>();
    csr_scan_bsum<<<1, 256>>>(NB);
    csr_finalize<<<NB, 256>>>();
    csr_fill<<<(Ee + 255) / 256, 256>>>(ei);
    cudaEventRecord(evCSR, 0);

    // sB: dst-sorted fp16 edge GEMMs
    cudaStreamWaitEvent(sB, evCSR, 0);
    gemm_f16<<<gEdge, 256, GEMMF_SMEM, sB>>>(Ee, 128, eaf, wef, adj, e1, b1[3]);
    cudaEventRecord(evE1, sB);
    gemm_f16<<<gEdge, 256, GEMMF_SMEM, sB>>>(Ee, 128, eaf, wef + 32768, adj, e2, b2[3]);
    cudaEventRecord(evE2, sB);

    // main: layer 1 node QKVS (q/k/v fp16, skip fp32 -> h)
    gemm_bf3<<<gQKVS, 256, GEMM_SMEM>>>(Nn, 256, xhi, xlo,
        whi + WOFF_QKVS1, wlo + WOFF_QKVS1,
        q, k, v, h, b1[0], b1[1], b1[2], b1[4]);

    cudaStreamWaitEvent(0, evE1, 0);
    flash_agg<<<bFlash, 256>>>(q, k, v, e1, h);
    relu_split<<<bSplit, 256>>>(h, xhi, xlo, (size_t)Nn * DD / 4);

    // main: layer 2 node QKVS (skip -> out)
    gemm_bf3<<<gQKVS, 256, GEMM_SMEM>>>(Nn, 256, xhi, xlo,
        whi + WOFF_QKVS2, wlo + WOFF_QKVS2,
        q, k, v, out, b2[0], b2[1], b2[2], b2[4]);

    cudaStreamWaitEvent(0, evE2, 0);
    flash_agg<<<bFlash, 256>>>(q, k, v, e2, out);
}

// round 10
// speedup vs baseline: 4.3379x; 1.0916x over previous
#include <cuda_runtime.h>
#include <cuda_bf16.h>
#include <cuda_fp16.h>
#include <math.h>
#include <math_constants.h>
#include <cstdint>

#define Nn   50000
#define Ee   800000
#define DD   256
#define EDD  128
#define Hh   4

typedef __nv_bfloat16 bf16;

// ================= scratch (device globals) =================
__device__ __half g_q[Nn * DD];
__device__ __half g_k[Nn * DD];
__device__ __half g_v[Nn * DD];
__device__ float  g_h[Nn * DD];
__device__ __half g_e1[(size_t)Ee * DD];   // layer-1 edge projections (dst-sorted)
__device__ __half g_e2[(size_t)Ee * DD];   // layer-2 edge projections (dst-sorted)
// CSR for dst-grouped edges
__device__ int g_deg[Nn];
__device__ int g_cursor[Nn];
__device__ int g_loc[Nn];
__device__ int g_bsum[256];
__device__ int g_rowptr[Nn + 1];
__device__ int g_adj[Ee];
__device__ int g_srcp[Ee];
// operands
__device__ bf16 g_xhi[Nn * DD], g_xlo[Nn * DD];      // bf16 split (for S GEMM)
__device__ __half g_xf16[Nn * DD];                   // fp16 (for QKV GEMM)
__device__ __half g_eaf16[(size_t)Ee * EDD];
__device__ bf16 g_whi[2 * 65536], g_wlo[2 * 65536];  // Ws only, bf16 split
__device__ __half g_wqkv16[2 * 768 * 256];           // fused QKV fp16 K-major
__device__ __half g_wef16[2 * 256 * 128];            // edge weights fp16 K-major

// ================= PTX helpers =================
__device__ __forceinline__ uint32_t smem_u32(const void* p) {
    uint32_t a;
    asm("{ .reg .u64 t; cvta.to.shared.u64 t, %1; cvt.u32.u64 %0, t; }"
        : "=r"(a) : "l"(p));
    return a;
}
__device__ __forceinline__ void ldsm_x4(uint32_t* r, uint32_t a) {
    asm volatile("ldmatrix.sync.aligned.m8n8.x4.shared.b16 {%0,%1,%2,%3}, [%4];"
        : "=r"(r[0]), "=r"(r[1]), "=r"(r[2]), "=r"(r[3]) : "r"(a));
}
__device__ __forceinline__ void ldsm_x2(uint32_t* r, uint32_t a) {
    asm volatile("ldmatrix.sync.aligned.m8n8.x2.shared.b16 {%0,%1}, [%2];"
        : "=r"(r[0]), "=r"(r[1]) : "r"(a));
}
__device__ __forceinline__ void mma_bf16(float* d, const uint32_t* a, const uint32_t* b) {
    asm volatile("mma.sync.aligned.m16n8k16.row.col.f32.bf16.bf16.f32 "
        "{%0,%1,%2,%3}, {%4,%5,%6,%7}, {%8,%9}, {%0,%1,%2,%3};"
        : "+f"(d[0]), "+f"(d[1]), "+f"(d[2]), "+f"(d[3])
        : "r"(a[0]), "r"(a[1]), "r"(a[2]), "r"(a[3]), "r"(b[0]), "r"(b[1]));
}
__device__ __forceinline__ void mma_f16(float* d, const uint32_t* a, const uint32_t* b) {
    asm volatile("mma.sync.aligned.m16n8k16.row.col.f32.f16.f16.f32 "
        "{%0,%1,%2,%3}, {%4,%5,%6,%7}, {%8,%9}, {%0,%1,%2,%3};"
        : "+f"(d[0]), "+f"(d[1]), "+f"(d[2]), "+f"(d[3])
        : "r"(a[0]), "r"(a[1]), "r"(a[2]), "r"(a[3]), "r"(b[0]), "r"(b[1]));
}
__device__ __forceinline__ void cpa16(uint32_t dst, const void* src, int sz) {
    asm volatile("cp.async.cg.shared.global [%0], [%1], 16, %2;"
        :: "r"(dst), "l"(src), "r"(sz) : "memory");
}
#define CP_COMMIT() asm volatile("cp.async.commit_group;" ::: "memory")
#define CP_WAIT1()  asm volatile("cp.async.wait_group 1;" ::: "memory")
#define CP_WAIT0()  asm volatile("cp.async.wait_group 0;" ::: "memory")

__device__ __forceinline__ void cvt8(float* f, uint4 u) {
    const __half2* h = (const __half2*)&u;
    float2 t;
    t = __half22float2(h[0]); f[0] = t.x; f[1] = t.y;
    t = __half22float2(h[1]); f[2] = t.x; f[3] = t.y;
    t = __half22float2(h[2]); f[4] = t.x; f[5] = t.y;
    t = __half22float2(h[3]); f[6] = t.x; f[7] = t.y;
}

// ================= bf16x3 pipelined GEMM (skip path S only) =============
#define PAD 40
#define STG_B 40960
#define OFF_AL 10240
#define OFF_BH 20480
#define OFF_BL 30720
#define GEMM_SMEM (2 * STG_B)

__global__ __launch_bounds__(256, 2) void gemm_bf3(
    int M, int K,
    const bf16* __restrict__ Ahi, const bf16* __restrict__ Alo,
    const bf16* __restrict__ Whi, const bf16* __restrict__ Wlo,
    float* __restrict__ Cf, const float* __restrict__ bias)
{
    extern __shared__ char sm[];
    const uint32_t sb = smem_u32(sm);

    const int tid  = threadIdx.x;
    const int lane = tid & 31;
    const int wid  = tid >> 5;
    const int wm   = wid >> 2;
    const int wn   = wid & 3;
    const int row0 = blockIdx.y * 128;
    const int nW0  = blockIdx.x * 128;
    const int colb = blockIdx.x * 128;

    const int lr  = tid >> 1;
    const int lcb = (tid & 1) * 16;
    const int grA  = row0 + lr;
    const int okA  = (grA < M) ? 16 : 0;
    const int arow = okA ? grA : 0;
    const size_t aoff = (size_t)arow * K + lcb;
    const size_t boff = (size_t)(nW0 + lr) * K + lcb;
    const char* pAh = (const char*)(Ahi + aoff);
    const char* pAl = (const char*)(Alo + aoff);
    const char* pBh = (const char*)(Whi + boff);
    const char* pBl = (const char*)(Wlo + boff);
    const uint32_t dstA = sb + (uint32_t)(lr * 80 + (tid & 1) * 32);

    const int nchunk = K >> 5;

    const int aRow    = lane & 15;
    const int aColSel = (lane >> 4) * 8;
    const int bRow    = lane & 7;
    const int bColSel = ((lane >> 3) & 1) * 8;

    float acc[4][4][4];
    #pragma unroll
    for (int i = 0; i < 4; i++)
        #pragma unroll
        for (int j = 0; j < 4; j++)
            #pragma unroll
            for (int t = 0; t < 4; t++) acc[i][j][t] = 0.f;

    {
        cpa16(dstA,               pAh,      okA);
        cpa16(dstA + 16,          pAh + 16, okA);
        cpa16(dstA + OFF_AL,      pAl,      okA);
        cpa16(dstA + OFF_AL + 16, pAl + 16, okA);
        cpa16(dstA + OFF_BH,      pBh,      16);
        cpa16(dstA + OFF_BH + 16, pBh + 16, 16);
        cpa16(dstA + OFF_BL,      pBl,      16);
        cpa16(dstA + OFF_BL + 16, pBl + 16, 16);
        CP_COMMIT();
    }

    for (int c = 0; c < nchunk; c++) {
        if (c + 1 < nchunk) {
            const uint32_t d = dstA + ((c + 1) & 1) * STG_B;
            const int go = (c + 1) * 64;
            cpa16(d,               pAh + go,      okA);
            cpa16(d + 16,          pAh + go + 16, okA);
            cpa16(d + OFF_AL,      pAl + go,      okA);
            cpa16(d + OFF_AL + 16, pAl + go + 16, okA);
            cpa16(d + OFF_BH,      pBh + go,      16);
            cpa16(d + OFF_BH + 16, pBh + go + 16, 16);
            cpa16(d + OFF_BL,      pBl + go,      16);
            cpa16(d + OFF_BL + 16, pBl + go + 16, 16);
            CP_COMMIT();
            CP_WAIT1();
        } else {
            CP_WAIT0();
        }
        __syncthreads();

        const uint32_t sbase = sb + (c & 1) * STG_B;
        #pragma unroll
        for (int ks = 0; ks < 2; ks++) {
            const int kb = ks * 16;
            uint32_t ah[4][4], al[4][4], bh[4][2], bl[4][2];
            #pragma unroll
            for (int mt = 0; mt < 4; mt++) {
                const uint32_t off = sbase +
                    (uint32_t)((wm * 64 + mt * 16 + aRow) * PAD + kb + aColSel) * 2;
                ldsm_x4(ah[mt], off);
                ldsm_x4(al[mt], off + OFF_AL);
            }
            #pragma unroll
            for (int nt = 0; nt < 4; nt++) {
                const uint32_t off = sbase + OFF_BH +
                    (uint32_t)((wn * 32 + nt * 8 + bRow) * PAD + kb + bColSel) * 2;
                ldsm_x2(bh[nt], off);
                ldsm_x2(bl[nt], off + (OFF_BL - OFF_BH));
            }
            #pragma unroll
            for (int mt = 0; mt < 4; mt++)
                #pragma unroll
                for (int nt = 0; nt < 4; nt++) {
                    mma_bf16(acc[mt][nt], ah[mt], bh[nt]);
                    mma_bf16(acc[mt][nt], ah[mt], bl[nt]);
                    mma_bf16(acc[mt][nt], al[mt], bh[nt]);
                }
        }
        __syncthreads();
    }

    #pragma unroll
    for (int mt = 0; mt < 4; mt++) {
        const int r = row0 + wm * 64 + mt * 16 + (lane >> 2);
        #pragma unroll
        for (int nt = 0; nt < 4; nt++) {
            const int c = colb + wn * 32 + nt * 8 + (lane & 3) * 2;
            if (r < M) {
                float2 o = make_float2(acc[mt][nt][0] + bias[c],
                                       acc[mt][nt][1] + bias[c + 1]);
                *(float2*)(Cf + (size_t)r * 256 + c) = o;
            }
            if (r + 8 < M) {
                float2 o = make_float2(acc[mt][nt][2] + bias[c],
                                       acc[mt][nt][3] + bias[c + 1]);
                *(float2*)(Cf + (size_t)(r + 8) * 256 + c) = o;
            }
        }
    }
}

// ============ single-pass fp16 GEMM, up to 3 routed fp16 outputs ============
// output i uses weight block W + i*256*K and bias bi; grid.x = 2*numOutputs
#define STG_F 20480
#define OFF_FB 10240
#define GEMMF_SMEM (2 * STG_F)

__global__ __launch_bounds__(256, 2) void gemm_f16(
    int M, int K,
    const __half* __restrict__ A, const __half* __restrict__ W,
    const int* __restrict__ rowmap,
    __half* c0, __half* c1, __half* c2,
    const float* b0, const float* b1, const float* b2)
{
    extern __shared__ char sm[];
    const uint32_t sb = smem_u32(sm);

    const int tid  = threadIdx.x;
    const int lane = tid & 31;
    const int wid  = tid >> 5;
    const int wm   = wid >> 2;
    const int wn   = wid & 3;
    const int row0 = blockIdx.y * 128;

    __half* const outs[3]        = { c0, c1, c2 };
    const float* const biases[3] = { b0, b1, b2 };
    const int    outIdx = blockIdx.x >> 1;
    __half*      C    = outs[outIdx];
    const float* bias = biases[outIdx];
    const int    colb = (blockIdx.x & 1) * 128;
    const int    nW0  = outIdx * 256 + colb;

    const int lr  = tid >> 1;
    const int lcb = (tid & 1) * 16;
    const int grA = row0 + lr;
    const int okA = (grA < M) ? 16 : 0;
    int arow = okA ? grA : 0;
    if (rowmap) arow = rowmap[arow];
    const char* pA = (const char*)(A + (size_t)arow * K + lcb);
    const char* pB = (const char*)(W + (size_t)(nW0 + lr) * K + lcb);
    const uint32_t dstA = sb + (uint32_t)(lr * 80 + (tid & 1) * 32);

    const int nchunk = K >> 5;

    const int aRow    = lane & 15;
    const int aColSel = (lane >> 4) * 8;
    const int bRow    = lane & 7;
    const int bColSel = ((lane >> 3) & 1) * 8;

    float acc[4][4][4];
    #pragma unroll
    for (int i = 0; i < 4; i++)
        #pragma unroll
        for (int j = 0; j < 4; j++)
            #pragma unroll
            for (int t = 0; t < 4; t++) acc[i][j][t] = 0.f;

    {
        cpa16(dstA,                pA,      okA);
        cpa16(dstA + 16,           pA + 16, okA);
        cpa16(dstA + OFF_FB,       pB,      16);
        cpa16(dstA + OFF_FB + 16,  pB + 16, 16);
        CP_COMMIT();
    }

    for (int c = 0; c < nchunk; c++) {
        if (c + 1 < nchunk) {
            const uint32_t d = dstA + ((c + 1) & 1) * STG_F;
            const int go = (c + 1) * 64;
            cpa16(d,               pA + go,      okA);
            cpa16(d + 16,          pA + go + 16, okA);
            cpa16(d + OFF_FB,      pB + go,      16);
            cpa16(d + OFF_FB + 16, pB + go + 16, 16);
            CP_COMMIT();
            CP_WAIT1();
        } else {
            CP_WAIT0();
        }
        __syncthreads();

        const uint32_t sbase = sb + (c & 1) * STG_F;
        #pragma unroll
        for (int ks = 0; ks < 2; ks++) {
            const int kb = ks * 16;
            uint32_t ah[4][4], bh[4][2];
            #pragma unroll
            for (int mt = 0; mt < 4; mt++) {
                const uint32_t off = sbase +
                    (uint32_t)((wm * 64 + mt * 16 + aRow) * PAD + kb + aColSel) * 2;
                ldsm_x4(ah[mt], off);
            }
            #pragma unroll
            for (int nt = 0; nt < 4; nt++) {
                const uint32_t off = sbase + OFF_FB +
                    (uint32_t)((wn * 32 + nt * 8 + bRow) * PAD + kb + bColSel) * 2;
                ldsm_x2(bh[nt], off);
            }
            #pragma unroll
            for (int mt = 0; mt < 4; mt++)
                #pragma unroll
                for (int nt = 0; nt < 4; nt++)
                    mma_f16(acc[mt][nt], ah[mt], bh[nt]);
        }
        __syncthreads();
    }

    #pragma unroll
    for (int mt = 0; mt < 4; mt++) {
        const int r = row0 + wm * 64 + mt * 16 + (lane >> 2);
        #pragma unroll
        for (int nt = 0; nt < 4; nt++) {
            const int c = colb + wn * 32 + nt * 8 + (lane & 3) * 2;
            if (r < M)
                *(__half2*)(C + (size_t)r * 256 + c) =
                    __floats2half2_rn(acc[mt][nt][0] + bias[c],
                                      acc[mt][nt][1] + bias[c + 1]);
            if (r + 8 < M)
                *(__half2*)(C + (size_t)(r + 8) * 256 + c) =
                    __floats2half2_rn(acc[mt][nt][2] + bias[c],
                                      acc[mt][nt][3] + bias[c + 1]);
        }
    }
}

// ======== weight prep ========
__global__ void tsplit_w(const float* __restrict__ W,
                         bf16* __restrict__ hi, bf16* __restrict__ lo, int K)
{
    const int i = blockIdx.x * blockDim.x + threadIdx.x;
    if (i < K * 256) {
        const int k = i >> 8, n = i & 255;
        const float v = W[i];
        const bf16 h = __float2bfloat16(v);
        hi[(size_t)n * K + k] = h;
        lo[(size_t)n * K + k] = __float2bfloat16(v - __bfloat162float(h));
    }
}
__global__ void tsplit_w16(const float* __restrict__ W, __half* __restrict__ wt, int K)
{
    const int i = blockIdx.x * blockDim.x + threadIdx.x;
    if (i < K * 256) {
        const int k = i >> 8, n = i & 255;
        wt[(size_t)n * K + k] = __float2half(W[i]);
    }
}

// fp32 -> bf16 hi/lo + fp16, optional relu
template <int RELU>
__global__ void split_all(const float* __restrict__ in,
                          bf16* __restrict__ hi, bf16* __restrict__ lo,
                          __half* __restrict__ f16, size_t n4)
{
    const size_t i = (size_t)blockIdx.x * blockDim.x + threadIdx.x;
    if (i >= n4) return;
    float4 v = ((const float4*)in)[i];
    if (RELU) {
        v.x = fmaxf(v.x, 0.f); v.y = fmaxf(v.y, 0.f);
        v.z = fmaxf(v.z, 0.f); v.w = fmaxf(v.w, 0.f);
    }
    __nv_bfloat162 h0 = __floats2bfloat162_rn(v.x, v.y);
    __nv_bfloat162 h1 = __floats2bfloat162_rn(v.z, v.w);
    __nv_bfloat162 l0 = __floats2bfloat162_rn(v.x - __low2float(h0), v.y - __high2float(h0));
    __nv_bfloat162 l1 = __floats2bfloat162_rn(v.z - __low2float(h1), v.w - __high2float(h1));
    ((__nv_bfloat162*)hi)[2 * i]     = h0;
    ((__nv_bfloat162*)hi)[2 * i + 1] = h1;
    ((__nv_bfloat162*)lo)[2 * i]     = l0;
    ((__nv_bfloat162*)lo)[2 * i + 1] = l1;
    ((__half2*)f16)[2 * i]     = __floats2half2_rn(v.x, v.y);
    ((__half2*)f16)[2 * i + 1] = __floats2half2_rn(v.z, v.w);
}

__global__ void cvt_f16(const float* __restrict__ in, __half* __restrict__ o, size_t n4)
{
    const size_t i = (size_t)blockIdx.x * blockDim.x + threadIdx.x;
    if (i >= n4) return;
    float4 v = ((const float4*)in)[i];
    ((__half2*)o)[2 * i]     = __floats2half2_rn(v.x, v.y);
    ((__half2*)o)[2 * i + 1] = __floats2half2_rn(v.z, v.w);
}

// ================= CSR build =================
__global__ void csr_zero()
{
    const int i = blockIdx.x * blockDim.x + threadIdx.x;
    if (i < Nn) { g_deg[i] = 0; g_cursor[i] = 0; }
}
__global__ void csr_count(const int* __restrict__ ei)
{
    const int i = blockIdx.x * blockDim.x + threadIdx.x;
    if (i < Ee) atomicAdd(&g_deg[ei[Ee + i]], 1);
}
__global__ void csr_scan_local()
{
    __shared__ int s[256];
    const int tid = threadIdx.x;
    const int i = blockIdx.x * 256 + tid;
    const int v = (i < Nn) ? g_deg[i] : 0;
    s[tid] = v; __syncthreads();
    for (int off = 1; off < 256; off <<= 1) {
        const int t = (tid >= off) ? s[tid - off] : 0;
        __syncthreads();
        s[tid] += t;
        __syncthreads();
    }
    if (i < Nn) g_loc[i] = s[tid] - v;
    if (tid == 255) g_bsum[blockIdx.x] = s[255];
}
__global__ void csr_scan_bsum(int nb)
{
    __shared__ int s[256];
    const int t = threadIdx.x;
    const int v = (t < nb) ? g_bsum[t] : 0;
    s[t] = v; __syncthreads();
    for (int off = 1; off < 256; off <<= 1) {
        const int u = (t >= off) ? s[t - off] : 0;
        __syncthreads();
        s[t] += u;
        __syncthreads();
    }
    if (t < nb) g_bsum[t] = s[t] - v;
}
__global__ void csr_finalize()
{
    const int i = blockIdx.x * blockDim.x + threadIdx.x;
    if (i < Nn) g_rowptr[i] = g_loc[i] + g_bsum[i >> 8];
    if (i == 0) g_rowptr[Nn] = Ee;
}
__global__ void csr_fill(const int* __restrict__ ei)
{
    const int eid = blockIdx.x * blockDim.x + threadIdx.x;
    if (eid < Ee) {
        const int src = ei[eid];
        const int dst = ei[Ee + eid];
        const int p = atomicAdd(&g_cursor[dst], 1);
        const int pos = g_rowptr[dst] + p;
        g_adj[pos]  = eid;
        g_srcp[pos] = src;
    }
}

// ================= flash-style segment softmax + aggregate =================
__global__ __launch_bounds__(256) void flash_agg(
    const __half* __restrict__ q, const __half* __restrict__ k,
    const __half* __restrict__ v, const __half* __restrict__ e,
    float* __restrict__ out)
{
    const int warp = (blockIdx.x * blockDim.x + threadIdx.x) >> 5;
    const int lane = threadIdx.x & 31;
    if (warp >= Nn) return;
    const int beg = g_rowptr[warp];
    const int end = g_rowptr[warp + 1];
    if (beg == end) return;

    const int co = lane * 8;
    float qf[8];
    { uint4 u = *(const uint4*)(q + (size_t)warp * DD + co); cvt8(qf, u); }

    float m = -CUDART_INF_F, d = 0.f;
    float a[8];
    #pragma unroll
    for (int i = 0; i < 8; i++) a[i] = 0.f;

    for (int idx = beg; idx < end; idx++) {
        const int src = g_srcp[idx];
        float ef[8], kf[8], vf[8];
        { uint4 u = *(const uint4*)(e + (size_t)idx * DD + co); cvt8(ef, u); }
        { uint4 u = *(const uint4*)(k + (size_t)src * DD + co); cvt8(kf, u); }
        { uint4 u = *(const uint4*)(v + (size_t)src * DD + co); cvt8(vf, u); }

        float dot = 0.f;
        #pragma unroll
        for (int i = 0; i < 8; i++) dot += qf[i] * (kf[i] + ef[i]);
        dot += __shfl_xor_sync(0xffffffffu, dot, 1);
        dot += __shfl_xor_sync(0xffffffffu, dot, 2);
        dot += __shfl_xor_sync(0xffffffffu, dot, 4);
        const float al = dot * 0.125f;

        const float mn = fmaxf(m, al);
        const float sc = __expf(m - mn);
        const float w  = __expf(al - mn);
        d = d * sc + w;
        #pragma unroll
        for (int i = 0; i < 8; i++) a[i] = a[i] * sc + (vf[i] + ef[i]) * w;
        m = mn;
    }

    const float inv = 1.f / (d + 1e-16f);
    float* op = out + (size_t)warp * DD + co;
    float4 o0 = *(float4*)op, o1 = *(float4*)(op + 4);
    o0.x += a[0] * inv; o0.y += a[1] * inv;
    o0.z += a[2] * inv; o0.w += a[3] * inv;
    o1.x += a[4] * inv; o1.y += a[5] * inv;
    o1.z += a[6] * inv; o1.w += a[7] * inv;
    *(float4*)op       = o0;
    *(float4*)(op + 4) = o1;
}

// ================= host driver =================
static void* symaddr(const void* sym)
{
    void* p = nullptr;
    cudaGetSymbolAddress(&p, sym);
    return p;
}

extern "C" void kernel_launch(void* const* d_in, const int* in_sizes, int n_in,
                              void* d_out, int out_size)
{
    const float* x  = (const float*)d_in[0];
    const int*   ei = (const int*)d_in[1];
    const float* ea = (const float*)d_in[2];
    const float* W1[5] = { (const float*)d_in[3],  (const float*)d_in[5],
                           (const float*)d_in[7],  (const float*)d_in[9],
                           (const float*)d_in[11] };
    const float* b1[5] = { (const float*)d_in[4],  (const float*)d_in[6],
                           (const float*)d_in[8],  (const float*)d_in[10],
                           (const float*)d_in[12] };
    const float* W2[5] = { (const float*)d_in[13], (const float*)d_in[15],
                           (const float*)d_in[17], (const float*)d_in[19],
                           (const float*)d_in[21] };
    const float* b2[5] = { (const float*)d_in[14], (const float*)d_in[16],
                           (const float*)d_in[18], (const float*)d_in[20],
                           (const float*)d_in[22] };

    static __half *q = nullptr, *k, *v, *e1, *e2, *eaf, *wef, *wqkv, *xf;
    static float *h;
    static bf16 *xhi, *xlo, *whi, *wlo;
    static int *adj;
    static cudaStream_t sB;
    static cudaEvent_t evRoot, evCSR, evE;
    if (!q) {
        q  = (__half*)symaddr(g_q);  k  = (__half*)symaddr(g_k);
        v  = (__half*)symaddr(g_v);  h  = (float*)symaddr(g_h);
        e1 = (__half*)symaddr(g_e1); e2 = (__half*)symaddr(g_e2);
        eaf = (__half*)symaddr(g_eaf16); wef = (__half*)symaddr(g_wef16);
        wqkv = (__half*)symaddr(g_wqkv16); xf = (__half*)symaddr(g_xf16);
        xhi = (bf16*)symaddr(g_xhi); xlo = (bf16*)symaddr(g_xlo);
        whi = (bf16*)symaddr(g_whi); wlo = (bf16*)symaddr(g_wlo);
        adj = (int*)symaddr(g_adj);
        cudaFuncSetAttribute(gemm_bf3,
            cudaFuncAttributeMaxDynamicSharedMemorySize, GEMM_SMEM);
        cudaFuncSetAttribute(gemm_f16,
            cudaFuncAttributeMaxDynamicSharedMemorySize, GEMMF_SMEM);
        cudaStreamCreateWithFlags(&sB, cudaStreamNonBlocking);
        cudaEventCreateWithFlags(&evRoot, cudaEventDisableTiming);
        cudaEventCreateWithFlags(&evCSR,  cudaEventDisableTiming);
        cudaEventCreateWithFlags(&evE,    cudaEventDisableTiming);
    }
    float* out = (float*)d_out;

    const dim3 gQKV(6, (Nn + 127) / 128);       // 3 outputs x 2 colblocks
    const dim3 gS(2, (Nn + 127) / 128);
    const dim3 gEdge(4, Ee / 128);              // 2 outputs x 2 colblocks
    const int  bFlash = (Nn * 32 + 255) / 256;
    const int  bSplit = (Nn * DD / 4 + 255) / 256;
    const int  NB = (Nn + 255) / 256;

    // ================= fork =================
    cudaEventRecord(evRoot, 0);
    cudaStreamWaitEvent(sB, evRoot, 0);

    // sB: edge-side prep (fp16)
    tsplit_w16<<<128, 256, 0, sB>>>(W1[3], wef, 128);
    tsplit_w16<<<128, 256, 0, sB>>>(W2[3], wef + 32768, 128);
    cvt_f16<<<(int)(((size_t)Ee * EDD / 4 + 255) / 256), 256, 0, sB>>>(
        ea, eaf, (size_t)Ee * EDD / 4);

    // main: node-side prep + CSR
    for (int s = 0; s < 3; s++) {
        tsplit_w16<<<256, 256>>>(W1[s], wqkv + (size_t)s * 65536, 256);
        tsplit_w16<<<256, 256>>>(W2[s], wqkv + 196608 + (size_t)s * 65536, 256);
    }
    tsplit_w<<<256, 256>>>(W1[4], whi, wlo, 256);
    tsplit_w<<<256, 256>>>(W2[4], whi + 65536, wlo + 65536, 256);
    split_all<0><<<bSplit, 256>>>(x, xhi, xlo, xf, (size_t)Nn * DD / 4);

    csr_zero<<<NB, 256>>>();
    csr_count<<<(Ee + 255) / 256, 256>>>(ei);
    csr_scan_local<<<NB, 256>>>();
    csr_scan_bsum<<<1, 256>>>(NB);
    csr_finalize<<<NB, 256>>>();
    csr_fill<<<(Ee + 255) / 256, 256>>>(ei);
    cudaEventRecord(evCSR, 0);

    // sB: fused dst-sorted edge GEMM (e1 + e2 in one launch, A read once)
    cudaStreamWaitEvent(sB, evCSR, 0);
    gemm_f16<<<gEdge, 256, GEMMF_SMEM, sB>>>(Ee, 128, eaf, wef, adj,
        e1, e2, e2, b1[3], b2[3], b2[3]);
    cudaEventRecord(evE, sB);

    // main: layer 1 node GEMMs
    gemm_f16<<<gQKV, 256, GEMMF_SMEM>>>(Nn, 256, xf, wqkv, nullptr,
        q, k, v, b1[0], b1[1], b1[2]);
    gemm_bf3<<<gS, 256, GEMM_SMEM>>>(Nn, 256, xhi, xlo, whi, wlo, h, b1[4]);

    cudaStreamWaitEvent(0, evE, 0);
    flash_agg<<<bFlash, 256>>>(q, k, v, e1, h);
    split_all<1><<<bSplit, 256>>>(h, xhi, xlo, xf, (size_t)Nn * DD / 4);

    // main: layer 2 node GEMMs
    gemm_f16<<<gQKV, 256, GEMMF_SMEM>>>(Nn, 256, xf, wqkv + 196608, nullptr,
        q, k, v, b2[0], b2[1], b2[2]);
    gemm_bf3<<<gS, 256, GEMM_SMEM>>>(Nn, 256, xhi, xlo,
        whi + 65536, wlo + 65536, out, b2[4]);

    flash_agg<<<bFlash, 256>>>(q, k, v, e2, out);
}

// round 11
// speedup vs baseline: 4.3673x; 1.0068x over previous
#include <cuda_runtime.h>
#include <cuda_bf16.h>
#include <cuda_fp16.h>
#include <math.h>
#include <math_constants.h>
#include <cstdint>

#define Nn   50000
#define Ee   800000
#define DD   256
#define EDD  128
#define Hh   4

typedef __nv_bfloat16 bf16;

// ================= scratch (device globals) =================
__device__ __half g_q[Nn * DD];
__device__ __half g_k[Nn * DD];
__device__ __half g_v[Nn * DD];
__device__ float  g_h[Nn * DD];
__device__ __half g_e1[(size_t)Ee * DD];
__device__ __half g_e2[(size_t)Ee * DD];
// CSR for dst-grouped edges
__device__ int g_deg[Nn];
__device__ int g_cursor[Nn];
__device__ int g_loc[Nn];
__device__ int g_bsum[256];
__device__ int g_rowptr[Nn + 1];
__device__ int g_adj[Ee];
__device__ int g_srcp[Ee];
// operands
__device__ bf16 g_xhi[Nn * DD], g_xlo[Nn * DD];
__device__ __half g_xf16[Nn * DD];
__device__ __half g_eaf16[(size_t)Ee * EDD];
__device__ bf16 g_whi[2 * 65536], g_wlo[2 * 65536];
__device__ __half g_wqkv16[2 * 768 * 256];
__device__ __half g_wef16[2 * 256 * 128];

// ================= PTX helpers =================
__device__ __forceinline__ uint32_t smem_u32(const void* p) {
    uint32_t a;
    asm("{ .reg .u64 t; cvta.to.shared.u64 t, %1; cvt.u32.u64 %0, t; }"
        : "=r"(a) : "l"(p));
    return a;
}
__device__ __forceinline__ void ldsm_x4(uint32_t* r, uint32_t a) {
    asm volatile("ldmatrix.sync.aligned.m8n8.x4.shared.b16 {%0,%1,%2,%3}, [%4];"
        : "=r"(r[0]), "=r"(r[1]), "=r"(r[2]), "=r"(r[3]) : "r"(a));
}
__device__ __forceinline__ void ldsm_x2(uint32_t* r, uint32_t a) {
    asm volatile("ldmatrix.sync.aligned.m8n8.x2.shared.b16 {%0,%1}, [%2];"
        : "=r"(r[0]), "=r"(r[1]) : "r"(a));
}
__device__ __forceinline__ void mma_bf16(float* d, const uint32_t* a, const uint32_t* b) {
    asm volatile("mma.sync.aligned.m16n8k16.row.col.f32.bf16.bf16.f32 "
        "{%0,%1,%2,%3}, {%4,%5,%6,%7}, {%8,%9}, {%0,%1,%2,%3};"
        : "+f"(d[0]), "+f"(d[1]), "+f"(d[2]), "+f"(d[3])
        : "r"(a[0]), "r"(a[1]), "r"(a[2]), "r"(a[3]), "r"(b[0]), "r"(b[1]));
}
__device__ __forceinline__ void mma_f16(float* d, const uint32_t* a, const uint32_t* b) {
    asm volatile("mma.sync.aligned.m16n8k16.row.col.f32.f16.f16.f32 "
        "{%0,%1,%2,%3}, {%4,%5,%6,%7}, {%8,%9}, {%0,%1,%2,%3};"
        : "+f"(d[0]), "+f"(d[1]), "+f"(d[2]), "+f"(d[3])
        : "r"(a[0]), "r"(a[1]), "r"(a[2]), "r"(a[3]), "r"(b[0]), "r"(b[1]));
}
__device__ __forceinline__ void cpa16(uint32_t dst, const void* src, int sz) {
    asm volatile("cp.async.cg.shared.global [%0], [%1], 16, %2;"
        :: "r"(dst), "l"(src), "r"(sz) : "memory");
}
#define CP_COMMIT() asm volatile("cp.async.commit_group;" ::: "memory")
#define CP_WAIT1()  asm volatile("cp.async.wait_group 1;" ::: "memory")
#define CP_WAIT0()  asm volatile("cp.async.wait_group 0;" ::: "memory")

__device__ __forceinline__ void cvt8(float* f, uint4 u) {
    const __half2* h = (const __half2*)&u;
    float2 t;
    t = __half22float2(h[0]); f[0] = t.x; f[1] = t.y;
    t = __half22float2(h[1]); f[2] = t.x; f[3] = t.y;
    t = __half22float2(h[2]); f[4] = t.x; f[5] = t.y;
    t = __half22float2(h[3]); f[6] = t.x; f[7] = t.y;
}

// ================= bf16x3 pipelined GEMM (skip path S only) =============
#define PAD 40
#define STG_B 40960
#define OFF_AL 10240
#define OFF_BH 20480
#define OFF_BL 30720
#define GEMM_SMEM (2 * STG_B)

__global__ __launch_bounds__(256, 2) void gemm_bf3(
    int M, int K,
    const bf16* __restrict__ Ahi, const bf16* __restrict__ Alo,
    const bf16* __restrict__ Whi, const bf16* __restrict__ Wlo,
    float* __restrict__ Cf, const float* __restrict__ bias)
{
    extern __shared__ char sm[];
    const uint32_t sb = smem_u32(sm);

    const int tid  = threadIdx.x;
    const int lane = tid & 31;
    const int wid  = tid >> 5;
    const int wm   = wid >> 2;
    const int wn   = wid & 3;
    const int row0 = blockIdx.y * 128;
    const int nW0  = blockIdx.x * 128;
    const int colb = blockIdx.x * 128;

    const int lr  = tid >> 1;
    const int lcb = (tid & 1) * 16;
    const int grA  = row0 + lr;
    const int okA  = (grA < M) ? 16 : 0;
    const int arow = okA ? grA : 0;
    const size_t aoff = (size_t)arow * K + lcb;
    const size_t boff = (size_t)(nW0 + lr) * K + lcb;
    const char* pAh = (const char*)(Ahi + aoff);
    const char* pAl = (const char*)(Alo + aoff);
    const char* pBh = (const char*)(Whi + boff);
    const char* pBl = (const char*)(Wlo + boff);
    const uint32_t dstA = sb + (uint32_t)(lr * 80 + (tid & 1) * 32);

    const int nchunk = K >> 5;

    const int aRow    = lane & 15;
    const int aColSel = (lane >> 4) * 8;
    const int bRow    = lane & 7;
    const int bColSel = ((lane >> 3) & 1) * 8;

    float acc[4][4][4];
    #pragma unroll
    for (int i = 0; i < 4; i++)
        #pragma unroll
        for (int j = 0; j < 4; j++)
            #pragma unroll
            for (int t = 0; t < 4; t++) acc[i][j][t] = 0.f;

    {
        cpa16(dstA,               pAh,      okA);
        cpa16(dstA + 16,          pAh + 16, okA);
        cpa16(dstA + OFF_AL,      pAl,      okA);
        cpa16(dstA + OFF_AL + 16, pAl + 16, okA);
        cpa16(dstA + OFF_BH,      pBh,      16);
        cpa16(dstA + OFF_BH + 16, pBh + 16, 16);
        cpa16(dstA + OFF_BL,      pBl,      16);
        cpa16(dstA + OFF_BL + 16, pBl + 16, 16);
        CP_COMMIT();
    }

    for (int c = 0; c < nchunk; c++) {
        if (c + 1 < nchunk) {
            const uint32_t d = dstA + ((c + 1) & 1) * STG_B;
            const int go = (c + 1) * 64;
            cpa16(d,               pAh + go,      okA);
            cpa16(d + 16,          pAh + go + 16, okA);
            cpa16(d + OFF_AL,      pAl + go,      okA);
            cpa16(d + OFF_AL + 16, pAl + go + 16, okA);
            cpa16(d + OFF_BH,      pBh + go,      16);
            cpa16(d + OFF_BH + 16, pBh + go + 16, 16);
            cpa16(d + OFF_BL,      pBl + go,      16);
            cpa16(d + OFF_BL + 16, pBl + go + 16, 16);
            CP_COMMIT();
            CP_WAIT1();
        } else {
            CP_WAIT0();
        }
        __syncthreads();

        const uint32_t sbase = sb + (c & 1) * STG_B;
        #pragma unroll
        for (int ks = 0; ks < 2; ks++) {
            const int kb = ks * 16;
            uint32_t ah[4][4], al[4][4], bh[4][2], bl[4][2];
            #pragma unroll
            for (int mt = 0; mt < 4; mt++) {
                const uint32_t off = sbase +
                    (uint32_t)((wm * 64 + mt * 16 + aRow) * PAD + kb + aColSel) * 2;
                ldsm_x4(ah[mt], off);
                ldsm_x4(al[mt], off + OFF_AL);
            }
            #pragma unroll
            for (int nt = 0; nt < 4; nt++) {
                const uint32_t off = sbase + OFF_BH +
                    (uint32_t)((wn * 32 + nt * 8 + bRow) * PAD + kb + bColSel) * 2;
                ldsm_x2(bh[nt], off);
                ldsm_x2(bl[nt], off + (OFF_BL - OFF_BH));
            }
            #pragma unroll
            for (int mt = 0; mt < 4; mt++)
                #pragma unroll
                for (int nt = 0; nt < 4; nt++) {
                    mma_bf16(acc[mt][nt], ah[mt], bh[nt]);
                    mma_bf16(acc[mt][nt], ah[mt], bl[nt]);
                    mma_bf16(acc[mt][nt], al[mt], bh[nt]);
                }
        }
        __syncthreads();
    }

    #pragma unroll
    for (int mt = 0; mt < 4; mt++) {
        const int r = row0 + wm * 64 + mt * 16 + (lane >> 2);
        #pragma unroll
        for (int nt = 0; nt < 4; nt++) {
            const int c = colb + wn * 32 + nt * 8 + (lane & 3) * 2;
            if (r < M) {
                float2 o = make_float2(acc[mt][nt][0] + bias[c],
                                       acc[mt][nt][1] + bias[c + 1]);
                *(float2*)(Cf + (size_t)r * 256 + c) = o;
            }
            if (r + 8 < M) {
                float2 o = make_float2(acc[mt][nt][2] + bias[c],
                                       acc[mt][nt][3] + bias[c + 1]);
                *(float2*)(Cf + (size_t)(r + 8) * 256 + c) = o;
            }
        }
    }
}

// ============ single-pass fp16 GEMM, up to 3 routed fp16 outputs ============
#define STG_F 20480
#define OFF_FB 10240
#define GEMMF_SMEM (2 * STG_F)

__global__ __launch_bounds__(256, 2) void gemm_f16(
    int M, int K,
    const __half* __restrict__ A, const __half* __restrict__ W,
    const int* __restrict__ rowmap,
    __half* c0, __half* c1, __half* c2,
    const float* b0, const float* b1, const float* b2)
{
    extern __shared__ char sm[];
    const uint32_t sb = smem_u32(sm);

    const int tid  = threadIdx.x;
    const int lane = tid & 31;
    const int wid  = tid >> 5;
    const int wm   = wid >> 2;
    const int wn   = wid & 3;
    const int row0 = blockIdx.y * 128;

    __half* const outs[3]        = { c0, c1, c2 };
    const float* const biases[3] = { b0, b1, b2 };
    const int    outIdx = blockIdx.x >> 1;
    __half*      C    = outs[outIdx];
    const float* bias = biases[outIdx];
    const int    colb = (blockIdx.x & 1) * 128;
    const int    nW0  = outIdx * 256 + colb;

    const int lr  = tid >> 1;
    const int lcb = (tid & 1) * 16;
    const int grA = row0 + lr;
    const int okA = (grA < M) ? 16 : 0;
    int arow = okA ? grA : 0;
    if (rowmap) arow = rowmap[arow];
    const char* pA = (const char*)(A + (size_t)arow * K + lcb);
    const char* pB = (const char*)(W + (size_t)(nW0 + lr) * K + lcb);
    const uint32_t dstA = sb + (uint32_t)(lr * 80 + (tid & 1) * 32);

    const int nchunk = K >> 5;

    const int aRow    = lane & 15;
    const int aColSel = (lane >> 4) * 8;
    const int bRow    = lane & 7;
    const int bColSel = ((lane >> 3) & 1) * 8;

    float acc[4][4][4];
    #pragma unroll
    for (int i = 0; i < 4; i++)
        #pragma unroll
        for (int j = 0; j < 4; j++)
            #pragma unroll
            for (int t = 0; t < 4; t++) acc[i][j][t] = 0.f;

    {
        cpa16(dstA,                pA,      okA);
        cpa16(dstA + 16,           pA + 16, okA);
        cpa16(dstA + OFF_FB,       pB,      16);
        cpa16(dstA + OFF_FB + 16,  pB + 16, 16);
        CP_COMMIT();
    }

    for (int c = 0; c < nchunk; c++) {
        if (c + 1 < nchunk) {
            const uint32_t d = dstA + ((c + 1) & 1) * STG_F;
            const int go = (c + 1) * 64;
            cpa16(d,               pA + go,      okA);
            cpa16(d + 16,          pA + go + 16, okA);
            cpa16(d + OFF_FB,      pB + go,      16);
            cpa16(d + OFF_FB + 16, pB + go + 16, 16);
            CP_COMMIT();
            CP_WAIT1();
        } else {
            CP_WAIT0();
        }
        __syncthreads();

        const uint32_t sbase = sb + (c & 1) * STG_F;
        #pragma unroll
        for (int ks = 0; ks < 2; ks++) {
            const int kb = ks * 16;
            uint32_t ah[4][4], bh[4][2];
            #pragma unroll
            for (int mt = 0; mt < 4; mt++) {
                const uint32_t off = sbase +
                    (uint32_t)((wm * 64 + mt * 16 + aRow) * PAD + kb + aColSel) * 2;
                ldsm_x4(ah[mt], off);
            }
            #pragma unroll
            for (int nt = 0; nt < 4; nt++) {
                const uint32_t off = sbase + OFF_FB +
                    (uint32_t)((wn * 32 + nt * 8 + bRow) * PAD + kb + bColSel) * 2;
                ldsm_x2(bh[nt], off);
            }
            #pragma unroll
            for (int mt = 0; mt < 4; mt++)
                #pragma unroll
                for (int nt = 0; nt < 4; nt++)
                    mma_f16(acc[mt][nt], ah[mt], bh[nt]);
        }
        __syncthreads();
    }

    #pragma unroll
    for (int mt = 0; mt < 4; mt++) {
        const int r = row0 + wm * 64 + mt * 16 + (lane >> 2);
        #pragma unroll
        for (int nt = 0; nt < 4; nt++) {
            const int c = colb + wn * 32 + nt * 8 + (lane & 3) * 2;
            if (r < M)
                *(__half2*)(C + (size_t)r * 256 + c) =
                    __floats2half2_rn(acc[mt][nt][0] + bias[c],
                                      acc[mt][nt][1] + bias[c + 1]);
            if (r + 8 < M)
                *(__half2*)(C + (size_t)(r + 8) * 256 + c) =
                    __floats2half2_rn(acc[mt][nt][2] + bias[c],
                                      acc[mt][nt][3] + bias[c + 1]);
        }
    }
}

// ======== weight prep ========
__global__ void tsplit_w(const float* __restrict__ W,
                         bf16* __restrict__ hi, bf16* __restrict__ lo, int K)
{
    const int i = blockIdx.x * blockDim.x + threadIdx.x;
    if (i < K * 256) {
        const int k = i >> 8, n = i & 255;
        const float v = W[i];
        const bf16 h = __float2bfloat16(v);
        hi[(size_t)n * K + k] = h;
        lo[(size_t)n * K + k] = __float2bfloat16(v - __bfloat162float(h));
    }
}
__global__ void tsplit_w16(const float* __restrict__ W, __half* __restrict__ wt, int K)
{
    const int i = blockIdx.x * blockDim.x + threadIdx.x;
    if (i < K * 256) {
        const int k = i >> 8, n = i & 255;
        wt[(size_t)n * K + k] = __float2half(W[i]);
    }
}

template <int RELU>
__global__ void split_all(const float* __restrict__ in,
                          bf16* __restrict__ hi, bf16* __restrict__ lo,
                          __half* __restrict__ f16, size_t n4)
{
    const size_t i = (size_t)blockIdx.x * blockDim.x + threadIdx.x;
    if (i >= n4) return;
    float4 v = ((const float4*)in)[i];
    if (RELU) {
        v.x = fmaxf(v.x, 0.f); v.y = fmaxf(v.y, 0.f);
        v.z = fmaxf(v.z, 0.f); v.w = fmaxf(v.w, 0.f);
    }
    __nv_bfloat162 h0 = __floats2bfloat162_rn(v.x, v.y);
    __nv_bfloat162 h1 = __floats2bfloat162_rn(v.z, v.w);
    __nv_bfloat162 l0 = __floats2bfloat162_rn(v.x - __low2float(h0), v.y - __high2float(h0));
    __nv_bfloat162 l1 = __floats2bfloat162_rn(v.z - __low2float(h1), v.w - __high2float(h1));
    ((__nv_bfloat162*)hi)[2 * i]     = h0;
    ((__nv_bfloat162*)hi)[2 * i + 1] = h1;
    ((__nv_bfloat162*)lo)[2 * i]     = l0;
    ((__nv_bfloat162*)lo)[2 * i + 1] = l1;
    ((__half2*)f16)[2 * i]     = __floats2half2_rn(v.x, v.y);
    ((__half2*)f16)[2 * i + 1] = __floats2half2_rn(v.z, v.w);
}

__global__ void cvt_f16(const float* __restrict__ in, __half* __restrict__ o, size_t n4)
{
    const size_t i = (size_t)blockIdx.x * blockDim.x + threadIdx.x;
    if (i >= n4) return;
    float4 v = ((const float4*)in)[i];
    ((__half2*)o)[2 * i]     = __floats2half2_rn(v.x, v.y);
    ((__half2*)o)[2 * i + 1] = __floats2half2_rn(v.z, v.w);
}

// ================= CSR build =================
__global__ void csr_zero()
{
    const int i = blockIdx.x * blockDim.x + threadIdx.x;
    if (i < Nn) { g_deg[i] = 0; g_cursor[i] = 0; }
}
__global__ void csr_count(const int* __restrict__ ei)
{
    const int i = blockIdx.x * blockDim.x + threadIdx.x;
    if (i < Ee) atomicAdd(&g_deg[ei[Ee + i]], 1);
}
__global__ void csr_scan_local()
{
    __shared__ int s[256];
    const int tid = threadIdx.x;
    const int i = blockIdx.x * 256 + tid;
    const int v = (i < Nn) ? g_deg[i] : 0;
    s[tid] = v; __syncthreads();
    for (int off = 1; off < 256; off <<= 1) {
        const int t = (tid >= off) ? s[tid - off] : 0;
        __syncthreads();
        s[tid] += t;
        __syncthreads();
    }
    if (i < Nn) g_loc[i] = s[tid] - v;
    if (tid == 255) g_bsum[blockIdx.x] = s[255];
}
__global__ void csr_scan_bsum(int nb)
{
    __shared__ int s[256];
    const int t = threadIdx.x;
    const int v = (t < nb) ? g_bsum[t] : 0;
    s[t] = v; __syncthreads();
    for (int off = 1; off < 256; off <<= 1) {
        const int u = (t >= off) ? s[t - off] : 0;
        __syncthreads();
        s[t] += u;
        __syncthreads();
    }
    if (t < nb) g_bsum[t] = s[t] - v;
}
__global__ void csr_finalize()
{
    const int i = blockIdx.x * blockDim.x + threadIdx.x;
    if (i < Nn) g_rowptr[i] = g_loc[i] + g_bsum[i >> 8];
    if (i == 0) g_rowptr[Nn] = Ee;
}
__global__ void csr_fill(const int* __restrict__ ei)
{
    const int eid = blockIdx.x * blockDim.x + threadIdx.x;
    if (eid < Ee) {
        const int src = ei[eid];
        const int dst = ei[Ee + eid];
        const int p = atomicAdd(&g_cursor[dst], 1);
        const int pos = g_rowptr[dst] + p;
        g_adj[pos]  = eid;
        g_srcp[pos] = src;
    }
}

// ====== flash softmax + aggregate, software-pipelined loads ======
__global__ __launch_bounds__(256) void flash_agg(
    const __half* __restrict__ q, const __half* __restrict__ k,
    const __half* __restrict__ v, const __half* __restrict__ e,
    float* __restrict__ out)
{
    const int warp = (blockIdx.x * blockDim.x + threadIdx.x) >> 5;
    const int lane = threadIdx.x & 31;
    if (warp >= Nn) return;
    const int beg = g_rowptr[warp];
    const int end = g_rowptr[warp + 1];
    if (beg == end) return;

    const int co = lane * 8;
    float qf[8];
    { uint4 u = *(const uint4*)(q + (size_t)warp * DD + co); cvt8(qf, u); }

    float m = -CUDART_INF_F, d = 0.f;
    float a[8];
    #pragma unroll
    for (int i = 0; i < 8; i++) a[i] = 0.f;

    // prefetch edge `beg`
    int src = g_srcp[beg];
    uint4 ue = *(const uint4*)(e + (size_t)beg * DD + co);
    uint4 uk = *(const uint4*)(k + (size_t)src * DD + co);
    uint4 uv = *(const uint4*)(v + (size_t)src * DD + co);

    for (int idx = beg; idx < end; idx++) {
        const uint4 ce = ue, ck = uk, cv = uv;
        if (idx + 1 < end) {               // issue next edge's loads early
            const int s2 = g_srcp[idx + 1];
            ue = *(const uint4*)(e + (size_t)(idx + 1) * DD + co);
            uk = *(const uint4*)(k + (size_t)s2 * DD + co);
            uv = *(const uint4*)(v + (size_t)s2 * DD + co);
        }

        float ef[8], kf[8], vf[8];
        cvt8(ef, ce); cvt8(kf, ck); cvt8(vf, cv);

        float dot = 0.f;
        #pragma unroll
        for (int i = 0; i < 8; i++) dot += qf[i] * (kf[i] + ef[i]);
        dot += __shfl_xor_sync(0xffffffffu, dot, 1);
        dot += __shfl_xor_sync(0xffffffffu, dot, 2);
        dot += __shfl_xor_sync(0xffffffffu, dot, 4);
        const float al = dot * 0.125f;

        const float mn = fmaxf(m, al);
        const float sc = __expf(m - mn);
        const float w  = __expf(al - mn);
        d = d * sc + w;
        #pragma unroll
        for (int i = 0; i < 8; i++) a[i] = a[i] * sc + (vf[i] + ef[i]) * w;
        m = mn;
    }

    const float inv = 1.f / (d + 1e-16f);
    float* op = out + (size_t)warp * DD + co;
    float4 o0 = *(float4*)op, o1 = *(float4*)(op + 4);
    o0.x += a[0] * inv; o0.y += a[1] * inv;
    o0.z += a[2] * inv; o0.w += a[3] * inv;
    o1.x += a[4] * inv; o1.y += a[5] * inv;
    o1.z += a[6] * inv; o1.w += a[7] * inv;
    *(float4*)op       = o0;
    *(float4*)(op + 4) = o1;
}

// ================= host driver =================
static void* symaddr(const void* sym)
{
    void* p = nullptr;
    cudaGetSymbolAddress(&p, sym);
    return p;
}

extern "C" void kernel_launch(void* const* d_in, const int* in_sizes, int n_in,
                              void* d_out, int out_size)
{
    const float* x  = (const float*)d_in[0];
    const int*   ei = (const int*)d_in[1];
    const float* ea = (const float*)d_in[2];
    const float* W1[5] = { (const float*)d_in[3],  (const float*)d_in[5],
                           (const float*)d_in[7],  (const float*)d_in[9],
                           (const float*)d_in[11] };
    const float* b1[5] = { (const float*)d_in[4],  (const float*)d_in[6],
                           (const float*)d_in[8],  (const float*)d_in[10],
                           (const float*)d_in[12] };
    const float* W2[5] = { (const float*)d_in[13], (const float*)d_in[15],
                           (const float*)d_in[17], (const float*)d_in[19],
                           (const float*)d_in[21] };
    const float* b2[5] = { (const float*)d_in[14], (const float*)d_in[16],
                           (const float*)d_in[18], (const float*)d_in[20],
                           (const float*)d_in[22] };

    static __half *q = nullptr, *k, *v, *e1, *e2, *eaf, *wef, *wqkv, *xf;
    static float *h;
    static bf16 *xhi, *xlo, *whi, *wlo;
    static int *adj;
    static cudaStream_t sB;
    static cudaEvent_t evRoot, evE1, evE2;
    if (!q) {
        q  = (__half*)symaddr(g_q);  k  = (__half*)symaddr(g_k);
        v  = (__half*)symaddr(g_v);  h  = (float*)symaddr(g_h);
        e1 = (__half*)symaddr(g_e1); e2 = (__half*)symaddr(g_e2);
        eaf = (__half*)symaddr(g_eaf16); wef = (__half*)symaddr(g_wef16);
        wqkv = (__half*)symaddr(g_wqkv16); xf = (__half*)symaddr(g_xf16);
        xhi = (bf16*)symaddr(g_xhi); xlo = (bf16*)symaddr(g_xlo);
        whi = (bf16*)symaddr(g_whi); wlo = (bf16*)symaddr(g_wlo);
        adj = (int*)symaddr(g_adj);
        cudaFuncSetAttribute(gemm_bf3,
            cudaFuncAttributeMaxDynamicSharedMemorySize, GEMM_SMEM);
        cudaFuncSetAttribute(gemm_f16,
            cudaFuncAttributeMaxDynamicSharedMemorySize, GEMMF_SMEM);
        cudaStreamCreateWithFlags(&sB, cudaStreamNonBlocking);
        cudaEventCreateWithFlags(&evRoot, cudaEventDisableTiming);
        cudaEventCreateWithFlags(&evE1,   cudaEventDisableTiming);
        cudaEventCreateWithFlags(&evE2,   cudaEventDisableTiming);
    }
    float* out = (float*)d_out;

    const dim3 gQKV(6, (Nn + 127) / 128);
    const dim3 gS(2, (Nn + 127) / 128);
    const dim3 gE(2, Ee / 128);
    const int  bFlash = (Nn * 32 + 255) / 256;
    const int  bSplit = (Nn * DD / 4 + 255) / 256;
    const int  NB = (Nn + 255) / 256;

    // ================= fork =================
    cudaEventRecord(evRoot, 0);
    cudaStreamWaitEvent(sB, evRoot, 0);

    // sB: edge-side prep + CSR + edge GEMMs (e1 first, gated separately)
    tsplit_w16<<<128, 256, 0, sB>>>(W1[3], wef, 128);
    tsplit_w16<<<128, 256, 0, sB>>>(W2[3], wef + 32768, 128);
    csr_zero<<<NB, 256, 0, sB>>>();
    csr_count<<<(Ee + 255) / 256, 256, 0, sB>>>(ei);
    csr_scan_local<<<NB, 256, 0, sB>>>();
    csr_scan_bsum<<<1, 256, 0, sB>>>(NB);
    csr_finalize<<<NB, 256, 0, sB>>>();
    csr_fill<<<(Ee + 255) / 256, 256, 0, sB>>>(ei);
    cvt_f16<<<(int)(((size_t)Ee * EDD / 4 + 255) / 256), 256, 0, sB>>>(
        ea, eaf, (size_t)Ee * EDD / 4);
    gemm_f16<<<gE, 256, GEMMF_SMEM, sB>>>(Ee, 128, eaf, wef, adj,
        e1, e1, e1, b1[3], b1[3], b1[3]);
    cudaEventRecord(evE1, sB);
    gemm_f16<<<gE, 256, GEMMF_SMEM, sB>>>(Ee, 128, eaf, wef + 32768, adj,
        e2, e2, e2, b2[3], b2[3], b2[3]);
    cudaEventRecord(evE2, sB);

    // main: node-side prep + layer-1 GEMMs (independent of CSR)
    for (int s = 0; s < 3; s++) {
        tsplit_w16<<<256, 256>>>(W1[s], wqkv + (size_t)s * 65536, 256);
        tsplit_w16<<<256, 256>>>(W2[s], wqkv + 196608 + (size_t)s * 65536, 256);
    }
    tsplit_w<<<256, 256>>>(W1[4], whi, wlo, 256);
    tsplit_w<<<256, 256>>>(W2[4], whi + 65536, wlo + 65536, 256);
    split_all<0><<<bSplit, 256>>>(x, xhi, xlo, xf, (size_t)Nn * DD / 4);

    gemm_f16<<<gQKV, 256, GEMMF_SMEM>>>(Nn, 256, xf, wqkv, nullptr,
        q, k, v, b1[0], b1[1], b1[2]);
    gemm_bf3<<<gS, 256, GEMM_SMEM>>>(Nn, 256, xhi, xlo, whi, wlo, h, b1[4]);

    cudaStreamWaitEvent(0, evE1, 0);
    flash_agg<<<bFlash, 256>>>(q, k, v, e1, h);
    split_all<1><<<bSplit, 256>>>(h, xhi, xlo, xf, (size_t)Nn * DD / 4);

    // main: layer 2
    gemm_f16<<<gQKV, 256, GEMMF_SMEM>>>(Nn, 256, xf, wqkv + 196608, nullptr,
        q, k, v, b2[0], b2[1], b2[2]);
    gemm_bf3<<<gS, 256, GEMM_SMEM>>>(Nn, 256, xhi, xlo,
        whi + 65536, wlo + 65536, out, b2[4]);

    cudaStreamWaitEvent(0, evE2, 0);
    flash_agg<<<bFlash, 256>>>(q, k, v, e2, out);
}